// round 1
// baseline (speedup 1.0000x reference)
#include <cuda_runtime.h>

#define NN 65536
#define NE 524288
#define NB 1024

// ---------------- scratch (device globals; no allocation allowed) ----------
__device__ float g_nf[NN * 128];    // node features [x | action_rep]
__device__ float g_AB1[NN * 256];   // [A1 | B1] per node, layer 1
__device__ float g_sum1[NN * 128];  // edge-mean accumulator layer 1
__device__ float g_cnt[NN];         // in-degree per node (float)
__device__ float g_h1[NN * 128];    // layer-1 node output
__device__ float g_AB2[NN * 128];   // [A2 | B2] per node, layer 2
__device__ float g_sum2[NN * 64];   // edge-mean accumulator layer 2
__device__ float g_h2[NN * 64];     // layer-2 node output
__device__ float g_ge[NB * 64];     // graph embedding
__device__ float g_z[NB * 192];     // q-head input
__device__ float g_t1[NB * 256];
__device__ float g_t2[NB * 256];
__device__ float g_W1[128 * 256];   // [W1_top | W1_bot] repacked
__device__ float g_bias1[256];      // [b1 | 0]
__device__ float g_W2[128 * 128];   // [W2_top | W2_bot] repacked (layer 2)
__device__ float g_bias2[128];      // [b2_1 | 0]

// ---------------- kernels ---------------------------------------------------

__global__ void zero_kernel() {
    unsigned idx = blockIdx.x * blockDim.x + threadIdx.x;
    const unsigned n1 = NN * 128, n2 = NN * 64;
    if (idx < n1) g_sum1[idx] = 0.f;
    else if (idx < n1 + n2) g_sum2[idx - n1] = 0.f;
    else if (idx < n1 + n2 + NN) g_cnt[idx - n1 - n2] = 0.f;
}

// repack weights: Wcat[k][j] so edge MLP input-concat becomes A[dst]+B[src]
__global__ void prep_kernel(const float* __restrict__ g1w1, const float* __restrict__ g1b1,
                            const float* __restrict__ g2w1, const float* __restrict__ g2b1) {
    int idx = blockIdx.x * blockDim.x + threadIdx.x;
    if (idx < 128 * 256) {
        int k = idx >> 8, j = idx & 255;
        g_W1[idx] = (j < 128) ? g1w1[k * 128 + j] : g1w1[(k + 128) * 128 + (j - 128)];
    } else if (idx < 128 * 256 + 256) {
        int j = idx - 128 * 256;
        g_bias1[j] = (j < 128) ? g1b1[j] : 0.f;
    } else if (idx < 128 * 256 + 256 + 128 * 128) {
        int i2 = idx - (128 * 256 + 256);
        int k = i2 >> 7, j = i2 & 127;
        g_W2[i2] = (j < 64) ? g2w1[k * 64 + j] : g2w1[(k + 128) * 64 + (j - 64)];
    } else if (idx < 128 * 256 + 256 + 128 * 128 + 128) {
        int j = idx - (128 * 256 + 256 + 128 * 128);
        g_bias2[j] = (j < 64) ? g2b1[j] : 0.f;
    }
}

__global__ void nf_kernel(const float* __restrict__ x, const float* __restrict__ action) {
    unsigned idx = blockIdx.x * blockDim.x + threadIdx.x; // NN*128
    int n = idx >> 7, j = idx & 127;
    g_nf[idx] = (j < 96) ? x[n * 96 + j] : action[(n >> 6) * 32 + (j - 96)];
}

// C[M,Nc] = act(A[M,K] @ W[K,Nc] + bias), optional relu, optional zero-mask
// by per-row count. Requires M%64==0, K%16==0, Nc%64==0.
__global__ void gemm_kernel(const float* __restrict__ A, const float* __restrict__ W,
                            const float* __restrict__ bias, float* __restrict__ C,
                            int M, int K, int Nc, int do_relu,
                            const float* __restrict__ cntmask) {
    __shared__ float As[16][68];
    __shared__ float Bs[16][68];
    int bm = blockIdx.y * 64;
    int bn = blockIdx.x * 64;
    int t = threadIdx.x;
    int ty = t >> 4, tx = t & 15;
    float acc[4][4] = {};
    for (int k0 = 0; k0 < K; k0 += 16) {
        #pragma unroll
        for (int idx = t; idx < 64 * 16; idx += 256) {
            int row = idx >> 4, kk = idx & 15;
            As[kk][row] = A[(size_t)(bm + row) * K + k0 + kk];
        }
        #pragma unroll
        for (int idx = t; idx < 16 * 64; idx += 256) {
            int kk = idx >> 6, col = idx & 63;
            Bs[kk][col] = W[(size_t)(k0 + kk) * Nc + bn + col];
        }
        __syncthreads();
        #pragma unroll
        for (int kk = 0; kk < 16; kk++) {
            float a[4], b[4];
            #pragma unroll
            for (int i = 0; i < 4; i++) a[i] = As[kk][ty * 4 + i];
            #pragma unroll
            for (int j = 0; j < 4; j++) b[j] = Bs[kk][tx * 4 + j];
            #pragma unroll
            for (int i = 0; i < 4; i++)
                #pragma unroll
                for (int j = 0; j < 4; j++) acc[i][j] = fmaf(a[i], b[j], acc[i][j]);
        }
        __syncthreads();
    }
    #pragma unroll
    for (int i = 0; i < 4; i++) {
        int r = bm + ty * 4 + i;
        float zeromask = (cntmask && cntmask[r] == 0.f) ? 0.f : 1.f;
        #pragma unroll
        for (int j = 0; j < 4; j++) {
            int c = bn + tx * 4 + j;
            float v = acc[i][j] + bias[c];
            if (do_relu) v = fmaxf(v, 0.f);
            C[(size_t)r * Nc + c] = v * zeromask;
        }
    }
}

__global__ void count_kernel(const int* __restrict__ dst) {
    int e = blockIdx.x * blockDim.x + threadIdx.x;
    if (e < NE) atomicAdd(&g_cnt[dst[e]], 1.f);
}

__global__ void edge1_kernel(const int* __restrict__ src, const int* __restrict__ dst) {
    unsigned t = blockIdx.x * blockDim.x + threadIdx.x; // NE*32 threads
    int e = t >> 5;
    int j = (t & 31) << 2;
    int s = src[e], d = dst[e];
    float4 a = *(const float4*)&g_AB1[d * 256 + j];
    float4 b = *(const float4*)&g_AB1[s * 256 + 128 + j];
    float* o = &g_sum1[d * 128 + j];
    atomicAdd(o + 0, fmaxf(a.x + b.x, 0.f));
    atomicAdd(o + 1, fmaxf(a.y + b.y, 0.f));
    atomicAdd(o + 2, fmaxf(a.z + b.z, 0.f));
    atomicAdd(o + 3, fmaxf(a.w + b.w, 0.f));
}

__global__ void edge2_kernel(const int* __restrict__ src, const int* __restrict__ dst) {
    unsigned t = blockIdx.x * blockDim.x + threadIdx.x; // NE*16 threads
    int e = t >> 4;
    int j = (t & 15) << 2;
    int s = src[e], d = dst[e];
    float4 a = *(const float4*)&g_AB2[d * 128 + j];
    float4 b = *(const float4*)&g_AB2[s * 128 + 64 + j];
    float* o = &g_sum2[d * 64 + j];
    atomicAdd(o + 0, fmaxf(a.x + b.x, 0.f));
    atomicAdd(o + 1, fmaxf(a.y + b.y, 0.f));
    atomicAdd(o + 2, fmaxf(a.z + b.z, 0.f));
    atomicAdd(o + 3, fmaxf(a.w + b.w, 0.f));
}

__global__ void scale_kernel(float* __restrict__ buf, int cols_log2, unsigned total) {
    unsigned idx = blockIdx.x * blockDim.x + threadIdx.x;
    if (idx >= total) return;
    int n = idx >> cols_log2;
    buf[idx] = buf[idx] / fmaxf(g_cnt[n], 1.f);
}

__global__ void ge_kernel() {
    int g = blockIdx.x;      // NB blocks
    int c = threadIdx.x;     // 64 threads
    float s = 0.f;
    #pragma unroll 8
    for (int r = 0; r < 64; r++) s += g_h2[(g * 64 + r) * 64 + c];
    g_ge[g * 64 + c] = s * (1.f / 64.f);
}

__global__ void z_kernel(const float* __restrict__ state, const float* __restrict__ action) {
    unsigned idx = blockIdx.x * blockDim.x + threadIdx.x; // NB*192
    if (idx >= NB * 192) return;
    int b = idx / 192, j = idx % 192;
    float v;
    if (j < 96)        v = state[b * 96 + j];
    else if (j < 128)  v = action[b * 32 + (j - 96)];
    else               v = g_ge[b * 64 + (j - 128)];
    g_z[idx] = v;
}

__global__ void qdot_kernel(const float* __restrict__ t2, const float* __restrict__ w3,
                            const float* __restrict__ b3, float* __restrict__ out) {
    int warp = (blockIdx.x * blockDim.x + threadIdx.x) >> 5;
    int lane = threadIdx.x & 31;
    if (warp >= NB) return;
    float s = 0.f;
    #pragma unroll
    for (int k = lane; k < 256; k += 32) s += t2[warp * 256 + k] * w3[k];
    #pragma unroll
    for (int o = 16; o > 0; o >>= 1) s += __shfl_down_sync(0xffffffffu, s, o);
    if (lane == 0) out[warp] = s + b3[0];
}

// ---------------- launch -----------------------------------------------------

extern "C" void kernel_launch(void* const* d_in, const int* in_sizes, int n_in,
                              void* d_out, int out_size) {
    const float* state  = (const float*)d_in[0];
    const float* action = (const float*)d_in[1];
    const float* x      = (const float*)d_in[2];
    const int*   eidx   = (const int*)d_in[3];
    // d_in[4] = batch (implicit arange//64, unused)
    const float* g1_w1 = (const float*)d_in[5];
    const float* g1_b1 = (const float*)d_in[6];
    const float* g1_w2 = (const float*)d_in[7];
    const float* g1_b2 = (const float*)d_in[8];
    const float* g2_w1 = (const float*)d_in[9];
    const float* g2_b1 = (const float*)d_in[10];
    const float* g2_w2 = (const float*)d_in[11];
    const float* g2_b2 = (const float*)d_in[12];
    const float* q1_w1 = (const float*)d_in[13];
    const float* q1_b1 = (const float*)d_in[14];
    const float* q1_w2 = (const float*)d_in[15];
    const float* q1_b2 = (const float*)d_in[16];
    const float* q1_w3 = (const float*)d_in[17];
    const float* q1_b3 = (const float*)d_in[18];
    const float* q2_w1 = (const float*)d_in[19];
    const float* q2_b1 = (const float*)d_in[20];
    const float* q2_w2 = (const float*)d_in[21];
    const float* q2_b2 = (const float*)d_in[22];
    const float* q2_w3 = (const float*)d_in[23];
    const float* q2_b3 = (const float*)d_in[24];
    float* out = (float*)d_out;

    const int* srcs = eidx;
    const int* dsts = eidx + NE;

    float *p_nf, *p_AB1, *p_sum1, *p_cnt, *p_h1, *p_AB2, *p_sum2, *p_h2;
    float *p_z, *p_t1, *p_t2, *p_W1, *p_b1, *p_W2, *p_b2;
    cudaGetSymbolAddress((void**)&p_nf,   g_nf);
    cudaGetSymbolAddress((void**)&p_AB1,  g_AB1);
    cudaGetSymbolAddress((void**)&p_sum1, g_sum1);
    cudaGetSymbolAddress((void**)&p_cnt,  g_cnt);
    cudaGetSymbolAddress((void**)&p_h1,   g_h1);
    cudaGetSymbolAddress((void**)&p_AB2,  g_AB2);
    cudaGetSymbolAddress((void**)&p_sum2, g_sum2);
    cudaGetSymbolAddress((void**)&p_h2,   g_h2);
    cudaGetSymbolAddress((void**)&p_z,    g_z);
    cudaGetSymbolAddress((void**)&p_t1,   g_t1);
    cudaGetSymbolAddress((void**)&p_t2,   g_t2);
    cudaGetSymbolAddress((void**)&p_W1,   g_W1);
    cudaGetSymbolAddress((void**)&p_b1,   g_bias1);
    cudaGetSymbolAddress((void**)&p_W2,   g_W2);
    cudaGetSymbolAddress((void**)&p_b2,   g_bias2);

    // 0. zero accumulators + counts
    {
        unsigned total = NN * 128u + NN * 64u + NN;
        zero_kernel<<<(total + 255) / 256, 256>>>();
    }
    // 1. repack concat weights
    prep_kernel<<<(128 * 256 + 256 + 128 * 128 + 128 + 255) / 256, 256>>>(g1_w1, g1_b1, g2_w1, g2_b1);
    // 2. node features
    nf_kernel<<<(NN * 128u) / 256, 256>>>(x, action);
    // 3. [A1|B1] = nf @ [W1_top|W1_bot] + [b1|0]
    gemm_kernel<<<dim3(256 / 64, NN / 64), 256>>>(p_nf, p_W1, p_b1, p_AB1, NN, 128, 256, 0, nullptr);
    // 4. in-degree counts
    count_kernel<<<NE / 256, 256>>>(dsts);
    // 5. edge phase 1: sum1[dst] += relu(A1[dst] + B1[src])
    edge1_kernel<<<(NE * 32u) / 256, 256>>>(srcs, dsts);
    // 6. mean
    scale_kernel<<<(NN * 128u + 255) / 256, 256>>>(p_sum1, 7, NN * 128u);
    // 7. h1 = relu(mean1 @ g1_w2 + g1_b2), masked for deg-0 nodes
    gemm_kernel<<<dim3(128 / 64, NN / 64), 256>>>(p_sum1, g1_w2, g1_b2, p_h1, NN, 128, 128, 1, p_cnt);
    // 8. [A2|B2] = h1 @ [W2_top|W2_bot] + [b2_1|0]
    gemm_kernel<<<dim3(128 / 64, NN / 64), 256>>>(p_h1, p_W2, p_b2, p_AB2, NN, 128, 128, 0, nullptr);
    // 9. edge phase 2
    edge2_kernel<<<(NE * 16u) / 256, 256>>>(srcs, dsts);
    // 10. mean
    scale_kernel<<<(NN * 64u + 255) / 256, 256>>>(p_sum2, 6, NN * 64u);
    // 11. h2 = mean2 @ g2_w2 + g2_b2, masked for deg-0 nodes (no relu)
    gemm_kernel<<<dim3(64 / 64, NN / 64), 256>>>(p_sum2, g2_w2, g2_b2, p_h2, NN, 64, 64, 0, p_cnt);
    // 12. graph embedding (64 contiguous nodes per graph)
    ge_kernel<<<NB, 64>>>();
    // 13. z = [state | action | ge]
    z_kernel<<<(NB * 192 + 255) / 256, 256>>>(state, action);
    // 14. Q head 1
    gemm_kernel<<<dim3(256 / 64, NB / 64), 256>>>(p_z, q1_w1, q1_b1, p_t1, NB, 192, 256, 1, nullptr);
    gemm_kernel<<<dim3(256 / 64, NB / 64), 256>>>(p_t1, q1_w2, q1_b2, p_t2, NB, 256, 256, 1, nullptr);
    qdot_kernel<<<(NB * 32 + 255) / 256, 256>>>(p_t2, q1_w3, q1_b3, out);
    // 15. Q head 2
    gemm_kernel<<<dim3(256 / 64, NB / 64), 256>>>(p_z, q2_w1, q2_b1, p_t1, NB, 192, 256, 1, nullptr);
    gemm_kernel<<<dim3(256 / 64, NB / 64), 256>>>(p_t1, q2_w2, q2_b2, p_t2, NB, 256, 256, 1, nullptr);
    qdot_kernel<<<(NB * 32 + 255) / 256, 256>>>(p_t2, q2_w3, q2_b3, out + NB);
}

// round 2
// speedup vs baseline: 1.4456x; 1.4456x over previous
#include <cuda_runtime.h>

#define NN 65536
#define NE 524288
#define NB 1024

// ---------------- scratch (device globals) ----------------------------------
__device__ float g_AB1[NN * 256];   // [A1 | B1] per node, layer 1
__device__ float g_sum1[NN * 128];  // edge-mean layer 1
__device__ float g_h1[NN * 128];    // layer-1 node output
__device__ float g_AB2[NN * 128];   // [A2 | B2] per node, layer 2
__device__ float g_sum2[NN * 64];   // edge-mean layer 2
__device__ float g_h2[NN * 64];     // layer-2 node output
__device__ float g_ge[NB * 64];
__device__ float g_z[NB * 192];
__device__ float g_t1[NB * 256];
__device__ float g_t2[NB * 256];
__device__ float g_actterm[NB * 256];  // action @ W1cat[96:128] + b1cat
__device__ float g_W1[128 * 256];   // [W1_dst | W1_src] repacked
__device__ float g_bias1[256];      // [b1 | 0]
__device__ float g_W2[128 * 128];   // layer-2 repack
__device__ float g_bias2[128];      // [b2_1 | 0]
__device__ int   g_deg[NN];
__device__ int   g_off[NN];
__device__ int   g_cur[NN];
__device__ int   g_csr[NE];         // src ids grouped by dst

// ---------------- small kernels ---------------------------------------------

__global__ void zero_deg_kernel() {
    unsigned idx = blockIdx.x * blockDim.x + threadIdx.x;
    if (idx < NN) g_deg[idx] = 0;
}

__global__ void prep_kernel(const float* __restrict__ g1w1, const float* __restrict__ g1b1,
                            const float* __restrict__ g2w1, const float* __restrict__ g2b1) {
    int idx = blockIdx.x * blockDim.x + threadIdx.x;
    if (idx < 128 * 256) {
        int k = idx >> 8, j = idx & 255;
        g_W1[idx] = (j < 128) ? g1w1[k * 128 + j] : g1w1[(k + 128) * 128 + (j - 128)];
    } else if (idx < 128 * 256 + 256) {
        int j = idx - 128 * 256;
        g_bias1[j] = (j < 128) ? g1b1[j] : 0.f;
    } else if (idx < 128 * 256 + 256 + 128 * 128) {
        int i2 = idx - (128 * 256 + 256);
        int k = i2 >> 7, j = i2 & 127;
        g_W2[i2] = (j < 64) ? g2w1[k * 64 + j] : g2w1[(k + 128) * 64 + (j - 64)];
    } else if (idx < 128 * 256 + 256 + 128 * 128 + 128) {
        int j = idx - (128 * 256 + 256 + 128 * 128);
        g_bias2[j] = (j < 64) ? g2b1[j] : 0.f;
    }
}

__global__ void count_kernel(const int* __restrict__ dst) {
    int e = blockIdx.x * blockDim.x + threadIdx.x;
    if (e < NE) atomicAdd(&g_deg[dst[e]], 1);
}

// exclusive scan of g_deg (NN entries) in one 1024-thread block
__global__ void scan_kernel() {
    __shared__ int buf[2][1024];
    int t = threadIdx.x;
    int base = t * 64;
    int s = 0;
    #pragma unroll 8
    for (int i = 0; i < 64; i++) s += g_deg[base + i];
    buf[0][t] = s;
    __syncthreads();
    int pi = 0;
    for (int off = 1; off < 1024; off <<= 1) {
        int v = buf[pi][t];
        if (t >= off) v += buf[pi][t - off];
        buf[pi ^ 1][t] = v;
        __syncthreads();
        pi ^= 1;
    }
    int run = (t == 0) ? 0 : buf[pi][t - 1];
    for (int i = 0; i < 64; i++) {
        int d = g_deg[base + i];
        g_off[base + i] = run;
        g_cur[base + i] = run;
        run += d;
    }
}

__global__ void scatter_kernel(const int* __restrict__ src, const int* __restrict__ dst) {
    int e = blockIdx.x * blockDim.x + threadIdx.x;
    if (e < NE) {
        int pos = atomicAdd(&g_cur[dst[e]], 1);
        g_csr[pos] = src[e];
    }
}

// ---------------- GEMM: C = act(A@W + bias + rowadd), 128x64 tile, 8x4/thread
__global__ void gemm_kernel(const float* __restrict__ A, const float* __restrict__ W,
                            const float* __restrict__ bias, float* __restrict__ C,
                            int M, int K, int Nc, int do_relu,
                            const int* __restrict__ degmask,
                            const float* __restrict__ rowadd) {
    __shared__ float As[16][132];
    __shared__ float Bs[16][68];
    int bm = blockIdx.y * 128;
    int bn = blockIdx.x * 64;
    int t = threadIdx.x;
    int ty = t >> 4, tx = t & 15;   // 16x16 thread grid
    float acc[8][4] = {};
    for (int k0 = 0; k0 < K; k0 += 16) {
        #pragma unroll
        for (int i = 0; i < 2; i++) {
            int idx = t + i * 256;              // 0..511 float4s
            int row = idx >> 2;
            int kq = (idx & 3) << 2;
            float4 v = *(const float4*)&A[(size_t)(bm + row) * K + k0 + kq];
            As[kq + 0][row] = v.x;
            As[kq + 1][row] = v.y;
            As[kq + 2][row] = v.z;
            As[kq + 3][row] = v.w;
        }
        {
            int kk = t >> 4;
            int col = (t & 15) << 2;
            *(float4*)&Bs[kk][col] = *(const float4*)&W[(size_t)(k0 + kk) * Nc + bn + col];
        }
        __syncthreads();
        #pragma unroll
        for (int kk = 0; kk < 16; kk++) {
            float4 a0 = *(const float4*)&As[kk][ty * 8];
            float4 a1 = *(const float4*)&As[kk][ty * 8 + 4];
            float4 b  = *(const float4*)&Bs[kk][tx * 4];
            float a[8] = {a0.x, a0.y, a0.z, a0.w, a1.x, a1.y, a1.z, a1.w};
            float bb[4] = {b.x, b.y, b.z, b.w};
            #pragma unroll
            for (int i = 0; i < 8; i++)
                #pragma unroll
                for (int j = 0; j < 4; j++) acc[i][j] = fmaf(a[i], bb[j], acc[i][j]);
        }
        __syncthreads();
    }
    #pragma unroll
    for (int i = 0; i < 8; i++) {
        int r = bm + ty * 8 + i;
        float zm = (degmask && degmask[r] == 0) ? 0.f : 1.f;
        int c0 = bn + tx * 4;
        float4 v;
        float* vp = &v.x;
        #pragma unroll
        for (int j = 0; j < 4; j++) {
            float x = acc[i][j];
            if (bias)   x += bias[c0 + j];
            if (rowadd) x += rowadd[(size_t)(r >> 6) * Nc + c0 + j];
            if (do_relu) x = fmaxf(x, 0.f);
            vp[j] = x * zm;
        }
        *(float4*)&C[(size_t)r * Nc + c0] = v;
    }
}

// ---------------- edge aggregation (CSR, one warp per dst node) -------------

__global__ void agg1_kernel() {
    int w = (blockIdx.x * blockDim.x + threadIdx.x) >> 5;   // node id
    int lane = threadIdx.x & 31;
    int deg = g_deg[w], start = g_off[w];
    float4 a = *(const float4*)&g_AB1[(size_t)w * 256 + lane * 4];
    float4 acc = {0.f, 0.f, 0.f, 0.f};
    int s = (deg > 0) ? g_csr[start] : 0;
    for (int i = 0; i < deg; i++) {
        int snext = (i + 1 < deg) ? g_csr[start + i + 1] : 0;
        float4 b = *(const float4*)&g_AB1[(size_t)s * 256 + 128 + lane * 4];
        acc.x += fmaxf(a.x + b.x, 0.f);
        acc.y += fmaxf(a.y + b.y, 0.f);
        acc.z += fmaxf(a.z + b.z, 0.f);
        acc.w += fmaxf(a.w + b.w, 0.f);
        s = snext;
    }
    float inv = 1.f / fmaxf((float)deg, 1.f);
    float4 o = {acc.x * inv, acc.y * inv, acc.z * inv, acc.w * inv};
    *(float4*)&g_sum1[(size_t)w * 128 + lane * 4] = o;
}

__global__ void agg2_kernel() {
    int w = (blockIdx.x * blockDim.x + threadIdx.x) >> 5;
    int lane = threadIdx.x & 31;
    int deg = g_deg[w], start = g_off[w];
    float2 a = *(const float2*)&g_AB2[(size_t)w * 128 + lane * 2];
    float2 acc = {0.f, 0.f};
    int s = (deg > 0) ? g_csr[start] : 0;
    for (int i = 0; i < deg; i++) {
        int snext = (i + 1 < deg) ? g_csr[start + i + 1] : 0;
        float2 b = *(const float2*)&g_AB2[(size_t)s * 128 + 64 + lane * 2];
        acc.x += fmaxf(a.x + b.x, 0.f);
        acc.y += fmaxf(a.y + b.y, 0.f);
        s = snext;
    }
    float inv = 1.f / fmaxf((float)deg, 1.f);
    float2 o = {acc.x * inv, acc.y * inv};
    *(float2*)&g_sum2[(size_t)w * 64 + lane * 2] = o;
}

// ---------------- tail kernels -----------------------------------------------

__global__ void ge_kernel() {
    int g = blockIdx.x;
    int c = threadIdx.x;
    float s = 0.f;
    #pragma unroll 8
    for (int r = 0; r < 64; r++) s += g_h2[(size_t)(g * 64 + r) * 64 + c];
    g_ge[g * 64 + c] = s * (1.f / 64.f);
}

__global__ void z_kernel(const float* __restrict__ state, const float* __restrict__ action) {
    unsigned idx = blockIdx.x * blockDim.x + threadIdx.x;
    if (idx >= NB * 192) return;
    int b = idx / 192, j = idx % 192;
    float v;
    if (j < 96)       v = state[b * 96 + j];
    else if (j < 128) v = action[b * 32 + (j - 96)];
    else              v = g_ge[b * 64 + (j - 128)];
    g_z[idx] = v;
}

__global__ void qdot_kernel(const float* __restrict__ t2, const float* __restrict__ w3,
                            const float* __restrict__ b3, float* __restrict__ out) {
    int warp = (blockIdx.x * blockDim.x + threadIdx.x) >> 5;
    int lane = threadIdx.x & 31;
    if (warp >= NB) return;
    float s = 0.f;
    #pragma unroll
    for (int k = lane; k < 256; k += 32) s += t2[warp * 256 + k] * w3[k];
    #pragma unroll
    for (int o = 16; o > 0; o >>= 1) s += __shfl_down_sync(0xffffffffu, s, o);
    if (lane == 0) out[warp] = s + b3[0];
}

// ---------------- launch ------------------------------------------------------

extern "C" void kernel_launch(void* const* d_in, const int* in_sizes, int n_in,
                              void* d_out, int out_size) {
    const float* state  = (const float*)d_in[0];
    const float* action = (const float*)d_in[1];
    const float* x      = (const float*)d_in[2];
    const int*   eidx   = (const int*)d_in[3];
    const float* g1_w1 = (const float*)d_in[5];
    const float* g1_b1 = (const float*)d_in[6];
    const float* g1_w2 = (const float*)d_in[7];
    const float* g1_b2 = (const float*)d_in[8];
    const float* g2_w1 = (const float*)d_in[9];
    const float* g2_b1 = (const float*)d_in[10];
    const float* g2_w2 = (const float*)d_in[11];
    const float* g2_b2 = (const float*)d_in[12];
    const float* q1_w1 = (const float*)d_in[13];
    const float* q1_b1 = (const float*)d_in[14];
    const float* q1_w2 = (const float*)d_in[15];
    const float* q1_b2 = (const float*)d_in[16];
    const float* q1_w3 = (const float*)d_in[17];
    const float* q1_b3 = (const float*)d_in[18];
    const float* q2_w1 = (const float*)d_in[19];
    const float* q2_b1 = (const float*)d_in[20];
    const float* q2_w2 = (const float*)d_in[21];
    const float* q2_b2 = (const float*)d_in[22];
    const float* q2_w3 = (const float*)d_in[23];
    const float* q2_b3 = (const float*)d_in[24];
    float* out = (float*)d_out;

    const int* srcs = eidx;
    const int* dsts = eidx + NE;

    float *p_AB1, *p_sum1, *p_h1, *p_AB2, *p_sum2, *p_h2;
    float *p_z, *p_t1, *p_t2, *p_W1, *p_b1, *p_W2, *p_b2, *p_act;
    int *p_deg;
    cudaGetSymbolAddress((void**)&p_AB1,  g_AB1);
    cudaGetSymbolAddress((void**)&p_sum1, g_sum1);
    cudaGetSymbolAddress((void**)&p_h1,   g_h1);
    cudaGetSymbolAddress((void**)&p_AB2,  g_AB2);
    cudaGetSymbolAddress((void**)&p_sum2, g_sum2);
    cudaGetSymbolAddress((void**)&p_h2,   g_h2);
    cudaGetSymbolAddress((void**)&p_z,    g_z);
    cudaGetSymbolAddress((void**)&p_t1,   g_t1);
    cudaGetSymbolAddress((void**)&p_t2,   g_t2);
    cudaGetSymbolAddress((void**)&p_W1,   g_W1);
    cudaGetSymbolAddress((void**)&p_b1,   g_bias1);
    cudaGetSymbolAddress((void**)&p_W2,   g_W2);
    cudaGetSymbolAddress((void**)&p_b2,   g_bias2);
    cudaGetSymbolAddress((void**)&p_act,  g_actterm);
    cudaGetSymbolAddress((void**)&p_deg,  g_deg);

    // CSR build
    zero_deg_kernel<<<NN / 256, 256>>>();
    prep_kernel<<<(128 * 256 + 256 + 128 * 128 + 128 + 255) / 256, 256>>>(g1_w1, g1_b1, g2_w1, g2_b1);
    count_kernel<<<NE / 256, 256>>>(dsts);
    scan_kernel<<<1, 1024>>>();
    scatter_kernel<<<NE / 256, 256>>>(srcs, dsts);

    // actterm[B,256] = action @ W1cat[96:128] + b1cat
    gemm_kernel<<<dim3(256 / 64, NB / 128), 256>>>(action, p_W1 + 96 * 256, p_b1, p_act,
                                                   NB, 32, 256, 0, nullptr, nullptr);
    // AB1 = x @ W1cat[0:96] + actterm[graph]
    gemm_kernel<<<dim3(256 / 64, NN / 128), 256>>>(x, p_W1, nullptr, p_AB1,
                                                   NN, 96, 256, 0, nullptr, p_act);
    // edge phase 1 (writes means directly)
    agg1_kernel<<<NN / 8, 256>>>();
    // h1 = relu(mean1 @ g1_w2 + b2), deg-0 masked
    gemm_kernel<<<dim3(128 / 64, NN / 128), 256>>>(p_sum1, g1_w2, g1_b2, p_h1,
                                                   NN, 128, 128, 1, p_deg, nullptr);
    // AB2 = h1 @ W2cat + [b2_1|0]
    gemm_kernel<<<dim3(128 / 64, NN / 128), 256>>>(p_h1, p_W2, p_b2, p_AB2,
                                                   NN, 128, 128, 0, nullptr, nullptr);
    // edge phase 2
    agg2_kernel<<<NN / 8, 256>>>();
    // h2 = mean2 @ g2_w2 + g2_b2, deg-0 masked, no relu
    gemm_kernel<<<dim3(64 / 64, NN / 128), 256>>>(p_sum2, g2_w2, g2_b2, p_h2,
                                                  NN, 64, 64, 0, p_deg, nullptr);
    // graph embedding + z
    ge_kernel<<<NB, 64>>>();
    z_kernel<<<(NB * 192 + 255) / 256, 256>>>(state, action);
    // Q heads
    gemm_kernel<<<dim3(256 / 64, NB / 128), 256>>>(p_z, q1_w1, q1_b1, p_t1, NB, 192, 256, 1, nullptr, nullptr);
    gemm_kernel<<<dim3(256 / 64, NB / 128), 256>>>(p_t1, q1_w2, q1_b2, p_t2, NB, 256, 256, 1, nullptr, nullptr);
    qdot_kernel<<<(NB * 32 + 255) / 256, 256>>>(p_t2, q1_w3, q1_b3, out);
    gemm_kernel<<<dim3(256 / 64, NB / 128), 256>>>(p_z, q2_w1, q2_b1, p_t1, NB, 192, 256, 1, nullptr, nullptr);
    gemm_kernel<<<dim3(256 / 64, NB / 128), 256>>>(p_t1, q2_w2, q2_b2, p_t2, NB, 256, 256, 1, nullptr, nullptr);
    qdot_kernel<<<(NB * 32 + 255) / 256, 256>>>(p_t2, q2_w3, q2_b3, out + NB);
}

// round 3
// speedup vs baseline: 1.9113x; 1.3221x over previous
#include <cuda_runtime.h>

#define NN 65536
#define NE 524288
#define NB 1024

// ---------------- scratch (device globals) ----------------------------------
__device__ float g_AB1[NN * 256];   // [A1 | B1] per node, layer 1
__device__ float g_sum1[NN * 128];  // edge-mean layer 1
__device__ float g_h1[NN * 128];    // layer-1 node output
__device__ float g_AB2[NN * 128];   // [A2 | B2] per node, layer 2
__device__ float g_sum2[NN * 64];   // edge-mean layer 2
__device__ float g_h2[NN * 64];     // layer-2 node output
__device__ float g_ge[NB * 64];
__device__ float g_z[NB * 192];
__device__ float g_t1[NB * 256];
__device__ float g_t2[NB * 256];
__device__ float g_actterm[NB * 256];
__device__ float g_W1[128 * 256];   // [W1_dst | W1_src] repacked
__device__ float g_bias1[256];      // [b1 | 0]
__device__ float g_W2[128 * 128];
__device__ float g_bias2[128];      // [b2_1 | 0]
__device__ int   g_deg[NN];
__device__ int   g_off[NN];
__device__ int   g_cur[NN];
__device__ int   g_csr[NE];
__device__ int   g_bsum[256];
__device__ int   g_boff[256];

// ---------------- small kernels ---------------------------------------------

__global__ void zero_deg_kernel() {
    unsigned idx = blockIdx.x * blockDim.x + threadIdx.x;
    if (idx < NN) g_deg[idx] = 0;
}

__global__ void prep_kernel(const float* __restrict__ g1w1, const float* __restrict__ g1b1,
                            const float* __restrict__ g2w1, const float* __restrict__ g2b1) {
    int idx = blockIdx.x * blockDim.x + threadIdx.x;
    if (idx < 128 * 256) {
        int k = idx >> 8, j = idx & 255;
        g_W1[idx] = (j < 128) ? g1w1[k * 128 + j] : g1w1[(k + 128) * 128 + (j - 128)];
    } else if (idx < 128 * 256 + 256) {
        int j = idx - 128 * 256;
        g_bias1[j] = (j < 128) ? g1b1[j] : 0.f;
    } else if (idx < 128 * 256 + 256 + 128 * 128) {
        int i2 = idx - (128 * 256 + 256);
        int k = i2 >> 7, j = i2 & 127;
        g_W2[i2] = (j < 64) ? g2w1[k * 64 + j] : g2w1[(k + 128) * 64 + (j - 64)];
    } else if (idx < 128 * 256 + 256 + 128 * 128 + 128) {
        int j = idx - (128 * 256 + 256 + 128 * 128);
        g_bias2[j] = (j < 64) ? g2b1[j] : 0.f;
    }
}

__global__ void count_kernel(const int* __restrict__ dst) {
    int e = blockIdx.x * blockDim.x + threadIdx.x;
    if (e < NE) atomicAdd(&g_deg[dst[e]], 1);
}

// hierarchical scan: phase 1 — per-block (256 entries) sums
__global__ void blocksum_kernel() {
    __shared__ int sh[256];
    int t = threadIdx.x;
    sh[t] = g_deg[blockIdx.x * 256 + t];
    __syncthreads();
    for (int off = 128; off > 0; off >>= 1) {
        if (t < off) sh[t] += sh[t + off];
        __syncthreads();
    }
    if (t == 0) g_bsum[blockIdx.x] = sh[0];
}

// phase 2 — exclusive scan of 256 block sums
__global__ void bscan_kernel() {
    __shared__ int sh[256];
    int t = threadIdx.x;
    sh[t] = g_bsum[t];
    __syncthreads();
    for (int off = 1; off < 256; off <<= 1) {
        int v = (t >= off) ? sh[t - off] : 0;
        __syncthreads();
        sh[t] += v;
        __syncthreads();
    }
    g_boff[t] = sh[t] - g_bsum[t];   // exclusive
}

// phase 3 — local exclusive scan + block offset
__global__ void fill_kernel() {
    __shared__ int sh[256];
    int t = threadIdx.x;
    int gi = blockIdx.x * 256 + t;
    int d = g_deg[gi];
    sh[t] = d;
    __syncthreads();
    for (int off = 1; off < 256; off <<= 1) {
        int v = (t >= off) ? sh[t - off] : 0;
        __syncthreads();
        sh[t] += v;
        __syncthreads();
    }
    int excl = sh[t] - d + g_boff[blockIdx.x];
    g_off[gi] = excl;
    g_cur[gi] = excl;
}

__global__ void scatter_kernel(const int* __restrict__ src, const int* __restrict__ dst) {
    int e = blockIdx.x * blockDim.x + threadIdx.x;
    if (e < NE) {
        int pos = atomicAdd(&g_cur[dst[e]], 1);
        g_csr[pos] = src[e];
    }
}

// ---------------- GEMM 128x128 tile, 8x8/thread ------------------------------
__global__ void __launch_bounds__(256)
gemm128_kernel(const float* __restrict__ A, const float* __restrict__ W,
               const float* __restrict__ bias, float* __restrict__ C,
               int M, int K, int Nc, int do_relu,
               const int* __restrict__ degmask,
               const float* __restrict__ rowadd) {
    __shared__ float As[16][132];
    __shared__ float Bs[16][132];
    int bm = blockIdx.y * 128;
    int bn = blockIdx.x * 128;
    int t = threadIdx.x;
    int ty = t >> 4, tx = t & 15;
    float acc[8][8] = {};
    for (int k0 = 0; k0 < K; k0 += 16) {
        #pragma unroll
        for (int i = 0; i < 2; i++) {
            int idx = t + i * 256;
            int row = idx >> 2;
            int kq = (idx & 3) << 2;
            float4 v = *(const float4*)&A[(size_t)(bm + row) * K + k0 + kq];
            As[kq + 0][row] = v.x;
            As[kq + 1][row] = v.y;
            As[kq + 2][row] = v.z;
            As[kq + 3][row] = v.w;
        }
        #pragma unroll
        for (int i = 0; i < 2; i++) {
            int idx = t + i * 256;
            int kk = idx >> 5;
            int col = (idx & 31) << 2;
            *(float4*)&Bs[kk][col] = *(const float4*)&W[(size_t)(k0 + kk) * Nc + bn + col];
        }
        __syncthreads();
        #pragma unroll
        for (int kk = 0; kk < 16; kk++) {
            float a[8], b[8];
            *(float4*)&a[0] = *(const float4*)&As[kk][ty * 8];
            *(float4*)&a[4] = *(const float4*)&As[kk][ty * 8 + 4];
            *(float4*)&b[0] = *(const float4*)&Bs[kk][tx * 8];
            *(float4*)&b[4] = *(const float4*)&Bs[kk][tx * 8 + 4];
            #pragma unroll
            for (int i = 0; i < 8; i++)
                #pragma unroll
                for (int j = 0; j < 8; j++) acc[i][j] = fmaf(a[i], b[j], acc[i][j]);
        }
        __syncthreads();
    }
    #pragma unroll
    for (int i = 0; i < 8; i++) {
        int r = bm + ty * 8 + i;
        float zm = (degmask && degmask[r] == 0) ? 0.f : 1.f;
        #pragma unroll
        for (int q = 0; q < 2; q++) {
            int c0 = bn + tx * 8 + q * 4;
            float4 v;
            float* vp = &v.x;
            #pragma unroll
            for (int j = 0; j < 4; j++) {
                float xv = acc[i][q * 4 + j];
                if (bias)   xv += bias[c0 + j];
                if (rowadd) xv += rowadd[(size_t)(r >> 6) * Nc + c0 + j];
                if (do_relu) xv = fmaxf(xv, 0.f);
                vp[j] = xv * zm;
            }
            *(float4*)&C[(size_t)r * Nc + c0] = v;
        }
    }
}

// ---------------- GEMM 128x64 tile, 8x4/thread (small/odd shapes) -----------
__global__ void gemm_kernel(const float* __restrict__ A, const float* __restrict__ W,
                            const float* __restrict__ bias, float* __restrict__ C,
                            int M, int K, int Nc, int do_relu,
                            const int* __restrict__ degmask,
                            const float* __restrict__ rowadd) {
    __shared__ float As[16][132];
    __shared__ float Bs[16][68];
    int bm = blockIdx.y * 128;
    int bn = blockIdx.x * 64;
    int t = threadIdx.x;
    int ty = t >> 4, tx = t & 15;
    float acc[8][4] = {};
    for (int k0 = 0; k0 < K; k0 += 16) {
        #pragma unroll
        for (int i = 0; i < 2; i++) {
            int idx = t + i * 256;
            int row = idx >> 2;
            int kq = (idx & 3) << 2;
            float4 v = *(const float4*)&A[(size_t)(bm + row) * K + k0 + kq];
            As[kq + 0][row] = v.x;
            As[kq + 1][row] = v.y;
            As[kq + 2][row] = v.z;
            As[kq + 3][row] = v.w;
        }
        {
            int kk = t >> 4;
            int col = (t & 15) << 2;
            *(float4*)&Bs[kk][col] = *(const float4*)&W[(size_t)(k0 + kk) * Nc + bn + col];
        }
        __syncthreads();
        #pragma unroll
        for (int kk = 0; kk < 16; kk++) {
            float a[8], b[4];
            *(float4*)&a[0] = *(const float4*)&As[kk][ty * 8];
            *(float4*)&a[4] = *(const float4*)&As[kk][ty * 8 + 4];
            *(float4*)&b[0] = *(const float4*)&Bs[kk][tx * 4];
            #pragma unroll
            for (int i = 0; i < 8; i++)
                #pragma unroll
                for (int j = 0; j < 4; j++) acc[i][j] = fmaf(a[i], b[j], acc[i][j]);
        }
        __syncthreads();
    }
    #pragma unroll
    for (int i = 0; i < 8; i++) {
        int r = bm + ty * 8 + i;
        float zm = (degmask && degmask[r] == 0) ? 0.f : 1.f;
        int c0 = bn + tx * 4;
        float4 v;
        float* vp = &v.x;
        #pragma unroll
        for (int j = 0; j < 4; j++) {
            float xv = acc[i][j];
            if (bias)   xv += bias[c0 + j];
            if (rowadd) xv += rowadd[(size_t)(r >> 6) * Nc + c0 + j];
            if (do_relu) xv = fmaxf(xv, 0.f);
            vp[j] = xv * zm;
        }
        *(float4*)&C[(size_t)r * Nc + c0] = v;
    }
}

// ---------------- edge aggregation (CSR, one warp per dst node) -------------

__global__ void agg1_kernel() {
    int w = (blockIdx.x * blockDim.x + threadIdx.x) >> 5;
    int lane = threadIdx.x & 31;
    int deg = g_deg[w], start = g_off[w];
    float4 a = *(const float4*)&g_AB1[(size_t)w * 256 + lane * 4];
    float4 acc = {0.f, 0.f, 0.f, 0.f};
    int s = (deg > 0) ? g_csr[start] : 0;
    for (int i = 0; i < deg; i++) {
        int snext = (i + 1 < deg) ? g_csr[start + i + 1] : 0;
        float4 b = *(const float4*)&g_AB1[(size_t)s * 256 + 128 + lane * 4];
        acc.x += fmaxf(a.x + b.x, 0.f);
        acc.y += fmaxf(a.y + b.y, 0.f);
        acc.z += fmaxf(a.z + b.z, 0.f);
        acc.w += fmaxf(a.w + b.w, 0.f);
        s = snext;
    }
    float inv = 1.f / fmaxf((float)deg, 1.f);
    float4 o = {acc.x * inv, acc.y * inv, acc.z * inv, acc.w * inv};
    *(float4*)&g_sum1[(size_t)w * 128 + lane * 4] = o;
}

__global__ void agg2_kernel() {
    int w = (blockIdx.x * blockDim.x + threadIdx.x) >> 5;
    int lane = threadIdx.x & 31;
    int deg = g_deg[w], start = g_off[w];
    float2 a = *(const float2*)&g_AB2[(size_t)w * 128 + lane * 2];
    float2 acc = {0.f, 0.f};
    int s = (deg > 0) ? g_csr[start] : 0;
    for (int i = 0; i < deg; i++) {
        int snext = (i + 1 < deg) ? g_csr[start + i + 1] : 0;
        float2 b = *(const float2*)&g_AB2[(size_t)s * 128 + 64 + lane * 2];
        acc.x += fmaxf(a.x + b.x, 0.f);
        acc.y += fmaxf(a.y + b.y, 0.f);
        s = snext;
    }
    float inv = 1.f / fmaxf((float)deg, 1.f);
    float2 o = {acc.x * inv, acc.y * inv};
    *(float2*)&g_sum2[(size_t)w * 64 + lane * 2] = o;
}

// ---------------- tail kernels -----------------------------------------------

__global__ void ge_kernel() {
    int g = blockIdx.x;
    int c = threadIdx.x;
    float s = 0.f;
    #pragma unroll 8
    for (int r = 0; r < 64; r++) s += g_h2[(size_t)(g * 64 + r) * 64 + c];
    g_ge[g * 64 + c] = s * (1.f / 64.f);
}

__global__ void z_kernel(const float* __restrict__ state, const float* __restrict__ action) {
    unsigned idx = blockIdx.x * blockDim.x + threadIdx.x;
    if (idx >= NB * 192) return;
    int b = idx / 192, j = idx % 192;
    float v;
    if (j < 96)       v = state[b * 96 + j];
    else if (j < 128) v = action[b * 32 + (j - 96)];
    else              v = g_ge[b * 64 + (j - 128)];
    g_z[idx] = v;
}

__global__ void qdot_kernel(const float* __restrict__ t2, const float* __restrict__ w3,
                            const float* __restrict__ b3, float* __restrict__ out) {
    int warp = (blockIdx.x * blockDim.x + threadIdx.x) >> 5;
    int lane = threadIdx.x & 31;
    if (warp >= NB) return;
    float s = 0.f;
    #pragma unroll
    for (int k = lane; k < 256; k += 32) s += t2[warp * 256 + k] * w3[k];
    #pragma unroll
    for (int o = 16; o > 0; o >>= 1) s += __shfl_down_sync(0xffffffffu, s, o);
    if (lane == 0) out[warp] = s + b3[0];
}

// ---------------- launch ------------------------------------------------------

extern "C" void kernel_launch(void* const* d_in, const int* in_sizes, int n_in,
                              void* d_out, int out_size) {
    const float* state  = (const float*)d_in[0];
    const float* action = (const float*)d_in[1];
    const float* x      = (const float*)d_in[2];
    const int*   eidx   = (const int*)d_in[3];
    const float* g1_w1 = (const float*)d_in[5];
    const float* g1_b1 = (const float*)d_in[6];
    const float* g1_w2 = (const float*)d_in[7];
    const float* g1_b2 = (const float*)d_in[8];
    const float* g2_w1 = (const float*)d_in[9];
    const float* g2_b1 = (const float*)d_in[10];
    const float* g2_w2 = (const float*)d_in[11];
    const float* g2_b2 = (const float*)d_in[12];
    const float* q1_w1 = (const float*)d_in[13];
    const float* q1_b1 = (const float*)d_in[14];
    const float* q1_w2 = (const float*)d_in[15];
    const float* q1_b2 = (const float*)d_in[16];
    const float* q1_w3 = (const float*)d_in[17];
    const float* q1_b3 = (const float*)d_in[18];
    const float* q2_w1 = (const float*)d_in[19];
    const float* q2_b1 = (const float*)d_in[20];
    const float* q2_w2 = (const float*)d_in[21];
    const float* q2_b2 = (const float*)d_in[22];
    const float* q2_w3 = (const float*)d_in[23];
    const float* q2_b3 = (const float*)d_in[24];
    float* out = (float*)d_out;

    const int* srcs = eidx;
    const int* dsts = eidx + NE;

    float *p_AB1, *p_sum1, *p_h1, *p_AB2, *p_sum2, *p_h2;
    float *p_z, *p_t1, *p_t2, *p_W1, *p_b1, *p_W2, *p_b2, *p_act;
    int *p_deg;
    cudaGetSymbolAddress((void**)&p_AB1,  g_AB1);
    cudaGetSymbolAddress((void**)&p_sum1, g_sum1);
    cudaGetSymbolAddress((void**)&p_h1,   g_h1);
    cudaGetSymbolAddress((void**)&p_AB2,  g_AB2);
    cudaGetSymbolAddress((void**)&p_sum2, g_sum2);
    cudaGetSymbolAddress((void**)&p_h2,   g_h2);
    cudaGetSymbolAddress((void**)&p_z,    g_z);
    cudaGetSymbolAddress((void**)&p_t1,   g_t1);
    cudaGetSymbolAddress((void**)&p_t2,   g_t2);
    cudaGetSymbolAddress((void**)&p_W1,   g_W1);
    cudaGetSymbolAddress((void**)&p_b1,   g_bias1);
    cudaGetSymbolAddress((void**)&p_W2,   g_W2);
    cudaGetSymbolAddress((void**)&p_b2,   g_bias2);
    cudaGetSymbolAddress((void**)&p_act,  g_actterm);
    cudaGetSymbolAddress((void**)&p_deg,  g_deg);

    // CSR build (hierarchical scan)
    zero_deg_kernel<<<NN / 256, 256>>>();
    prep_kernel<<<(128 * 256 + 256 + 128 * 128 + 128 + 255) / 256, 256>>>(g1_w1, g1_b1, g2_w1, g2_b1);
    count_kernel<<<NE / 256, 256>>>(dsts);
    blocksum_kernel<<<256, 256>>>();
    bscan_kernel<<<1, 256>>>();
    fill_kernel<<<256, 256>>>();
    scatter_kernel<<<NE / 256, 256>>>(srcs, dsts);

    // actterm[B,256] = action @ W1cat[96:128] + b1cat
    gemm_kernel<<<dim3(256 / 64, NB / 128), 256>>>(action, p_W1 + 96 * 256, p_b1, p_act,
                                                   NB, 32, 256, 0, nullptr, nullptr);
    // AB1 = x @ W1cat[0:96] + actterm[graph]
    gemm128_kernel<<<dim3(256 / 128, NN / 128), 256>>>(x, p_W1, nullptr, p_AB1,
                                                       NN, 96, 256, 0, nullptr, p_act);
    // edge phase 1
    agg1_kernel<<<NN / 8, 256>>>();
    // h1 = relu(mean1 @ g1_w2 + b2), deg-0 masked
    gemm128_kernel<<<dim3(128 / 128, NN / 128), 256>>>(p_sum1, g1_w2, g1_b2, p_h1,
                                                       NN, 128, 128, 1, p_deg, nullptr);
    // AB2 = h1 @ W2cat + [b2_1|0]
    gemm128_kernel<<<dim3(128 / 128, NN / 128), 256>>>(p_h1, p_W2, p_b2, p_AB2,
                                                       NN, 128, 128, 0, nullptr, nullptr);
    // edge phase 2
    agg2_kernel<<<NN / 8, 256>>>();
    // h2 = mean2 @ g2_w2 + g2_b2, deg-0 masked
    gemm_kernel<<<dim3(64 / 64, NN / 128), 256>>>(p_sum2, g2_w2, g2_b2, p_h2,
                                                  NN, 64, 64, 0, p_deg, nullptr);
    // graph embedding + z
    ge_kernel<<<NB, 64>>>();
    z_kernel<<<(NB * 192 + 255) / 256, 256>>>(state, action);
    // Q heads
    gemm_kernel<<<dim3(256 / 64, NB / 128), 256>>>(p_z, q1_w1, q1_b1, p_t1, NB, 192, 256, 1, nullptr, nullptr);
    gemm_kernel<<<dim3(256 / 64, NB / 128), 256>>>(p_t1, q1_w2, q1_b2, p_t2, NB, 256, 256, 1, nullptr, nullptr);
    qdot_kernel<<<(NB * 32 + 255) / 256, 256>>>(p_t2, q1_w3, q1_b3, out);
    gemm_kernel<<<dim3(256 / 64, NB / 128), 256>>>(p_z, q2_w1, q2_b1, p_t1, NB, 192, 256, 1, nullptr, nullptr);
    gemm_kernel<<<dim3(256 / 64, NB / 128), 256>>>(p_t1, q2_w2, q2_b2, p_t2, NB, 256, 256, 1, nullptr, nullptr);
    qdot_kernel<<<(NB * 32 + 255) / 256, 256>>>(p_t2, q2_w3, q2_b3, out + NB);
}

// round 4
// speedup vs baseline: 3.1658x; 1.6564x over previous
#include <cuda_runtime.h>
#include <cstdint>

#define NN 65536
#define NE 524288
#define NB 1024

// ---------------- scratch (device globals) ----------------------------------
__device__ float g_AB1[NN * 256];
__device__ float g_sum1[NN * 128];
__device__ float g_h1[NN * 128];
__device__ float g_AB2[NN * 128];
__device__ float g_sum2[NN * 64];
__device__ float g_h2[NN * 64];
__device__ float g_ge[NB * 64];
__device__ float g_z[NB * 192];
__device__ float g_t1[NB * 256];
__device__ float g_t2[NB * 256];
__device__ float g_actterm[NB * 256];
__device__ float g_W1[128 * 256];
__device__ float g_bias1[256];
__device__ float g_W2[128 * 128];
__device__ float g_bias2[128];
__device__ int   g_deg[NN];
__device__ int   g_off[NN];
__device__ int   g_cur[NN];
__device__ int   g_csr[NE];
__device__ int   g_bsum[256];
__device__ int   g_boff[256];

// ---------------- small kernels ---------------------------------------------

__global__ void zero_deg_kernel() {
    unsigned idx = blockIdx.x * blockDim.x + threadIdx.x;
    if (idx < NN) g_deg[idx] = 0;
}

__global__ void prep_kernel(const float* __restrict__ g1w1, const float* __restrict__ g1b1,
                            const float* __restrict__ g2w1, const float* __restrict__ g2b1) {
    int idx = blockIdx.x * blockDim.x + threadIdx.x;
    if (idx < 128 * 256) {
        int k = idx >> 8, j = idx & 255;
        g_W1[idx] = (j < 128) ? g1w1[k * 128 + j] : g1w1[(k + 128) * 128 + (j - 128)];
    } else if (idx < 128 * 256 + 256) {
        int j = idx - 128 * 256;
        g_bias1[j] = (j < 128) ? g1b1[j] : 0.f;
    } else if (idx < 128 * 256 + 256 + 128 * 128) {
        int i2 = idx - (128 * 256 + 256);
        int k = i2 >> 7, j = i2 & 127;
        g_W2[i2] = (j < 64) ? g2w1[k * 64 + j] : g2w1[(k + 128) * 64 + (j - 64)];
    } else if (idx < 128 * 256 + 256 + 128 * 128 + 128) {
        int j = idx - (128 * 256 + 256 + 128 * 128);
        g_bias2[j] = (j < 64) ? g2b1[j] : 0.f;
    }
}

__global__ void count_kernel(const int* __restrict__ dst) {
    int e = blockIdx.x * blockDim.x + threadIdx.x;
    if (e < NE) atomicAdd(&g_deg[dst[e]], 1);
}

__global__ void blocksum_kernel() {
    __shared__ int sh[256];
    int t = threadIdx.x;
    sh[t] = g_deg[blockIdx.x * 256 + t];
    __syncthreads();
    for (int off = 128; off > 0; off >>= 1) {
        if (t < off) sh[t] += sh[t + off];
        __syncthreads();
    }
    if (t == 0) g_bsum[blockIdx.x] = sh[0];
}

__global__ void bscan_kernel() {
    __shared__ int sh[256];
    int t = threadIdx.x;
    sh[t] = g_bsum[t];
    __syncthreads();
    for (int off = 1; off < 256; off <<= 1) {
        int v = (t >= off) ? sh[t - off] : 0;
        __syncthreads();
        sh[t] += v;
        __syncthreads();
    }
    g_boff[t] = sh[t] - g_bsum[t];
}

__global__ void fill_kernel() {
    __shared__ int sh[256];
    int t = threadIdx.x;
    int gi = blockIdx.x * 256 + t;
    int d = g_deg[gi];
    sh[t] = d;
    __syncthreads();
    for (int off = 1; off < 256; off <<= 1) {
        int v = (t >= off) ? sh[t - off] : 0;
        __syncthreads();
        sh[t] += v;
        __syncthreads();
    }
    int excl = sh[t] - d + g_boff[blockIdx.x];
    g_off[gi] = excl;
    g_cur[gi] = excl;
}

__global__ void scatter_kernel(const int* __restrict__ src, const int* __restrict__ dst) {
    int e = blockIdx.x * blockDim.x + threadIdx.x;
    if (e < NE) {
        int pos = atomicAdd(&g_cur[dst[e]], 1);
        g_csr[pos] = src[e];
    }
}

// ---------------- tf32 tensor-core GEMM --------------------------------------
// C[M,Nc] = act(A@W + bias + rowadd), 128x128 tile, BK=32, mma.m16n8k8.tf32
// requires M%128==0, Nc%128==0, K%32==0

__device__ __forceinline__ float to_tf32(float x) {
    uint32_t u;
    asm("cvt.rna.tf32.f32 %0, %1;" : "=r"(u) : "f"(x));
    return __uint_as_float(u);
}

__global__ void __launch_bounds__(256)
gemm_tf32_kernel(const float* __restrict__ A, const float* __restrict__ W,
                 const float* __restrict__ bias, float* __restrict__ C,
                 int M, int K, int Nc, int do_relu,
                 const int* __restrict__ degmask,
                 const float* __restrict__ rowadd) {
    __shared__ float As[128 * 36];   // [row][k], stride 36
    __shared__ float Bs[32 * 136];   // [k][n], stride 136
    int bm = blockIdx.y * 128;
    int bn = blockIdx.x * 128;
    int t = threadIdx.x;
    int warp = t >> 5, lane = t & 31;
    int wm = warp >> 2, wn = warp & 3;          // 2 x 4 warps
    int gid = lane >> 2, tig = lane & 3;
    float acc[4][4][4];
    #pragma unroll
    for (int a = 0; a < 4; a++)
        #pragma unroll
        for (int b = 0; b < 4; b++)
            #pragma unroll
            for (int c = 0; c < 4; c++) acc[a][b][c] = 0.f;

    for (int k0 = 0; k0 < K; k0 += 32) {
        #pragma unroll
        for (int i = 0; i < 4; i++) {
            int idx = t + i * 256;
            int row = idx >> 3, kq = (idx & 7) << 2;
            float4 v = *(const float4*)&A[(size_t)(bm + row) * K + k0 + kq];
            v.x = to_tf32(v.x); v.y = to_tf32(v.y);
            v.z = to_tf32(v.z); v.w = to_tf32(v.w);
            *(float4*)&As[row * 36 + kq] = v;
        }
        #pragma unroll
        for (int i = 0; i < 4; i++) {
            int idx = t + i * 256;
            int kk = idx >> 5, n4 = (idx & 31) << 2;
            float4 v = *(const float4*)&W[(size_t)(k0 + kk) * Nc + bn + n4];
            v.x = to_tf32(v.x); v.y = to_tf32(v.y);
            v.z = to_tf32(v.z); v.w = to_tf32(v.w);
            *(float4*)&Bs[kk * 136 + n4] = v;
        }
        __syncthreads();
        #pragma unroll
        for (int ks = 0; ks < 32; ks += 8) {
            uint32_t af[4][4], bf[4][2];
            #pragma unroll
            for (int mt = 0; mt < 4; mt++) {
                const float* ap = &As[(wm * 64 + mt * 16 + gid) * 36 + ks + tig];
                af[mt][0] = __float_as_uint(ap[0]);
                af[mt][1] = __float_as_uint(ap[8 * 36]);
                af[mt][2] = __float_as_uint(ap[4]);
                af[mt][3] = __float_as_uint(ap[8 * 36 + 4]);
            }
            #pragma unroll
            for (int nt = 0; nt < 4; nt++) {
                const float* bp = &Bs[(ks + tig) * 136 + wn * 32 + nt * 8 + gid];
                bf[nt][0] = __float_as_uint(bp[0]);
                bf[nt][1] = __float_as_uint(bp[4 * 136]);
            }
            #pragma unroll
            for (int mt = 0; mt < 4; mt++)
                #pragma unroll
                for (int nt = 0; nt < 4; nt++) {
                    asm volatile(
                        "mma.sync.aligned.m16n8k8.row.col.f32.tf32.tf32.f32 "
                        "{%0,%1,%2,%3}, {%4,%5,%6,%7}, {%8,%9}, {%0,%1,%2,%3};"
                        : "+f"(acc[mt][nt][0]), "+f"(acc[mt][nt][1]),
                          "+f"(acc[mt][nt][2]), "+f"(acc[mt][nt][3])
                        : "r"(af[mt][0]), "r"(af[mt][1]), "r"(af[mt][2]), "r"(af[mt][3]),
                          "r"(bf[nt][0]), "r"(bf[nt][1]));
                }
        }
        __syncthreads();
    }

    // epilogue
    #pragma unroll
    for (int mt = 0; mt < 4; mt++) {
        int r0 = bm + wm * 64 + mt * 16 + gid;
        int r1 = r0 + 8;
        float zm0 = (degmask && degmask[r0] == 0) ? 0.f : 1.f;
        float zm1 = (degmask && degmask[r1] == 0) ? 0.f : 1.f;
        #pragma unroll
        for (int nt = 0; nt < 4; nt++) {
            int c0 = bn + wn * 32 + nt * 8 + 2 * tig;
            float b0 = bias ? bias[c0] : 0.f;
            float b1 = bias ? bias[c0 + 1] : 0.f;
            float ra00 = 0.f, ra01 = 0.f, ra10 = 0.f, ra11 = 0.f;
            if (rowadd) {
                ra00 = rowadd[(size_t)(r0 >> 6) * Nc + c0];
                ra01 = rowadd[(size_t)(r0 >> 6) * Nc + c0 + 1];
                ra10 = rowadd[(size_t)(r1 >> 6) * Nc + c0];
                ra11 = rowadd[(size_t)(r1 >> 6) * Nc + c0 + 1];
            }
            float v00 = acc[mt][nt][0] + b0 + ra00;
            float v01 = acc[mt][nt][1] + b1 + ra01;
            float v10 = acc[mt][nt][2] + b0 + ra10;
            float v11 = acc[mt][nt][3] + b1 + ra11;
            if (do_relu) {
                v00 = fmaxf(v00, 0.f); v01 = fmaxf(v01, 0.f);
                v10 = fmaxf(v10, 0.f); v11 = fmaxf(v11, 0.f);
            }
            float2 o0 = {v00 * zm0, v01 * zm0};
            float2 o1 = {v10 * zm1, v11 * zm1};
            *(float2*)&C[(size_t)r0 * Nc + c0] = o0;
            *(float2*)&C[(size_t)r1 * Nc + c0] = o1;
        }
    }
}

// ---------------- fp32 GEMM 128x64 tile (small/odd shapes) -------------------
__global__ void gemm_kernel(const float* __restrict__ A, const float* __restrict__ W,
                            const float* __restrict__ bias, float* __restrict__ C,
                            int M, int K, int Nc, int do_relu,
                            const int* __restrict__ degmask,
                            const float* __restrict__ rowadd) {
    __shared__ float As[16][132];
    __shared__ float Bs[16][68];
    int bm = blockIdx.y * 128;
    int bn = blockIdx.x * 64;
    int t = threadIdx.x;
    int ty = t >> 4, tx = t & 15;
    float acc[8][4] = {};
    for (int k0 = 0; k0 < K; k0 += 16) {
        #pragma unroll
        for (int i = 0; i < 2; i++) {
            int idx = t + i * 256;
            int row = idx >> 2;
            int kq = (idx & 3) << 2;
            float4 v = *(const float4*)&A[(size_t)(bm + row) * K + k0 + kq];
            As[kq + 0][row] = v.x;
            As[kq + 1][row] = v.y;
            As[kq + 2][row] = v.z;
            As[kq + 3][row] = v.w;
        }
        {
            int kk = t >> 4;
            int col = (t & 15) << 2;
            *(float4*)&Bs[kk][col] = *(const float4*)&W[(size_t)(k0 + kk) * Nc + bn + col];
        }
        __syncthreads();
        #pragma unroll
        for (int kk = 0; kk < 16; kk++) {
            float a[8], b[4];
            *(float4*)&a[0] = *(const float4*)&As[kk][ty * 8];
            *(float4*)&a[4] = *(const float4*)&As[kk][ty * 8 + 4];
            *(float4*)&b[0] = *(const float4*)&Bs[kk][tx * 4];
            #pragma unroll
            for (int i = 0; i < 8; i++)
                #pragma unroll
                for (int j = 0; j < 4; j++) acc[i][j] = fmaf(a[i], b[j], acc[i][j]);
        }
        __syncthreads();
    }
    #pragma unroll
    for (int i = 0; i < 8; i++) {
        int r = bm + ty * 8 + i;
        float zm = (degmask && degmask[r] == 0) ? 0.f : 1.f;
        int c0 = bn + tx * 4;
        float4 v;
        float* vp = &v.x;
        #pragma unroll
        for (int j = 0; j < 4; j++) {
            float xv = acc[i][j];
            if (bias)   xv += bias[c0 + j];
            if (rowadd) xv += rowadd[(size_t)(r >> 6) * Nc + c0 + j];
            if (do_relu) xv = fmaxf(xv, 0.f);
            vp[j] = xv * zm;
        }
        *(float4*)&C[(size_t)r * Nc + c0] = v;
    }
}

// ---------------- edge aggregation (CSR, one warp per dst node) -------------

__global__ void agg1_kernel() {
    int w = (blockIdx.x * blockDim.x + threadIdx.x) >> 5;
    int lane = threadIdx.x & 31;
    int deg = g_deg[w], start = g_off[w];
    float4 a = *(const float4*)&g_AB1[(size_t)w * 256 + lane * 4];
    float4 acc = {0.f, 0.f, 0.f, 0.f};
    int s = (deg > 0) ? g_csr[start] : 0;
    for (int i = 0; i < deg; i++) {
        int snext = (i + 1 < deg) ? g_csr[start + i + 1] : 0;
        float4 b = *(const float4*)&g_AB1[(size_t)s * 256 + 128 + lane * 4];
        acc.x += fmaxf(a.x + b.x, 0.f);
        acc.y += fmaxf(a.y + b.y, 0.f);
        acc.z += fmaxf(a.z + b.z, 0.f);
        acc.w += fmaxf(a.w + b.w, 0.f);
        s = snext;
    }
    float inv = 1.f / fmaxf((float)deg, 1.f);
    float4 o = {acc.x * inv, acc.y * inv, acc.z * inv, acc.w * inv};
    *(float4*)&g_sum1[(size_t)w * 128 + lane * 4] = o;
}

__global__ void agg2_kernel() {
    int w = (blockIdx.x * blockDim.x + threadIdx.x) >> 5;
    int lane = threadIdx.x & 31;
    int deg = g_deg[w], start = g_off[w];
    float2 a = *(const float2*)&g_AB2[(size_t)w * 128 + lane * 2];
    float2 acc = {0.f, 0.f};
    int s = (deg > 0) ? g_csr[start] : 0;
    for (int i = 0; i < deg; i++) {
        int snext = (i + 1 < deg) ? g_csr[start + i + 1] : 0;
        float2 b = *(const float2*)&g_AB2[(size_t)s * 128 + 64 + lane * 2];
        acc.x += fmaxf(a.x + b.x, 0.f);
        acc.y += fmaxf(a.y + b.y, 0.f);
        s = snext;
    }
    float inv = 1.f / fmaxf((float)deg, 1.f);
    float2 o = {acc.x * inv, acc.y * inv};
    *(float2*)&g_sum2[(size_t)w * 64 + lane * 2] = o;
}

// ---------------- tail kernels -----------------------------------------------

__global__ void ge_kernel() {
    int g = blockIdx.x;
    int c = threadIdx.x;
    float s = 0.f;
    #pragma unroll 8
    for (int r = 0; r < 64; r++) s += g_h2[(size_t)(g * 64 + r) * 64 + c];
    g_ge[g * 64 + c] = s * (1.f / 64.f);
}

__global__ void z_kernel(const float* __restrict__ state, const float* __restrict__ action) {
    unsigned idx = blockIdx.x * blockDim.x + threadIdx.x;
    if (idx >= NB * 192) return;
    int b = idx / 192, j = idx % 192;
    float v;
    if (j < 96)       v = state[b * 96 + j];
    else if (j < 128) v = action[b * 32 + (j - 96)];
    else              v = g_ge[b * 64 + (j - 128)];
    g_z[idx] = v;
}

__global__ void qdot_kernel(const float* __restrict__ t2, const float* __restrict__ w3,
                            const float* __restrict__ b3, float* __restrict__ out) {
    int warp = (blockIdx.x * blockDim.x + threadIdx.x) >> 5;
    int lane = threadIdx.x & 31;
    if (warp >= NB) return;
    float s = 0.f;
    #pragma unroll
    for (int k = lane; k < 256; k += 32) s += t2[warp * 256 + k] * w3[k];
    #pragma unroll
    for (int o = 16; o > 0; o >>= 1) s += __shfl_down_sync(0xffffffffu, s, o);
    if (lane == 0) out[warp] = s + b3[0];
}

// ---------------- launch ------------------------------------------------------

extern "C" void kernel_launch(void* const* d_in, const int* in_sizes, int n_in,
                              void* d_out, int out_size) {
    const float* state  = (const float*)d_in[0];
    const float* action = (const float*)d_in[1];
    const float* x      = (const float*)d_in[2];
    const int*   eidx   = (const int*)d_in[3];
    const float* g1_w1 = (const float*)d_in[5];
    const float* g1_b1 = (const float*)d_in[6];
    const float* g1_w2 = (const float*)d_in[7];
    const float* g1_b2 = (const float*)d_in[8];
    const float* g2_w1 = (const float*)d_in[9];
    const float* g2_b1 = (const float*)d_in[10];
    const float* g2_w2 = (const float*)d_in[11];
    const float* g2_b2 = (const float*)d_in[12];
    const float* q1_w1 = (const float*)d_in[13];
    const float* q1_b1 = (const float*)d_in[14];
    const float* q1_w2 = (const float*)d_in[15];
    const float* q1_b2 = (const float*)d_in[16];
    const float* q1_w3 = (const float*)d_in[17];
    const float* q1_b3 = (const float*)d_in[18];
    const float* q2_w1 = (const float*)d_in[19];
    const float* q2_b1 = (const float*)d_in[20];
    const float* q2_w2 = (const float*)d_in[21];
    const float* q2_b2 = (const float*)d_in[22];
    const float* q2_w3 = (const float*)d_in[23];
    const float* q2_b3 = (const float*)d_in[24];
    float* out = (float*)d_out;

    const int* srcs = eidx;
    const int* dsts = eidx + NE;

    float *p_AB1, *p_sum1, *p_h1, *p_AB2, *p_sum2, *p_h2;
    float *p_z, *p_t1, *p_t2, *p_W1, *p_b1, *p_W2, *p_b2, *p_act;
    int *p_deg;
    cudaGetSymbolAddress((void**)&p_AB1,  g_AB1);
    cudaGetSymbolAddress((void**)&p_sum1, g_sum1);
    cudaGetSymbolAddress((void**)&p_h1,   g_h1);
    cudaGetSymbolAddress((void**)&p_AB2,  g_AB2);
    cudaGetSymbolAddress((void**)&p_sum2, g_sum2);
    cudaGetSymbolAddress((void**)&p_h2,   g_h2);
    cudaGetSymbolAddress((void**)&p_z,    g_z);
    cudaGetSymbolAddress((void**)&p_t1,   g_t1);
    cudaGetSymbolAddress((void**)&p_t2,   g_t2);
    cudaGetSymbolAddress((void**)&p_W1,   g_W1);
    cudaGetSymbolAddress((void**)&p_b1,   g_bias1);
    cudaGetSymbolAddress((void**)&p_W2,   g_W2);
    cudaGetSymbolAddress((void**)&p_b2,   g_bias2);
    cudaGetSymbolAddress((void**)&p_act,  g_actterm);
    cudaGetSymbolAddress((void**)&p_deg,  g_deg);

    // CSR build
    zero_deg_kernel<<<NN / 256, 256>>>();
    prep_kernel<<<(128 * 256 + 256 + 128 * 128 + 128 + 255) / 256, 256>>>(g1_w1, g1_b1, g2_w1, g2_b1);
    count_kernel<<<NE / 256, 256>>>(dsts);
    blocksum_kernel<<<256, 256>>>();
    bscan_kernel<<<1, 256>>>();
    fill_kernel<<<256, 256>>>();
    scatter_kernel<<<NE / 256, 256>>>(srcs, dsts);

    // actterm[B,256] = action @ W1cat[96:128] + b1cat  (fp32, tiny)
    gemm_kernel<<<dim3(256 / 64, NB / 128), 256>>>(action, p_W1 + 96 * 256, p_b1, p_act,
                                                   NB, 32, 256, 0, nullptr, nullptr);
    // AB1 = x @ W1cat[0:96] + actterm[graph]   (tf32, K=96)
    gemm_tf32_kernel<<<dim3(256 / 128, NN / 128), 256>>>(x, p_W1, nullptr, p_AB1,
                                                         NN, 96, 256, 0, nullptr, p_act);
    // edge phase 1
    agg1_kernel<<<NN / 8, 256>>>();
    // h1 = relu(mean1 @ g1_w2 + b2), deg-0 masked  (tf32)
    gemm_tf32_kernel<<<dim3(128 / 128, NN / 128), 256>>>(p_sum1, g1_w2, g1_b2, p_h1,
                                                         NN, 128, 128, 1, p_deg, nullptr);
    // AB2 = h1 @ W2cat + [b2_1|0]  (tf32)
    gemm_tf32_kernel<<<dim3(128 / 128, NN / 128), 256>>>(p_h1, p_W2, p_b2, p_AB2,
                                                         NN, 128, 128, 0, nullptr, nullptr);
    // edge phase 2
    agg2_kernel<<<NN / 8, 256>>>();
    // h2 = mean2 @ g2_w2 + g2_b2, deg-0 masked  (fp32, N=64)
    gemm_kernel<<<dim3(64 / 64, NN / 128), 256>>>(p_sum2, g2_w2, g2_b2, p_h2,
                                                  NN, 64, 64, 0, p_deg, nullptr);
    // graph embedding + z
    ge_kernel<<<NB, 64>>>();
    z_kernel<<<(NB * 192 + 255) / 256, 256>>>(state, action);
    // Q heads (tf32)
    gemm_tf32_kernel<<<dim3(256 / 128, NB / 128), 256>>>(p_z, q1_w1, q1_b1, p_t1,
                                                         NB, 192, 256, 1, nullptr, nullptr);
    gemm_tf32_kernel<<<dim3(256 / 128, NB / 128), 256>>>(p_t1, q1_w2, q1_b2, p_t2,
                                                         NB, 256, 256, 1, nullptr, nullptr);
    qdot_kernel<<<(NB * 32 + 255) / 256, 256>>>(p_t2, q1_w3, q1_b3, out);
    gemm_tf32_kernel<<<dim3(256 / 128, NB / 128), 256>>>(p_z, q2_w1, q2_b1, p_t1,
                                                         NB, 192, 256, 1, nullptr, nullptr);
    gemm_tf32_kernel<<<dim3(256 / 128, NB / 128), 256>>>(p_t1, q2_w2, q2_b2, p_t2,
                                                         NB, 256, 256, 1, nullptr, nullptr);
    qdot_kernel<<<(NB * 32 + 255) / 256, 256>>>(p_t2, q2_w3, q2_b3, out + NB);
}

// round 5
// speedup vs baseline: 3.4333x; 1.0845x over previous
#include <cuda_runtime.h>
#include <cstdint>

#define NN 65536
#define NE 524288
#define NB 1024

// ---------------- scratch (device globals) ----------------------------------
__device__ float g_AB1[NN * 256];
__device__ float g_sum1[NN * 128];
__device__ float g_h1[NN * 128];
__device__ float g_AB2[NN * 128];
__device__ float g_sum2[NN * 64];
__device__ float g_z[NB * 192];
__device__ float g_t1[NB * 512];
__device__ float g_t2[2 * NB * 256];
__device__ float g_actterm[NB * 256];
__device__ float g_W1[128 * 256];
__device__ float g_bias1[256];
__device__ float g_W2[128 * 128];
__device__ float g_bias2[128];
__device__ float g_QW1[192 * 512];
__device__ float g_Qb1[512];
__device__ int   g_deg[NN];
__device__ int   g_off[NN];
__device__ int   g_cur[NN];
__device__ int   g_csr[NE];
__device__ int   g_bsum[256];
__device__ int   g_boff[256];

// ---------------- small kernels ---------------------------------------------

__global__ void zero_deg_kernel() {
    unsigned idx = blockIdx.x * blockDim.x + threadIdx.x;
    if (idx < NN) g_deg[idx] = 0;
}

__global__ void prep_kernel(const float* __restrict__ g1w1, const float* __restrict__ g1b1,
                            const float* __restrict__ g2w1, const float* __restrict__ g2b1,
                            const float* __restrict__ q1w1, const float* __restrict__ q1b1,
                            const float* __restrict__ q2w1, const float* __restrict__ q2b1) {
    int idx = blockIdx.x * blockDim.x + threadIdx.x;
    if (idx < 32768) {
        int k = idx >> 8, j = idx & 255;
        g_W1[idx] = (j < 128) ? g1w1[k * 128 + j] : g1w1[(k + 128) * 128 + (j - 128)];
    } else if (idx < 33024) {
        int j = idx - 32768;
        g_bias1[j] = (j < 128) ? g1b1[j] : 0.f;
    } else if (idx < 49408) {
        int i2 = idx - 33024;
        int k = i2 >> 7, j = i2 & 127;
        g_W2[i2] = (j < 64) ? g2w1[k * 64 + j] : g2w1[(k + 128) * 64 + (j - 64)];
    } else if (idx < 49536) {
        int j = idx - 49408;
        g_bias2[j] = (j < 64) ? g2b1[j] : 0.f;
    } else if (idx < 147840) {
        int i2 = idx - 49536;
        int k = i2 / 512, c = i2 & 511;
        g_QW1[i2] = (c < 256) ? q1w1[k * 256 + c] : q2w1[k * 256 + (c - 256)];
    } else if (idx < 148352) {
        int j = idx - 147840;
        g_Qb1[j] = (j < 256) ? q1b1[j] : q2b1[j - 256];
    }
}

__global__ void count_kernel(const int* __restrict__ dst) {
    int e = blockIdx.x * blockDim.x + threadIdx.x;
    if (e < NE) atomicAdd(&g_deg[dst[e]], 1);
}

__global__ void blocksum_kernel() {
    __shared__ int sh[256];
    int t = threadIdx.x;
    sh[t] = g_deg[blockIdx.x * 256 + t];
    __syncthreads();
    for (int off = 128; off > 0; off >>= 1) {
        if (t < off) sh[t] += sh[t + off];
        __syncthreads();
    }
    if (t == 0) g_bsum[blockIdx.x] = sh[0];
}

__global__ void bscan_kernel() {
    __shared__ int sh[256];
    int t = threadIdx.x;
    sh[t] = g_bsum[t];
    __syncthreads();
    for (int off = 1; off < 256; off <<= 1) {
        int v = (t >= off) ? sh[t - off] : 0;
        __syncthreads();
        sh[t] += v;
        __syncthreads();
    }
    g_boff[t] = sh[t] - g_bsum[t];
}

__global__ void fill_kernel() {
    __shared__ int sh[256];
    int t = threadIdx.x;
    int gi = blockIdx.x * 256 + t;
    int d = g_deg[gi];
    sh[t] = d;
    __syncthreads();
    for (int off = 1; off < 256; off <<= 1) {
        int v = (t >= off) ? sh[t - off] : 0;
        __syncthreads();
        sh[t] += v;
        __syncthreads();
    }
    int excl = sh[t] - d + g_boff[blockIdx.x];
    g_off[gi] = excl;
    g_cur[gi] = excl;
}

__global__ void scatter_kernel(const int* __restrict__ src, const int* __restrict__ dst) {
    int e = blockIdx.x * blockDim.x + threadIdx.x;
    if (e < NE) {
        int pos = atomicAdd(&g_cur[dst[e]], 1);
        g_csr[pos] = src[e];
    }
}

// ---------------- tf32 tensor-core GEMM --------------------------------------
// C = act(A@W + bias + rowadd); 128x128 tile, BK=32, mma.m16n8k8.tf32
// lda = row stride of A. If gridDim.z==2, blockIdx.z==1 switches to the
// second-head operands (A column offset acoloff, Wb/biasb/Cb).

__device__ __forceinline__ float to_tf32(float x) {
    uint32_t u;
    asm("cvt.rna.tf32.f32 %0, %1;" : "=r"(u) : "f"(x));
    return __uint_as_float(u);
}

__global__ void __launch_bounds__(256)
gemm_tf32_kernel(const float* __restrict__ A, const float* __restrict__ W,
                 const float* __restrict__ bias, float* __restrict__ C,
                 int M, int K, int Nc, int lda, int do_relu,
                 const int* __restrict__ degmask,
                 const float* __restrict__ rowadd,
                 const float* Wb, const float* biasb, float* Cb, int acoloff) {
    if (blockIdx.z == 1) {
        A += acoloff;
        W = Wb;
        bias = biasb;
        C = Cb;
    }
    __shared__ float As[128 * 36];
    __shared__ float Bs[32 * 136];
    int bm = blockIdx.y * 128;
    int bn = blockIdx.x * 128;
    int t = threadIdx.x;
    int warp = t >> 5, lane = t & 31;
    int wm = warp >> 2, wn = warp & 3;
    int gid = lane >> 2, tig = lane & 3;
    float acc[4][4][4];
    #pragma unroll
    for (int a = 0; a < 4; a++)
        #pragma unroll
        for (int b = 0; b < 4; b++)
            #pragma unroll
            for (int c = 0; c < 4; c++) acc[a][b][c] = 0.f;

    for (int k0 = 0; k0 < K; k0 += 32) {
        #pragma unroll
        for (int i = 0; i < 4; i++) {
            int idx = t + i * 256;
            int row = idx >> 3, kq = (idx & 7) << 2;
            float4 v = *(const float4*)&A[(size_t)(bm + row) * lda + k0 + kq];
            v.x = to_tf32(v.x); v.y = to_tf32(v.y);
            v.z = to_tf32(v.z); v.w = to_tf32(v.w);
            *(float4*)&As[row * 36 + kq] = v;
        }
        #pragma unroll
        for (int i = 0; i < 4; i++) {
            int idx = t + i * 256;
            int kk = idx >> 5, n4 = (idx & 31) << 2;
            float4 v = *(const float4*)&W[(size_t)(k0 + kk) * Nc + bn + n4];
            v.x = to_tf32(v.x); v.y = to_tf32(v.y);
            v.z = to_tf32(v.z); v.w = to_tf32(v.w);
            *(float4*)&Bs[kk * 136 + n4] = v;
        }
        __syncthreads();
        #pragma unroll
        for (int ks = 0; ks < 32; ks += 8) {
            uint32_t af[4][4], bf[4][2];
            #pragma unroll
            for (int mt = 0; mt < 4; mt++) {
                const float* ap = &As[(wm * 64 + mt * 16 + gid) * 36 + ks + tig];
                af[mt][0] = __float_as_uint(ap[0]);
                af[mt][1] = __float_as_uint(ap[8 * 36]);
                af[mt][2] = __float_as_uint(ap[4]);
                af[mt][3] = __float_as_uint(ap[8 * 36 + 4]);
            }
            #pragma unroll
            for (int nt = 0; nt < 4; nt++) {
                const float* bp = &Bs[(ks + tig) * 136 + wn * 32 + nt * 8 + gid];
                bf[nt][0] = __float_as_uint(bp[0]);
                bf[nt][1] = __float_as_uint(bp[4 * 136]);
            }
            #pragma unroll
            for (int mt = 0; mt < 4; mt++)
                #pragma unroll
                for (int nt = 0; nt < 4; nt++) {
                    asm volatile(
                        "mma.sync.aligned.m16n8k8.row.col.f32.tf32.tf32.f32 "
                        "{%0,%1,%2,%3}, {%4,%5,%6,%7}, {%8,%9}, {%0,%1,%2,%3};"
                        : "+f"(acc[mt][nt][0]), "+f"(acc[mt][nt][1]),
                          "+f"(acc[mt][nt][2]), "+f"(acc[mt][nt][3])
                        : "r"(af[mt][0]), "r"(af[mt][1]), "r"(af[mt][2]), "r"(af[mt][3]),
                          "r"(bf[nt][0]), "r"(bf[nt][1]));
                }
        }
        __syncthreads();
    }

    #pragma unroll
    for (int mt = 0; mt < 4; mt++) {
        int r0 = bm + wm * 64 + mt * 16 + gid;
        int r1 = r0 + 8;
        float zm0 = (degmask && degmask[r0] == 0) ? 0.f : 1.f;
        float zm1 = (degmask && degmask[r1] == 0) ? 0.f : 1.f;
        #pragma unroll
        for (int nt = 0; nt < 4; nt++) {
            int c0 = bn + wn * 32 + nt * 8 + 2 * tig;
            float b0 = bias ? bias[c0] : 0.f;
            float b1 = bias ? bias[c0 + 1] : 0.f;
            float ra00 = 0.f, ra01 = 0.f, ra10 = 0.f, ra11 = 0.f;
            if (rowadd) {
                ra00 = rowadd[(size_t)(r0 >> 6) * Nc + c0];
                ra01 = rowadd[(size_t)(r0 >> 6) * Nc + c0 + 1];
                ra10 = rowadd[(size_t)(r1 >> 6) * Nc + c0];
                ra11 = rowadd[(size_t)(r1 >> 6) * Nc + c0 + 1];
            }
            float v00 = acc[mt][nt][0] + b0 + ra00;
            float v01 = acc[mt][nt][1] + b1 + ra01;
            float v10 = acc[mt][nt][2] + b0 + ra10;
            float v11 = acc[mt][nt][3] + b1 + ra11;
            if (do_relu) {
                v00 = fmaxf(v00, 0.f); v01 = fmaxf(v01, 0.f);
                v10 = fmaxf(v10, 0.f); v11 = fmaxf(v11, 0.f);
            }
            float2 o0 = {v00 * zm0, v01 * zm0};
            float2 o1 = {v10 * zm1, v11 * zm1};
            *(float2*)&C[(size_t)r0 * Nc + c0] = o0;
            *(float2*)&C[(size_t)r1 * Nc + c0] = o1;
        }
    }
}

// ---------------- fp32 GEMM 128x64 tile (small shapes) -----------------------
__global__ void gemm_kernel(const float* __restrict__ A, const float* __restrict__ W,
                            const float* __restrict__ bias, float* __restrict__ C,
                            int M, int K, int Nc, int do_relu) {
    __shared__ float As[16][132];
    __shared__ float Bs[16][68];
    int bm = blockIdx.y * 128;
    int bn = blockIdx.x * 64;
    int t = threadIdx.x;
    int ty = t >> 4, tx = t & 15;
    float acc[8][4] = {};
    for (int k0 = 0; k0 < K; k0 += 16) {
        #pragma unroll
        for (int i = 0; i < 2; i++) {
            int idx = t + i * 256;
            int row = idx >> 2;
            int kq = (idx & 3) << 2;
            float4 v = *(const float4*)&A[(size_t)(bm + row) * K + k0 + kq];
            As[kq + 0][row] = v.x;
            As[kq + 1][row] = v.y;
            As[kq + 2][row] = v.z;
            As[kq + 3][row] = v.w;
        }
        {
            int kk = t >> 4;
            int col = (t & 15) << 2;
            *(float4*)&Bs[kk][col] = *(const float4*)&W[(size_t)(k0 + kk) * Nc + bn + col];
        }
        __syncthreads();
        #pragma unroll
        for (int kk = 0; kk < 16; kk++) {
            float a[8], b[4];
            *(float4*)&a[0] = *(const float4*)&As[kk][ty * 8];
            *(float4*)&a[4] = *(const float4*)&As[kk][ty * 8 + 4];
            *(float4*)&b[0] = *(const float4*)&Bs[kk][tx * 4];
            #pragma unroll
            for (int i = 0; i < 8; i++)
                #pragma unroll
                for (int j = 0; j < 4; j++) acc[i][j] = fmaf(a[i], b[j], acc[i][j]);
        }
        __syncthreads();
    }
    #pragma unroll
    for (int i = 0; i < 8; i++) {
        int r = bm + ty * 8 + i;
        int c0 = bn + tx * 4;
        float4 v;
        float* vp = &v.x;
        #pragma unroll
        for (int j = 0; j < 4; j++) {
            float xv = acc[i][j] + bias[c0 + j];
            if (do_relu) xv = fmaxf(xv, 0.f);
            vp[j] = xv;
        }
        *(float4*)&C[(size_t)r * Nc + c0] = v;
    }
}

// ---------------- edge aggregation (CSR, one warp per dst node) -------------

__device__ __forceinline__ void acc_relu4(float4& acc, float4 a, float4 b) {
    acc.x += fmaxf(a.x + b.x, 0.f);
    acc.y += fmaxf(a.y + b.y, 0.f);
    acc.z += fmaxf(a.z + b.z, 0.f);
    acc.w += fmaxf(a.w + b.w, 0.f);
}

__global__ void agg1_kernel() {
    int w = (blockIdx.x * blockDim.x + threadIdx.x) >> 5;
    int lane = threadIdx.x & 31;
    int deg = g_deg[w], start = g_off[w];
    float4 a = *(const float4*)&g_AB1[(size_t)w * 256 + lane * 4];
    float4 acc = {0.f, 0.f, 0.f, 0.f};
    int i = 0;
    for (; i + 4 <= deg; i += 4) {
        int s0 = g_csr[start + i + 0];
        int s1 = g_csr[start + i + 1];
        int s2 = g_csr[start + i + 2];
        int s3 = g_csr[start + i + 3];
        float4 b0 = *(const float4*)&g_AB1[(size_t)s0 * 256 + 128 + lane * 4];
        float4 b1 = *(const float4*)&g_AB1[(size_t)s1 * 256 + 128 + lane * 4];
        float4 b2 = *(const float4*)&g_AB1[(size_t)s2 * 256 + 128 + lane * 4];
        float4 b3 = *(const float4*)&g_AB1[(size_t)s3 * 256 + 128 + lane * 4];
        acc_relu4(acc, a, b0);
        acc_relu4(acc, a, b1);
        acc_relu4(acc, a, b2);
        acc_relu4(acc, a, b3);
    }
    for (; i < deg; i++) {
        int s = g_csr[start + i];
        float4 b = *(const float4*)&g_AB1[(size_t)s * 256 + 128 + lane * 4];
        acc_relu4(acc, a, b);
    }
    float inv = 1.f / fmaxf((float)deg, 1.f);
    float4 o = {acc.x * inv, acc.y * inv, acc.z * inv, acc.w * inv};
    *(float4*)&g_sum1[(size_t)w * 128 + lane * 4] = o;
}

__device__ __forceinline__ void acc_relu2(float2& acc, float2 a, float2 b) {
    acc.x += fmaxf(a.x + b.x, 0.f);
    acc.y += fmaxf(a.y + b.y, 0.f);
}

__global__ void agg2_kernel() {
    int w = (blockIdx.x * blockDim.x + threadIdx.x) >> 5;
    int lane = threadIdx.x & 31;
    int deg = g_deg[w], start = g_off[w];
    float2 a = *(const float2*)&g_AB2[(size_t)w * 128 + lane * 2];
    float2 acc = {0.f, 0.f};
    int i = 0;
    for (; i + 4 <= deg; i += 4) {
        int s0 = g_csr[start + i + 0];
        int s1 = g_csr[start + i + 1];
        int s2 = g_csr[start + i + 2];
        int s3 = g_csr[start + i + 3];
        float2 b0 = *(const float2*)&g_AB2[(size_t)s0 * 128 + 64 + lane * 2];
        float2 b1 = *(const float2*)&g_AB2[(size_t)s1 * 128 + 64 + lane * 2];
        float2 b2 = *(const float2*)&g_AB2[(size_t)s2 * 128 + 64 + lane * 2];
        float2 b3 = *(const float2*)&g_AB2[(size_t)s3 * 128 + 64 + lane * 2];
        acc_relu2(acc, a, b0);
        acc_relu2(acc, a, b1);
        acc_relu2(acc, a, b2);
        acc_relu2(acc, a, b3);
    }
    for (; i < deg; i++) {
        int s = g_csr[start + i];
        float2 b = *(const float2*)&g_AB2[(size_t)s * 128 + 64 + lane * 2];
        acc_relu2(acc, a, b);
    }
    float inv = 1.f / fmaxf((float)deg, 1.f);
    float2 o = {acc.x * inv, acc.y * inv};
    *(float2*)&g_sum2[(size_t)w * 64 + lane * 2] = o;
}

// ---------------- per-graph reduce + tiny GEMM → ge written into z ----------
// ge_g = ((sum over nodes of sum2) @ g2_w2 + npos_g * b2) / 64
__global__ void reduce_ge_kernel(const float* __restrict__ w2, const float* __restrict__ b2) {
    __shared__ float S[64];
    __shared__ int np[2];
    int g = blockIdx.x;
    int t = threadIdx.x;   // 64 threads
    if (t < 2) np[t] = 0;
    float s = 0.f;
    #pragma unroll 8
    for (int n = 0; n < 64; n++) s += g_sum2[(size_t)(g * 64 + n) * 64 + t];
    S[t] = s;
    // count deg>0 among this graph's 64 nodes
    unsigned bal = __ballot_sync(0xffffffffu, g_deg[g * 64 + t] > 0);
    __syncthreads();
    if ((t & 31) == 0) atomicAdd(&np[0], __popc(bal));
    __syncthreads();
    float npos = (float)np[0];
    float acc = 0.f;
    #pragma unroll 8
    for (int k = 0; k < 64; k++) acc = fmaf(S[k], w2[k * 64 + t], acc);
    g_z[g * 192 + 128 + t] = (acc + npos * b2[t]) * (1.f / 64.f);
}

__global__ void z_kernel(const float* __restrict__ state, const float* __restrict__ action) {
    unsigned idx = blockIdx.x * blockDim.x + threadIdx.x;  // NB*128
    if (idx >= NB * 128) return;
    int b = idx >> 7, j = idx & 127;
    g_z[b * 192 + j] = (j < 96) ? state[b * 96 + j] : action[b * 32 + (j - 96)];
}

__global__ void qdot_kernel(const float* __restrict__ w3a, const float* __restrict__ b3a,
                            const float* __restrict__ w3b, const float* __restrict__ b3b,
                            float* __restrict__ out) {
    int warp = (blockIdx.x * blockDim.x + threadIdx.x) >> 5;
    int lane = threadIdx.x & 31;
    if (warp >= 2 * NB) return;
    int head = warp >> 10;
    const float* w3 = head ? w3b : w3a;
    const float* b3 = head ? b3b : b3a;
    const float* t2 = &g_t2[(size_t)warp * 256];
    float s = 0.f;
    #pragma unroll
    for (int k = lane; k < 256; k += 32) s += t2[k] * w3[k];
    #pragma unroll
    for (int o = 16; o > 0; o >>= 1) s += __shfl_down_sync(0xffffffffu, s, o);
    if (lane == 0) out[warp] = s + b3[0];
}

// ---------------- launch ------------------------------------------------------

extern "C" void kernel_launch(void* const* d_in, const int* in_sizes, int n_in,
                              void* d_out, int out_size) {
    const float* state  = (const float*)d_in[0];
    const float* action = (const float*)d_in[1];
    const float* x      = (const float*)d_in[2];
    const int*   eidx   = (const int*)d_in[3];
    const float* g1_w1 = (const float*)d_in[5];
    const float* g1_b1 = (const float*)d_in[6];
    const float* g1_w2 = (const float*)d_in[7];
    const float* g1_b2 = (const float*)d_in[8];
    const float* g2_w1 = (const float*)d_in[9];
    const float* g2_b1 = (const float*)d_in[10];
    const float* g2_w2 = (const float*)d_in[11];
    const float* g2_b2 = (const float*)d_in[12];
    const float* q1_w1 = (const float*)d_in[13];
    const float* q1_b1 = (const float*)d_in[14];
    const float* q1_w2 = (const float*)d_in[15];
    const float* q1_b2 = (const float*)d_in[16];
    const float* q1_w3 = (const float*)d_in[17];
    const float* q1_b3 = (const float*)d_in[18];
    const float* q2_w1 = (const float*)d_in[19];
    const float* q2_b1 = (const float*)d_in[20];
    const float* q2_w2 = (const float*)d_in[21];
    const float* q2_b2 = (const float*)d_in[22];
    const float* q2_w3 = (const float*)d_in[23];
    const float* q2_b3 = (const float*)d_in[24];
    float* out = (float*)d_out;

    const int* srcs = eidx;
    const int* dsts = eidx + NE;

    float *p_AB1, *p_sum1, *p_h1, *p_AB2, *p_z, *p_t1, *p_t2;
    float *p_W1, *p_b1, *p_W2, *p_b2, *p_act, *p_QW1, *p_Qb1;
    int *p_deg;
    cudaGetSymbolAddress((void**)&p_AB1,  g_AB1);
    cudaGetSymbolAddress((void**)&p_sum1, g_sum1);
    cudaGetSymbolAddress((void**)&p_h1,   g_h1);
    cudaGetSymbolAddress((void**)&p_AB2,  g_AB2);
    cudaGetSymbolAddress((void**)&p_z,    g_z);
    cudaGetSymbolAddress((void**)&p_t1,   g_t1);
    cudaGetSymbolAddress((void**)&p_t2,   g_t2);
    cudaGetSymbolAddress((void**)&p_W1,   g_W1);
    cudaGetSymbolAddress((void**)&p_b1,   g_bias1);
    cudaGetSymbolAddress((void**)&p_W2,   g_W2);
    cudaGetSymbolAddress((void**)&p_b2,   g_bias2);
    cudaGetSymbolAddress((void**)&p_act,  g_actterm);
    cudaGetSymbolAddress((void**)&p_QW1,  g_QW1);
    cudaGetSymbolAddress((void**)&p_Qb1,  g_Qb1);
    cudaGetSymbolAddress((void**)&p_deg,  g_deg);

    // CSR build
    zero_deg_kernel<<<NN / 256, 256>>>();
    prep_kernel<<<(148352 + 255) / 256, 256>>>(g1_w1, g1_b1, g2_w1, g2_b1,
                                               q1_w1, q1_b1, q2_w1, q2_b1);
    count_kernel<<<NE / 256, 256>>>(dsts);
    blocksum_kernel<<<256, 256>>>();
    bscan_kernel<<<1, 256>>>();
    fill_kernel<<<256, 256>>>();
    scatter_kernel<<<NE / 256, 256>>>(srcs, dsts);

    // actterm = action @ W1cat[96:128] + b1cat  (fp32, tiny)
    gemm_kernel<<<dim3(4, NB / 128), 256>>>(action, p_W1 + 96 * 256, p_b1, p_act,
                                            NB, 32, 256, 0);
    // AB1 = x @ W1cat[0:96] + actterm[graph]
    gemm_tf32_kernel<<<dim3(2, NN / 128), 256>>>(x, p_W1, nullptr, p_AB1,
                                                 NN, 96, 256, 96, 0, nullptr, p_act,
                                                 nullptr, nullptr, nullptr, 0);
    // edge phase 1
    agg1_kernel<<<NN / 8, 256>>>();
    // h1 = relu(mean1 @ g1_w2 + b2), deg-0 masked
    gemm_tf32_kernel<<<dim3(1, NN / 128), 256>>>(p_sum1, g1_w2, g1_b2, p_h1,
                                                 NN, 128, 128, 128, 1, p_deg, nullptr,
                                                 nullptr, nullptr, nullptr, 0);
    // AB2 = h1 @ W2cat + [b2_1|0]
    gemm_tf32_kernel<<<dim3(1, NN / 128), 256>>>(p_h1, p_W2, p_b2, p_AB2,
                                                 NN, 128, 128, 128, 0, nullptr, nullptr,
                                                 nullptr, nullptr, nullptr, 0);
    // edge phase 2
    agg2_kernel<<<NN / 8, 256>>>();
    // ge directly into z (replaces h2 GEMM + ge)
    reduce_ge_kernel<<<NB, 64>>>(g2_w2, g2_b2);
    z_kernel<<<(NB * 128) / 256, 256>>>(state, action);
    // Q heads: fused layer 1 (both heads, Nc=512)
    gemm_tf32_kernel<<<dim3(4, NB / 128), 256>>>(p_z, p_QW1, p_Qb1, p_t1,
                                                 NB, 192, 512, 192, 1, nullptr, nullptr,
                                                 nullptr, nullptr, nullptr, 0);
    // layer 2: z-batched over heads (A strided into t1)
    gemm_tf32_kernel<<<dim3(2, NB / 128, 2), 256>>>(p_t1, q1_w2, q1_b2, p_t2,
                                                    NB, 256, 256, 512, 1, nullptr, nullptr,
                                                    q2_w2, q2_b2, p_t2 + NB * 256, 256);
    // both qdots
    qdot_kernel<<<(2 * NB * 32) / 256, 256>>>(q1_w3, q1_b3, q2_w3, q2_b3, out);
}

// round 6
// speedup vs baseline: 4.0547x; 1.1810x over previous
#include <cuda_runtime.h>
#include <cstdint>

#define NN 65536
#define NE 524288
#define NB 1024

// ---------------- scratch (device globals) ----------------------------------
__device__ float g_AB1[NN * 256];
__device__ float g_sum1[NN * 128];
__device__ float g_h1[NN * 128];
__device__ float g_AB2[NN * 128];
__device__ float g_sum2[NN * 64];
__device__ float g_z[NB * 192];
__device__ float g_t1[NB * 512];
__device__ float g_t2[2 * NB * 256];
__device__ float g_actterm[NB * 256];
__device__ float g_W1[128 * 256];
__device__ float g_bias1[256];
__device__ float g_W2[128 * 128];
__device__ float g_bias2[128];
__device__ float g_QW1[192 * 512];
__device__ float g_Qb1[512];
__device__ int   g_deg[NN];
__device__ int   g_off[NN];
__device__ int   g_cur[NN];
__device__ int   g_csr[NE];
__device__ int   g_bsum[256];
__device__ int   g_boff[256];

// ---------------- prep (+deg zero) -------------------------------------------

__global__ void prep_kernel(const float* __restrict__ g1w1, const float* __restrict__ g1b1,
                            const float* __restrict__ g2w1, const float* __restrict__ g2b1,
                            const float* __restrict__ q1w1, const float* __restrict__ q1b1,
                            const float* __restrict__ q2w1, const float* __restrict__ q2b1) {
    int idx = blockIdx.x * blockDim.x + threadIdx.x;
    if (idx < 32768) {
        int k = idx >> 8, j = idx & 255;
        g_W1[idx] = (j < 128) ? g1w1[k * 128 + j] : g1w1[(k + 128) * 128 + (j - 128)];
    } else if (idx < 33024) {
        int j = idx - 32768;
        g_bias1[j] = (j < 128) ? g1b1[j] : 0.f;
    } else if (idx < 49408) {
        int i2 = idx - 33024;
        int k = i2 >> 7, j = i2 & 127;
        g_W2[i2] = (j < 64) ? g2w1[k * 64 + j] : g2w1[(k + 128) * 64 + (j - 64)];
    } else if (idx < 49536) {
        int j = idx - 49408;
        g_bias2[j] = (j < 64) ? g2b1[j] : 0.f;
    } else if (idx < 147840) {
        int i2 = idx - 49536;
        int k = i2 / 512, c = i2 & 511;
        g_QW1[i2] = (c < 256) ? q1w1[k * 256 + c] : q2w1[k * 256 + (c - 256)];
    } else if (idx < 148352) {
        int j = idx - 147840;
        g_Qb1[j] = (j < 256) ? q1b1[j] : q2b1[j - 256];
    } else if (idx < 148352 + NN) {
        g_deg[idx - 148352] = 0;
    }
}

// ---------------- CSR build ---------------------------------------------------

__global__ void count_kernel(const int4* __restrict__ dst4) {
    int i = blockIdx.x * blockDim.x + threadIdx.x;   // NE/4
    int4 d = dst4[i];
    atomicAdd(&g_deg[d.x], 1);
    atomicAdd(&g_deg[d.y], 1);
    atomicAdd(&g_deg[d.z], 1);
    atomicAdd(&g_deg[d.w], 1);
}

__global__ void blocksum_kernel() {
    __shared__ int sh[256];
    int t = threadIdx.x;
    sh[t] = g_deg[blockIdx.x * 256 + t];
    __syncthreads();
    for (int off = 128; off > 0; off >>= 1) {
        if (t < off) sh[t] += sh[t + off];
        __syncthreads();
    }
    if (t == 0) g_bsum[blockIdx.x] = sh[0];
}

__global__ void bscan_kernel() {
    __shared__ int sh[256];
    int t = threadIdx.x;
    sh[t] = g_bsum[t];
    __syncthreads();
    for (int off = 1; off < 256; off <<= 1) {
        int v = (t >= off) ? sh[t - off] : 0;
        __syncthreads();
        sh[t] += v;
        __syncthreads();
    }
    g_boff[t] = sh[t] - g_bsum[t];
}

__global__ void fill_kernel() {
    __shared__ int sh[256];
    int t = threadIdx.x;
    int gi = blockIdx.x * 256 + t;
    int d = g_deg[gi];
    sh[t] = d;
    __syncthreads();
    for (int off = 1; off < 256; off <<= 1) {
        int v = (t >= off) ? sh[t - off] : 0;
        __syncthreads();
        sh[t] += v;
        __syncthreads();
    }
    int excl = sh[t] - d + g_boff[blockIdx.x];
    g_off[gi] = excl;
    g_cur[gi] = excl;
}

__global__ void scatter_kernel(const int4* __restrict__ src4, const int4* __restrict__ dst4) {
    int i = blockIdx.x * blockDim.x + threadIdx.x;   // NE/4
    int4 s = src4[i];
    int4 d = dst4[i];
    g_csr[atomicAdd(&g_cur[d.x], 1)] = s.x;
    g_csr[atomicAdd(&g_cur[d.y], 1)] = s.y;
    g_csr[atomicAdd(&g_cur[d.z], 1)] = s.z;
    g_csr[atomicAdd(&g_cur[d.w], 1)] = s.w;
}

// ---------------- tf32 tensor-core GEMM (register-prefetch pipelined) --------
// C = act(A@W + bias + rowadd); 128x128 tile, BK=32, mma.m16n8k8.tf32.
// lda = row stride of A. gridDim.z==2: blockIdx.z==1 uses Wb/biasb/Cb, A+acoloff.

__device__ __forceinline__ float to_tf32(float x) {
    uint32_t u;
    asm("cvt.rna.tf32.f32 %0, %1;" : "=r"(u) : "f"(x));
    return __uint_as_float(u);
}

__global__ void __launch_bounds__(256)
gemm_tf32_kernel(const float* __restrict__ A, const float* __restrict__ W,
                 const float* __restrict__ bias, float* __restrict__ C,
                 int M, int K, int Nc, int lda, int do_relu,
                 const int* __restrict__ degmask,
                 const float* __restrict__ rowadd,
                 const float* Wb, const float* biasb, float* Cb, int acoloff) {
    if (blockIdx.z == 1) {
        A += acoloff;
        W = Wb;
        bias = biasb;
        C = Cb;
    }
    __shared__ float As[128 * 36];
    __shared__ float Bs[32 * 136];
    int bm = blockIdx.y * 128;
    int bn = blockIdx.x * 128;
    int t = threadIdx.x;
    int warp = t >> 5, lane = t & 31;
    int wm = warp >> 2, wn = warp & 3;
    int gid = lane >> 2, tig = lane & 3;

    // per-thread staging coordinates
    int arow[4], akq[4], bkk[4], bn4[4];
    #pragma unroll
    for (int i = 0; i < 4; i++) {
        int idx = t + i * 256;
        arow[i] = idx >> 3;
        akq[i]  = (idx & 7) << 2;
        bkk[i]  = idx >> 5;
        bn4[i]  = (idx & 31) << 2;
    }

    float acc[4][4][4];
    #pragma unroll
    for (int a = 0; a < 4; a++)
        #pragma unroll
        for (int b = 0; b < 4; b++)
            #pragma unroll
            for (int c = 0; c < 4; c++) acc[a][b][c] = 0.f;

    float4 ra[4], rb[4];
    #pragma unroll
    for (int i = 0; i < 4; i++) {
        ra[i] = *(const float4*)&A[(size_t)(bm + arow[i]) * lda + akq[i]];
        rb[i] = *(const float4*)&W[(size_t)bkk[i] * Nc + bn + bn4[i]];
    }

    for (int k0 = 0; k0 < K; k0 += 32) {
        // commit staged tile to smem (cvt at store)
        #pragma unroll
        for (int i = 0; i < 4; i++) {
            float4 v = ra[i];
            v.x = to_tf32(v.x); v.y = to_tf32(v.y);
            v.z = to_tf32(v.z); v.w = to_tf32(v.w);
            *(float4*)&As[arow[i] * 36 + akq[i]] = v;
            float4 w = rb[i];
            w.x = to_tf32(w.x); w.y = to_tf32(w.y);
            w.z = to_tf32(w.z); w.w = to_tf32(w.w);
            *(float4*)&Bs[bkk[i] * 136 + bn4[i]] = w;
        }
        __syncthreads();
        // prefetch next tile while MMAs run
        if (k0 + 32 < K) {
            #pragma unroll
            for (int i = 0; i < 4; i++) {
                ra[i] = *(const float4*)&A[(size_t)(bm + arow[i]) * lda + k0 + 32 + akq[i]];
                rb[i] = *(const float4*)&W[(size_t)(k0 + 32 + bkk[i]) * Nc + bn + bn4[i]];
            }
        }
        #pragma unroll
        for (int ks = 0; ks < 32; ks += 8) {
            uint32_t af[4][4], bf[4][2];
            #pragma unroll
            for (int mt = 0; mt < 4; mt++) {
                const float* ap = &As[(wm * 64 + mt * 16 + gid) * 36 + ks + tig];
                af[mt][0] = __float_as_uint(ap[0]);
                af[mt][1] = __float_as_uint(ap[8 * 36]);
                af[mt][2] = __float_as_uint(ap[4]);
                af[mt][3] = __float_as_uint(ap[8 * 36 + 4]);
            }
            #pragma unroll
            for (int nt = 0; nt < 4; nt++) {
                const float* bp = &Bs[(ks + tig) * 136 + wn * 32 + nt * 8 + gid];
                bf[nt][0] = __float_as_uint(bp[0]);
                bf[nt][1] = __float_as_uint(bp[4 * 136]);
            }
            #pragma unroll
            for (int mt = 0; mt < 4; mt++)
                #pragma unroll
                for (int nt = 0; nt < 4; nt++) {
                    asm volatile(
                        "mma.sync.aligned.m16n8k8.row.col.f32.tf32.tf32.f32 "
                        "{%0,%1,%2,%3}, {%4,%5,%6,%7}, {%8,%9}, {%0,%1,%2,%3};"
                        : "+f"(acc[mt][nt][0]), "+f"(acc[mt][nt][1]),
                          "+f"(acc[mt][nt][2]), "+f"(acc[mt][nt][3])
                        : "r"(af[mt][0]), "r"(af[mt][1]), "r"(af[mt][2]), "r"(af[mt][3]),
                          "r"(bf[nt][0]), "r"(bf[nt][1]));
                }
        }
        __syncthreads();
    }

    #pragma unroll
    for (int mt = 0; mt < 4; mt++) {
        int r0 = bm + wm * 64 + mt * 16 + gid;
        int r1 = r0 + 8;
        float zm0 = (degmask && degmask[r0] == 0) ? 0.f : 1.f;
        float zm1 = (degmask && degmask[r1] == 0) ? 0.f : 1.f;
        #pragma unroll
        for (int nt = 0; nt < 4; nt++) {
            int c0 = bn + wn * 32 + nt * 8 + 2 * tig;
            float b0 = bias ? bias[c0] : 0.f;
            float b1 = bias ? bias[c0 + 1] : 0.f;
            float ra00 = 0.f, ra01 = 0.f, ra10 = 0.f, ra11 = 0.f;
            if (rowadd) {
                ra00 = rowadd[(size_t)(r0 >> 6) * Nc + c0];
                ra01 = rowadd[(size_t)(r0 >> 6) * Nc + c0 + 1];
                ra10 = rowadd[(size_t)(r1 >> 6) * Nc + c0];
                ra11 = rowadd[(size_t)(r1 >> 6) * Nc + c0 + 1];
            }
            float v00 = acc[mt][nt][0] + b0 + ra00;
            float v01 = acc[mt][nt][1] + b1 + ra01;
            float v10 = acc[mt][nt][2] + b0 + ra10;
            float v11 = acc[mt][nt][3] + b1 + ra11;
            if (do_relu) {
                v00 = fmaxf(v00, 0.f); v01 = fmaxf(v01, 0.f);
                v10 = fmaxf(v10, 0.f); v11 = fmaxf(v11, 0.f);
            }
            float2 o0 = {v00 * zm0, v01 * zm0};
            float2 o1 = {v10 * zm1, v11 * zm1};
            *(float2*)&C[(size_t)r0 * Nc + c0] = o0;
            *(float2*)&C[(size_t)r1 * Nc + c0] = o1;
        }
    }
}

// ---------------- fp32 GEMM 128x64 tile (actterm) ----------------------------
__global__ void gemm_kernel(const float* __restrict__ A, const float* __restrict__ W,
                            const float* __restrict__ bias, float* __restrict__ C,
                            int M, int K, int Nc, int do_relu) {
    __shared__ float As[16][132];
    __shared__ float Bs[16][68];
    int bm = blockIdx.y * 128;
    int bn = blockIdx.x * 64;
    int t = threadIdx.x;
    int ty = t >> 4, tx = t & 15;
    float acc[8][4] = {};
    for (int k0 = 0; k0 < K; k0 += 16) {
        #pragma unroll
        for (int i = 0; i < 2; i++) {
            int idx = t + i * 256;
            int row = idx >> 2;
            int kq = (idx & 3) << 2;
            float4 v = *(const float4*)&A[(size_t)(bm + row) * K + k0 + kq];
            As[kq + 0][row] = v.x;
            As[kq + 1][row] = v.y;
            As[kq + 2][row] = v.z;
            As[kq + 3][row] = v.w;
        }
        {
            int kk = t >> 4;
            int col = (t & 15) << 2;
            *(float4*)&Bs[kk][col] = *(const float4*)&W[(size_t)(k0 + kk) * Nc + bn + col];
        }
        __syncthreads();
        #pragma unroll
        for (int kk = 0; kk < 16; kk++) {
            float a[8], b[4];
            *(float4*)&a[0] = *(const float4*)&As[kk][ty * 8];
            *(float4*)&a[4] = *(const float4*)&As[kk][ty * 8 + 4];
            *(float4*)&b[0] = *(const float4*)&Bs[kk][tx * 4];
            #pragma unroll
            for (int i = 0; i < 8; i++)
                #pragma unroll
                for (int j = 0; j < 4; j++) acc[i][j] = fmaf(a[i], b[j], acc[i][j]);
        }
        __syncthreads();
    }
    #pragma unroll
    for (int i = 0; i < 8; i++) {
        int r = bm + ty * 8 + i;
        int c0 = bn + tx * 4;
        float4 v;
        float* vp = &v.x;
        #pragma unroll
        for (int j = 0; j < 4; j++) {
            float xv = acc[i][j] + bias[c0 + j];
            if (do_relu) xv = fmaxf(xv, 0.f);
            vp[j] = xv;
        }
        *(float4*)&C[(size_t)r * Nc + c0] = v;
    }
}

// ---------------- edge aggregation (CSR, one warp per dst node) -------------

__device__ __forceinline__ void acc_relu4(float4& acc, float4 a, float4 b) {
    acc.x += fmaxf(a.x + b.x, 0.f);
    acc.y += fmaxf(a.y + b.y, 0.f);
    acc.z += fmaxf(a.z + b.z, 0.f);
    acc.w += fmaxf(a.w + b.w, 0.f);
}

__global__ void agg1_kernel() {
    int w = (blockIdx.x * blockDim.x + threadIdx.x) >> 5;
    int lane = threadIdx.x & 31;
    int deg = g_deg[w], start = g_off[w];
    float4 a = *(const float4*)&g_AB1[(size_t)w * 256 + lane * 4];
    float4 acc = {0.f, 0.f, 0.f, 0.f};
    int i = 0;
    for (; i + 8 <= deg; i += 8) {
        int s[8];
        #pragma unroll
        for (int u = 0; u < 8; u++) s[u] = g_csr[start + i + u];
        float4 b[8];
        #pragma unroll
        for (int u = 0; u < 8; u++)
            b[u] = *(const float4*)&g_AB1[(size_t)s[u] * 256 + 128 + lane * 4];
        #pragma unroll
        for (int u = 0; u < 8; u++) acc_relu4(acc, a, b[u]);
    }
    for (; i + 2 <= deg; i += 2) {
        int s0 = g_csr[start + i], s1 = g_csr[start + i + 1];
        float4 b0 = *(const float4*)&g_AB1[(size_t)s0 * 256 + 128 + lane * 4];
        float4 b1 = *(const float4*)&g_AB1[(size_t)s1 * 256 + 128 + lane * 4];
        acc_relu4(acc, a, b0);
        acc_relu4(acc, a, b1);
    }
    for (; i < deg; i++) {
        int s = g_csr[start + i];
        float4 b = *(const float4*)&g_AB1[(size_t)s * 256 + 128 + lane * 4];
        acc_relu4(acc, a, b);
    }
    float inv = 1.f / fmaxf((float)deg, 1.f);
    float4 o = {acc.x * inv, acc.y * inv, acc.z * inv, acc.w * inv};
    *(float4*)&g_sum1[(size_t)w * 128 + lane * 4] = o;
}

__device__ __forceinline__ void acc_relu2(float2& acc, float2 a, float2 b) {
    acc.x += fmaxf(a.x + b.x, 0.f);
    acc.y += fmaxf(a.y + b.y, 0.f);
}

__global__ void agg2_kernel() {
    int w = (blockIdx.x * blockDim.x + threadIdx.x) >> 5;
    int lane = threadIdx.x & 31;
    int deg = g_deg[w], start = g_off[w];
    float2 a = *(const float2*)&g_AB2[(size_t)w * 128 + lane * 2];
    float2 acc = {0.f, 0.f};
    int i = 0;
    for (; i + 8 <= deg; i += 8) {
        int s[8];
        #pragma unroll
        for (int u = 0; u < 8; u++) s[u] = g_csr[start + i + u];
        float2 b[8];
        #pragma unroll
        for (int u = 0; u < 8; u++)
            b[u] = *(const float2*)&g_AB2[(size_t)s[u] * 128 + 64 + lane * 2];
        #pragma unroll
        for (int u = 0; u < 8; u++) acc_relu2(acc, a, b[u]);
    }
    for (; i + 2 <= deg; i += 2) {
        int s0 = g_csr[start + i], s1 = g_csr[start + i + 1];
        float2 b0 = *(const float2*)&g_AB2[(size_t)s0 * 128 + 64 + lane * 2];
        float2 b1 = *(const float2*)&g_AB2[(size_t)s1 * 128 + 64 + lane * 2];
        acc_relu2(acc, a, b0);
        acc_relu2(acc, a, b1);
    }
    for (; i < deg; i++) {
        int s = g_csr[start + i];
        float2 b = *(const float2*)&g_AB2[(size_t)s * 128 + 64 + lane * 2];
        acc_relu2(acc, a, b);
    }
    float inv = 1.f / fmaxf((float)deg, 1.f);
    float2 o = {acc.x * inv, acc.y * inv};
    *(float2*)&g_sum2[(size_t)w * 64 + lane * 2] = o;
}

// ---------------- fused tail: z = [state|action|ge] --------------------------
// ge_g = ((sum over nodes of sum2) @ g2_w2 + npos_g*b2)/64, computed by threads
// 128..191 while threads 0..127 copy state/action.
__global__ void tail_kernel(const float* __restrict__ state, const float* __restrict__ action,
                            const float* __restrict__ w2, const float* __restrict__ b2) {
    __shared__ float S[64];
    __shared__ int np;
    int g = blockIdx.x;
    int t = threadIdx.x;    // 192
    if (t == 0) np = 0;
    __syncthreads();
    if (t < 128) {
        g_z[g * 192 + t] = (t < 96) ? state[g * 96 + t] : action[g * 32 + (t - 96)];
    } else {
        int c = t - 128;
        float s = 0.f;
        #pragma unroll 8
        for (int n = 0; n < 64; n++) s += g_sum2[(size_t)(g * 64 + n) * 64 + c];
        S[c] = s;
        unsigned bal = __ballot_sync(0xffffffffu, g_deg[g * 64 + c] > 0);
        if ((t & 31) == 0) atomicAdd(&np, __popc(bal));
    }
    __syncthreads();
    if (t >= 128) {
        int c = t - 128;
        float npos = (float)np;
        float acc = 0.f;
        #pragma unroll 8
        for (int k = 0; k < 64; k++) acc = fmaf(S[k], w2[k * 64 + c], acc);
        g_z[g * 192 + 128 + c] = (acc + npos * b2[c]) * (1.f / 64.f);
    }
}

__global__ void qdot_kernel(const float* __restrict__ w3a, const float* __restrict__ b3a,
                            const float* __restrict__ w3b, const float* __restrict__ b3b,
                            float* __restrict__ out) {
    int warp = (blockIdx.x * blockDim.x + threadIdx.x) >> 5;
    int lane = threadIdx.x & 31;
    if (warp >= 2 * NB) return;
    int head = warp >> 10;
    const float* w3 = head ? w3b : w3a;
    const float* b3 = head ? b3b : b3a;
    const float* t2 = &g_t2[(size_t)warp * 256];
    float s = 0.f;
    #pragma unroll
    for (int k = lane; k < 256; k += 32) s += t2[k] * w3[k];
    #pragma unroll
    for (int o = 16; o > 0; o >>= 1) s += __shfl_down_sync(0xffffffffu, s, o);
    if (lane == 0) out[warp] = s + b3[0];
}

// ---------------- launch ------------------------------------------------------

extern "C" void kernel_launch(void* const* d_in, const int* in_sizes, int n_in,
                              void* d_out, int out_size) {
    const float* state  = (const float*)d_in[0];
    const float* action = (const float*)d_in[1];
    const float* x      = (const float*)d_in[2];
    const int*   eidx   = (const int*)d_in[3];
    const float* g1_w1 = (const float*)d_in[5];
    const float* g1_b1 = (const float*)d_in[6];
    const float* g1_w2 = (const float*)d_in[7];
    const float* g1_b2 = (const float*)d_in[8];
    const float* g2_w1 = (const float*)d_in[9];
    const float* g2_b1 = (const float*)d_in[10];
    const float* g2_w2 = (const float*)d_in[11];
    const float* g2_b2 = (const float*)d_in[12];
    const float* q1_w1 = (const float*)d_in[13];
    const float* q1_b1 = (const float*)d_in[14];
    const float* q1_w2 = (const float*)d_in[15];
    const float* q1_b2 = (const float*)d_in[16];
    const float* q1_w3 = (const float*)d_in[17];
    const float* q1_b3 = (const float*)d_in[18];
    const float* q2_w1 = (const float*)d_in[19];
    const float* q2_b1 = (const float*)d_in[20];
    const float* q2_w2 = (const float*)d_in[21];
    const float* q2_b2 = (const float*)d_in[22];
    const float* q2_w3 = (const float*)d_in[23];
    const float* q2_b3 = (const float*)d_in[24];
    float* out = (float*)d_out;

    const int4* srcs4 = (const int4*)eidx;
    const int4* dsts4 = (const int4*)(eidx + NE);

    float *p_AB1, *p_sum1, *p_h1, *p_AB2, *p_z, *p_t1, *p_t2;
    float *p_W1, *p_b1, *p_W2, *p_b2, *p_act, *p_QW1, *p_Qb1;
    int *p_deg;
    cudaGetSymbolAddress((void**)&p_AB1,  g_AB1);
    cudaGetSymbolAddress((void**)&p_sum1, g_sum1);
    cudaGetSymbolAddress((void**)&p_h1,   g_h1);
    cudaGetSymbolAddress((void**)&p_AB2,  g_AB2);
    cudaGetSymbolAddress((void**)&p_z,    g_z);
    cudaGetSymbolAddress((void**)&p_t1,   g_t1);
    cudaGetSymbolAddress((void**)&p_t2,   g_t2);
    cudaGetSymbolAddress((void**)&p_W1,   g_W1);
    cudaGetSymbolAddress((void**)&p_b1,   g_bias1);
    cudaGetSymbolAddress((void**)&p_W2,   g_W2);
    cudaGetSymbolAddress((void**)&p_b2,   g_bias2);
    cudaGetSymbolAddress((void**)&p_act,  g_actterm);
    cudaGetSymbolAddress((void**)&p_QW1,  g_QW1);
    cudaGetSymbolAddress((void**)&p_Qb1,  g_Qb1);
    cudaGetSymbolAddress((void**)&p_deg,  g_deg);

    // prep (+deg zero) and CSR build
    prep_kernel<<<(148352 + NN + 255) / 256, 256>>>(g1_w1, g1_b1, g2_w1, g2_b1,
                                                    q1_w1, q1_b1, q2_w1, q2_b1);
    count_kernel<<<NE / 4 / 256, 256>>>(dsts4);
    blocksum_kernel<<<256, 256>>>();
    bscan_kernel<<<1, 256>>>();
    fill_kernel<<<256, 256>>>();
    scatter_kernel<<<NE / 4 / 256, 256>>>(srcs4, dsts4);

    // actterm = action @ W1cat[96:128] + b1cat
    gemm_kernel<<<dim3(4, NB / 128), 256>>>(action, p_W1 + 96 * 256, p_b1, p_act,
                                            NB, 32, 256, 0);
    // AB1 = x @ W1cat[0:96] + actterm[graph]
    gemm_tf32_kernel<<<dim3(2, NN / 128), 256>>>(x, p_W1, nullptr, p_AB1,
                                                 NN, 96, 256, 96, 0, nullptr, p_act,
                                                 nullptr, nullptr, nullptr, 0);
    agg1_kernel<<<NN / 8, 256>>>();
    gemm_tf32_kernel<<<dim3(1, NN / 128), 256>>>(p_sum1, g1_w2, g1_b2, p_h1,
                                                 NN, 128, 128, 128, 1, p_deg, nullptr,
                                                 nullptr, nullptr, nullptr, 0);
    gemm_tf32_kernel<<<dim3(1, NN / 128), 256>>>(p_h1, p_W2, p_b2, p_AB2,
                                                 NN, 128, 128, 128, 0, nullptr, nullptr,
                                                 nullptr, nullptr, nullptr, 0);
    agg2_kernel<<<NN / 8, 256>>>();
    tail_kernel<<<NB, 192>>>(state, action, g2_w2, g2_b2);
    // Q heads
    gemm_tf32_kernel<<<dim3(4, NB / 128), 256>>>(p_z, p_QW1, p_Qb1, p_t1,
                                                 NB, 192, 512, 192, 1, nullptr, nullptr,
                                                 nullptr, nullptr, nullptr, 0);
    gemm_tf32_kernel<<<dim3(2, NB / 128, 2), 256>>>(p_t1, q1_w2, q1_b2, p_t2,
                                                    NB, 256, 256, 512, 1, nullptr, nullptr,
                                                    q2_w2, q2_b2, p_t2 + NB * 256, 256);
    qdot_kernel<<<(2 * NB * 32) / 256, 256>>>(q1_w3, q1_b3, q2_w3, q2_b3, out);
}

// round 7
// speedup vs baseline: 4.0779x; 1.0057x over previous
#include <cuda_runtime.h>
#include <cstdint>

#define NN 65536
#define NE 524288
#define NB 1024

// ---------------- scratch (device globals) ----------------------------------
__device__ float g_AB1[NN * 256];
__device__ float g_sum1[NN * 128];
__device__ float g_AB2[NN * 128];
__device__ float g_gsum[NB * 64];
__device__ float g_z[NB * 192];
__device__ float g_t1[NB * 512];
__device__ float g_t2[2 * NB * 256];
__device__ float g_actterm[NB * 256];
__device__ float g_W1[128 * 256];
__device__ float g_bias1[256];
__device__ float g_W2[128 * 128];
__device__ float g_bias2[128];
__device__ float g_QW1[192 * 512];
__device__ float g_Qb1[512];
__device__ int   g_deg[NN];
__device__ int   g_off[NN];
__device__ int   g_cur[NN];
__device__ int   g_csr[NE];
__device__ int   g_bsum[256];
__device__ int   g_boff[256];

// ---------------- prep (+deg zero, +gsum zero) --------------------------------

__global__ void prep_kernel(const float* __restrict__ g1w1, const float* __restrict__ g1b1,
                            const float* __restrict__ g2w1, const float* __restrict__ g2b1,
                            const float* __restrict__ q1w1, const float* __restrict__ q1b1,
                            const float* __restrict__ q2w1, const float* __restrict__ q2b1) {
    int idx = blockIdx.x * blockDim.x + threadIdx.x;
    if (idx < 32768) {
        int k = idx >> 8, j = idx & 255;
        g_W1[idx] = (j < 128) ? g1w1[k * 128 + j] : g1w1[(k + 128) * 128 + (j - 128)];
    } else if (idx < 33024) {
        int j = idx - 32768;
        g_bias1[j] = (j < 128) ? g1b1[j] : 0.f;
    } else if (idx < 49408) {
        int i2 = idx - 33024;
        int k = i2 >> 7, j = i2 & 127;
        g_W2[i2] = (j < 64) ? g2w1[k * 64 + j] : g2w1[(k + 128) * 64 + (j - 64)];
    } else if (idx < 49536) {
        int j = idx - 49408;
        g_bias2[j] = (j < 64) ? g2b1[j] : 0.f;
    } else if (idx < 147840) {
        int i2 = idx - 49536;
        int k = i2 / 512, c = i2 & 511;
        g_QW1[i2] = (c < 256) ? q1w1[k * 256 + c] : q2w1[k * 256 + (c - 256)];
    } else if (idx < 148352) {
        int j = idx - 147840;
        g_Qb1[j] = (j < 256) ? q1b1[j] : q2b1[j - 256];
    } else if (idx < 148352 + NN) {
        g_deg[idx - 148352] = 0;
    } else if (idx < 148352 + NN + NB * 64) {
        g_gsum[idx - 148352 - NN] = 0.f;
    }
}

// ---------------- CSR build ---------------------------------------------------

__global__ void count_kernel(const int4* __restrict__ dst4) {
    int i = blockIdx.x * blockDim.x + threadIdx.x;
    int4 d = dst4[i];
    atomicAdd(&g_deg[d.x], 1);
    atomicAdd(&g_deg[d.y], 1);
    atomicAdd(&g_deg[d.z], 1);
    atomicAdd(&g_deg[d.w], 1);
}

__global__ void blocksum_kernel() {
    __shared__ int sh[256];
    int t = threadIdx.x;
    sh[t] = g_deg[blockIdx.x * 256 + t];
    __syncthreads();
    for (int off = 128; off > 0; off >>= 1) {
        if (t < off) sh[t] += sh[t + off];
        __syncthreads();
    }
    if (t == 0) g_bsum[blockIdx.x] = sh[0];
}

__global__ void bscan_kernel() {
    __shared__ int sh[256];
    int t = threadIdx.x;
    sh[t] = g_bsum[t];
    __syncthreads();
    for (int off = 1; off < 256; off <<= 1) {
        int v = (t >= off) ? sh[t - off] : 0;
        __syncthreads();
        sh[t] += v;
        __syncthreads();
    }
    g_boff[t] = sh[t] - g_bsum[t];
}

__global__ void fill_kernel() {
    __shared__ int sh[256];
    int t = threadIdx.x;
    int gi = blockIdx.x * 256 + t;
    int d = g_deg[gi];
    sh[t] = d;
    __syncthreads();
    for (int off = 1; off < 256; off <<= 1) {
        int v = (t >= off) ? sh[t - off] : 0;
        __syncthreads();
        sh[t] += v;
        __syncthreads();
    }
    int excl = sh[t] - d + g_boff[blockIdx.x];
    g_off[gi] = excl;
    g_cur[gi] = excl;
}

__global__ void scatter_kernel(const int4* __restrict__ src4, const int4* __restrict__ dst4) {
    int i = blockIdx.x * blockDim.x + threadIdx.x;
    int4 s = src4[i];
    int4 d = dst4[i];
    g_csr[atomicAdd(&g_cur[d.x], 1)] = s.x;
    g_csr[atomicAdd(&g_cur[d.y], 1)] = s.y;
    g_csr[atomicAdd(&g_cur[d.z], 1)] = s.z;
    g_csr[atomicAdd(&g_cur[d.w], 1)] = s.w;
}

// ---------------- tf32 helpers -------------------------------------------------

__device__ __forceinline__ float to_tf32(float x) {
    uint32_t u;
    asm("cvt.rna.tf32.f32 %0, %1;" : "=r"(u) : "f"(x));
    return __uint_as_float(u);
}

#define MMA_TF32(acc, af, bf)                                              \
    asm volatile(                                                          \
        "mma.sync.aligned.m16n8k8.row.col.f32.tf32.tf32.f32 "              \
        "{%0,%1,%2,%3}, {%4,%5,%6,%7}, {%8,%9}, {%0,%1,%2,%3};"            \
        : "+f"(acc[0]), "+f"(acc[1]), "+f"(acc[2]), "+f"(acc[3])           \
        : "r"(af[0]), "r"(af[1]), "r"(af[2]), "r"(af[3]),                  \
          "r"(bf[0]), "r"(bf[1]))

// ---------------- tf32 GEMM (register-prefetch pipelined) --------------------
__global__ void __launch_bounds__(256)
gemm_tf32_kernel(const float* __restrict__ A, const float* __restrict__ W,
                 const float* __restrict__ bias, float* __restrict__ C,
                 int M, int K, int Nc, int lda, int do_relu,
                 const float* __restrict__ rowadd,
                 const float* Wb, const float* biasb, float* Cb, int acoloff) {
    if (blockIdx.z == 1) {
        A += acoloff;
        W = Wb;
        bias = biasb;
        C = Cb;
    }
    __shared__ float As[128 * 36];
    __shared__ float Bs[32 * 136];
    int bm = blockIdx.y * 128;
    int bn = blockIdx.x * 128;
    int t = threadIdx.x;
    int warp = t >> 5, lane = t & 31;
    int wm = warp >> 2, wn = warp & 3;
    int gid = lane >> 2, tig = lane & 3;

    int arow[4], akq[4], bkk[4], bn4[4];
    #pragma unroll
    for (int i = 0; i < 4; i++) {
        int idx = t + i * 256;
        arow[i] = idx >> 3;
        akq[i]  = (idx & 7) << 2;
        bkk[i]  = idx >> 5;
        bn4[i]  = (idx & 31) << 2;
    }

    float acc[4][4][4];
    #pragma unroll
    for (int a = 0; a < 4; a++)
        #pragma unroll
        for (int b = 0; b < 4; b++)
            #pragma unroll
            for (int c = 0; c < 4; c++) acc[a][b][c] = 0.f;

    float4 ra[4], rb[4];
    #pragma unroll
    for (int i = 0; i < 4; i++) {
        ra[i] = *(const float4*)&A[(size_t)(bm + arow[i]) * lda + akq[i]];
        rb[i] = *(const float4*)&W[(size_t)bkk[i] * Nc + bn + bn4[i]];
    }

    for (int k0 = 0; k0 < K; k0 += 32) {
        #pragma unroll
        for (int i = 0; i < 4; i++) {
            float4 v = ra[i];
            v.x = to_tf32(v.x); v.y = to_tf32(v.y);
            v.z = to_tf32(v.z); v.w = to_tf32(v.w);
            *(float4*)&As[arow[i] * 36 + akq[i]] = v;
            float4 w = rb[i];
            w.x = to_tf32(w.x); w.y = to_tf32(w.y);
            w.z = to_tf32(w.z); w.w = to_tf32(w.w);
            *(float4*)&Bs[bkk[i] * 136 + bn4[i]] = w;
        }
        __syncthreads();
        if (k0 + 32 < K) {
            #pragma unroll
            for (int i = 0; i < 4; i++) {
                ra[i] = *(const float4*)&A[(size_t)(bm + arow[i]) * lda + k0 + 32 + akq[i]];
                rb[i] = *(const float4*)&W[(size_t)(k0 + 32 + bkk[i]) * Nc + bn + bn4[i]];
            }
        }
        #pragma unroll
        for (int ks = 0; ks < 32; ks += 8) {
            uint32_t af[4][4], bf[4][2];
            #pragma unroll
            for (int mt = 0; mt < 4; mt++) {
                const float* ap = &As[(wm * 64 + mt * 16 + gid) * 36 + ks + tig];
                af[mt][0] = __float_as_uint(ap[0]);
                af[mt][1] = __float_as_uint(ap[8 * 36]);
                af[mt][2] = __float_as_uint(ap[4]);
                af[mt][3] = __float_as_uint(ap[8 * 36 + 4]);
            }
            #pragma unroll
            for (int nt = 0; nt < 4; nt++) {
                const float* bp = &Bs[(ks + tig) * 136 + wn * 32 + nt * 8 + gid];
                bf[nt][0] = __float_as_uint(bp[0]);
                bf[nt][1] = __float_as_uint(bp[4 * 136]);
            }
            #pragma unroll
            for (int mt = 0; mt < 4; mt++)
                #pragma unroll
                for (int nt = 0; nt < 4; nt++) MMA_TF32(acc[mt][nt], af[mt], bf[nt]);
        }
        __syncthreads();
    }

    #pragma unroll
    for (int mt = 0; mt < 4; mt++) {
        int r0 = bm + wm * 64 + mt * 16 + gid;
        int r1 = r0 + 8;
        #pragma unroll
        for (int nt = 0; nt < 4; nt++) {
            int c0 = bn + wn * 32 + nt * 8 + 2 * tig;
            float b0 = bias ? bias[c0] : 0.f;
            float b1 = bias ? bias[c0 + 1] : 0.f;
            float ra00 = 0.f, ra01 = 0.f, ra10 = 0.f, ra11 = 0.f;
            if (rowadd) {
                ra00 = rowadd[(size_t)(r0 >> 6) * Nc + c0];
                ra01 = rowadd[(size_t)(r0 >> 6) * Nc + c0 + 1];
                ra10 = rowadd[(size_t)(r1 >> 6) * Nc + c0];
                ra11 = rowadd[(size_t)(r1 >> 6) * Nc + c0 + 1];
            }
            float v00 = acc[mt][nt][0] + b0 + ra00;
            float v01 = acc[mt][nt][1] + b1 + ra01;
            float v10 = acc[mt][nt][2] + b0 + ra10;
            float v11 = acc[mt][nt][3] + b1 + ra11;
            if (do_relu) {
                v00 = fmaxf(v00, 0.f); v01 = fmaxf(v01, 0.f);
                v10 = fmaxf(v10, 0.f); v11 = fmaxf(v11, 0.f);
            }
            float2 o0 = {v00, v01};
            float2 o1 = {v10, v11};
            *(float2*)&C[(size_t)r0 * Nc + c0] = o0;
            *(float2*)&C[(size_t)r1 * Nc + c0] = o1;
        }
    }
}

// ---------------- fused GNN stage 2: AB2 = (relu(sum1@W1b+b)masked) @ W2cat + b2cat
// One block per 128-row stripe; h1 tile lives only in smem (tf32, identical
// rounding to the unfused path). Dynamic smem: Hs[128*132] (aliases As) + Bs.
__global__ void __launch_bounds__(256)
gnn2_kernel(const float* __restrict__ sum1, const float* __restrict__ W1b,
            const float* __restrict__ b1b, const float* __restrict__ W2c,
            const float* __restrict__ b2c, float* __restrict__ AB2,
            const int* __restrict__ deg) {
    extern __shared__ float sm[];
    float* Hs = sm;               // 128*132 floats (phase-2 A operand)
    float* As = sm;               // alias: phase-1 staging, 128*36
    float* Bs = sm + 128 * 132;   // 32*136
    int bm = blockIdx.y * 128;
    int t = threadIdx.x;
    int warp = t >> 5, lane = t & 31;
    int wm = warp >> 2, wn = warp & 3;
    int gid = lane >> 2, tig = lane & 3;

    int arow[4], akq[4], bkk[4], bn4[4];
    #pragma unroll
    for (int i = 0; i < 4; i++) {
        int idx = t + i * 256;
        arow[i] = idx >> 3;
        akq[i]  = (idx & 7) << 2;
        bkk[i]  = idx >> 5;
        bn4[i]  = (idx & 31) << 2;
    }

    float acc[4][4][4];
    #pragma unroll
    for (int a = 0; a < 4; a++)
        #pragma unroll
        for (int b = 0; b < 4; b++)
            #pragma unroll
            for (int c = 0; c < 4; c++) acc[a][b][c] = 0.f;

    // ---- phase 1: acc = sum1 @ W1b (K=128) ----
    float4 ra[4], rb[4];
    #pragma unroll
    for (int i = 0; i < 4; i++) {
        ra[i] = *(const float4*)&sum1[(size_t)(bm + arow[i]) * 128 + akq[i]];
        rb[i] = *(const float4*)&W1b[(size_t)bkk[i] * 128 + bn4[i]];
    }
    for (int k0 = 0; k0 < 128; k0 += 32) {
        #pragma unroll
        for (int i = 0; i < 4; i++) {
            float4 v = ra[i];
            v.x = to_tf32(v.x); v.y = to_tf32(v.y);
            v.z = to_tf32(v.z); v.w = to_tf32(v.w);
            *(float4*)&As[arow[i] * 36 + akq[i]] = v;
            float4 w = rb[i];
            w.x = to_tf32(w.x); w.y = to_tf32(w.y);
            w.z = to_tf32(w.z); w.w = to_tf32(w.w);
            *(float4*)&Bs[bkk[i] * 136 + bn4[i]] = w;
        }
        __syncthreads();
        if (k0 + 32 < 128) {
            #pragma unroll
            for (int i = 0; i < 4; i++) {
                ra[i] = *(const float4*)&sum1[(size_t)(bm + arow[i]) * 128 + k0 + 32 + akq[i]];
                rb[i] = *(const float4*)&W1b[(size_t)(k0 + 32 + bkk[i]) * 128 + bn4[i]];
            }
        }
        #pragma unroll
        for (int ks = 0; ks < 32; ks += 8) {
            uint32_t af[4][4], bf[4][2];
            #pragma unroll
            for (int mt = 0; mt < 4; mt++) {
                const float* ap = &As[(wm * 64 + mt * 16 + gid) * 36 + ks + tig];
                af[mt][0] = __float_as_uint(ap[0]);
                af[mt][1] = __float_as_uint(ap[8 * 36]);
                af[mt][2] = __float_as_uint(ap[4]);
                af[mt][3] = __float_as_uint(ap[8 * 36 + 4]);
            }
            #pragma unroll
            for (int nt = 0; nt < 4; nt++) {
                const float* bp = &Bs[(ks + tig) * 136 + wn * 32 + nt * 8 + gid];
                bf[nt][0] = __float_as_uint(bp[0]);
                bf[nt][1] = __float_as_uint(bp[4 * 136]);
            }
            #pragma unroll
            for (int mt = 0; mt < 4; mt++)
                #pragma unroll
                for (int nt = 0; nt < 4; nt++) MMA_TF32(acc[mt][nt], af[mt], bf[nt]);
        }
        __syncthreads();
    }

    // ---- phase-1 epilogue: h1 = relu(acc + b1b)*mask -> Hs (tf32) ----
    #pragma unroll
    for (int mt = 0; mt < 4; mt++) {
        int rl0 = wm * 64 + mt * 16 + gid;
        int rl1 = rl0 + 8;
        float zm0 = (deg[bm + rl0] == 0) ? 0.f : 1.f;
        float zm1 = (deg[bm + rl1] == 0) ? 0.f : 1.f;
        #pragma unroll
        for (int nt = 0; nt < 4; nt++) {
            int c0 = wn * 32 + nt * 8 + 2 * tig;
            float b0 = b1b[c0], b1 = b1b[c0 + 1];
            float2 o0 = {to_tf32(fmaxf(acc[mt][nt][0] + b0, 0.f) * zm0),
                         to_tf32(fmaxf(acc[mt][nt][1] + b1, 0.f) * zm0)};
            float2 o1 = {to_tf32(fmaxf(acc[mt][nt][2] + b0, 0.f) * zm1),
                         to_tf32(fmaxf(acc[mt][nt][3] + b1, 0.f) * zm1)};
            *(float2*)&Hs[rl0 * 132 + c0] = o0;
            *(float2*)&Hs[rl1 * 132 + c0] = o1;
            acc[mt][nt][0] = 0.f; acc[mt][nt][1] = 0.f;
            acc[mt][nt][2] = 0.f; acc[mt][nt][3] = 0.f;
        }
    }
    __syncthreads();

    // ---- phase 2: AB2 = Hs @ W2cat (K=128, Nc=128) ----
    #pragma unroll
    for (int i = 0; i < 4; i++)
        rb[i] = *(const float4*)&W2c[(size_t)bkk[i] * 128 + bn4[i]];
    for (int k0 = 0; k0 < 128; k0 += 32) {
        #pragma unroll
        for (int i = 0; i < 4; i++) {
            float4 w = rb[i];
            w.x = to_tf32(w.x); w.y = to_tf32(w.y);
            w.z = to_tf32(w.z); w.w = to_tf32(w.w);
            *(float4*)&Bs[bkk[i] * 136 + bn4[i]] = w;
        }
        __syncthreads();
        if (k0 + 32 < 128) {
            #pragma unroll
            for (int i = 0; i < 4; i++)
                rb[i] = *(const float4*)&W2c[(size_t)(k0 + 32 + bkk[i]) * 128 + bn4[i]];
        }
        #pragma unroll
        for (int ks = 0; ks < 32; ks += 8) {
            uint32_t af[4][4], bf[4][2];
            #pragma unroll
            for (int mt = 0; mt < 4; mt++) {
                const float* ap = &Hs[(wm * 64 + mt * 16 + gid) * 132 + k0 + ks + tig];
                af[mt][0] = __float_as_uint(ap[0]);
                af[mt][1] = __float_as_uint(ap[8 * 132]);
                af[mt][2] = __float_as_uint(ap[4]);
                af[mt][3] = __float_as_uint(ap[8 * 132 + 4]);
            }
            #pragma unroll
            for (int nt = 0; nt < 4; nt++) {
                const float* bp = &Bs[(ks + tig) * 136 + wn * 32 + nt * 8 + gid];
                bf[nt][0] = __float_as_uint(bp[0]);
                bf[nt][1] = __float_as_uint(bp[4 * 136]);
            }
            #pragma unroll
            for (int mt = 0; mt < 4; mt++)
                #pragma unroll
                for (int nt = 0; nt < 4; nt++) MMA_TF32(acc[mt][nt], af[mt], bf[nt]);
        }
        __syncthreads();
    }

    #pragma unroll
    for (int mt = 0; mt < 4; mt++) {
        int r0 = bm + wm * 64 + mt * 16 + gid;
        int r1 = r0 + 8;
        #pragma unroll
        for (int nt = 0; nt < 4; nt++) {
            int c0 = wn * 32 + nt * 8 + 2 * tig;
            float b0 = b2c[c0], b1 = b2c[c0 + 1];
            float2 o0 = {acc[mt][nt][0] + b0, acc[mt][nt][1] + b1};
            float2 o1 = {acc[mt][nt][2] + b0, acc[mt][nt][3] + b1};
            *(float2*)&g_AB2[(size_t)r0 * 128 + c0] = o0;
            *(float2*)&g_AB2[(size_t)r1 * 128 + c0] = o1;
        }
    }
    (void)AB2;
}

// ---------------- fp32 GEMM 128x64 tile (actterm) ----------------------------
__global__ void gemm_kernel(const float* __restrict__ A, const float* __restrict__ W,
                            const float* __restrict__ bias, float* __restrict__ C,
                            int M, int K, int Nc, int do_relu) {
    __shared__ float As[16][132];
    __shared__ float Bs[16][68];
    int bm = blockIdx.y * 128;
    int bn = blockIdx.x * 64;
    int t = threadIdx.x;
    int ty = t >> 4, tx = t & 15;
    float acc[8][4] = {};
    for (int k0 = 0; k0 < K; k0 += 16) {
        #pragma unroll
        for (int i = 0; i < 2; i++) {
            int idx = t + i * 256;
            int row = idx >> 2;
            int kq = (idx & 3) << 2;
            float4 v = *(const float4*)&A[(size_t)(bm + row) * K + k0 + kq];
            As[kq + 0][row] = v.x;
            As[kq + 1][row] = v.y;
            As[kq + 2][row] = v.z;
            As[kq + 3][row] = v.w;
        }
        {
            int kk = t >> 4;
            int col = (t & 15) << 2;
            *(float4*)&Bs[kk][col] = *(const float4*)&W[(size_t)(k0 + kk) * Nc + bn + col];
        }
        __syncthreads();
        #pragma unroll
        for (int kk = 0; kk < 16; kk++) {
            float a[8], b[4];
            *(float4*)&a[0] = *(const float4*)&As[kk][ty * 8];
            *(float4*)&a[4] = *(const float4*)&As[kk][ty * 8 + 4];
            *(float4*)&b[0] = *(const float4*)&Bs[kk][tx * 4];
            #pragma unroll
            for (int i = 0; i < 8; i++)
                #pragma unroll
                for (int j = 0; j < 4; j++) acc[i][j] = fmaf(a[i], b[j], acc[i][j]);
        }
        __syncthreads();
    }
    #pragma unroll
    for (int i = 0; i < 8; i++) {
        int r = bm + ty * 8 + i;
        int c0 = bn + tx * 4;
        float4 v;
        float* vp = &v.x;
        #pragma unroll
        for (int j = 0; j < 4; j++) {
            float xv = acc[i][j] + bias[c0 + j];
            if (do_relu) xv = fmaxf(xv, 0.f);
            vp[j] = xv;
        }
        *(float4*)&C[(size_t)r * Nc + c0] = v;
    }
}

// ---------------- edge aggregation --------------------------------------------

__device__ __forceinline__ void acc_relu4(float4& acc, float4 a, float4 b) {
    acc.x += fmaxf(a.x + b.x, 0.f);
    acc.y += fmaxf(a.y + b.y, 0.f);
    acc.z += fmaxf(a.z + b.z, 0.f);
    acc.w += fmaxf(a.w + b.w, 0.f);
}

__global__ void agg1_kernel() {
    int w = (blockIdx.x * blockDim.x + threadIdx.x) >> 5;
    int lane = threadIdx.x & 31;
    int deg = g_deg[w], start = g_off[w];
    float4 a = *(const float4*)&g_AB1[(size_t)w * 256 + lane * 4];
    float4 acc = {0.f, 0.f, 0.f, 0.f};
    int i = 0;
    for (; i + 8 <= deg; i += 8) {
        int s[8];
        #pragma unroll
        for (int u = 0; u < 8; u++) s[u] = g_csr[start + i + u];
        float4 b[8];
        #pragma unroll
        for (int u = 0; u < 8; u++)
            b[u] = *(const float4*)&g_AB1[(size_t)s[u] * 256 + 128 + lane * 4];
        #pragma unroll
        for (int u = 0; u < 8; u++) acc_relu4(acc, a, b[u]);
    }
    for (; i + 2 <= deg; i += 2) {
        int s0 = g_csr[start + i], s1 = g_csr[start + i + 1];
        float4 b0 = *(const float4*)&g_AB1[(size_t)s0 * 256 + 128 + lane * 4];
        float4 b1 = *(const float4*)&g_AB1[(size_t)s1 * 256 + 128 + lane * 4];
        acc_relu4(acc, a, b0);
        acc_relu4(acc, a, b1);
    }
    for (; i < deg; i++) {
        int s = g_csr[start + i];
        float4 b = *(const float4*)&g_AB1[(size_t)s * 256 + 128 + lane * 4];
        acc_relu4(acc, a, b);
    }
    float inv = 1.f / fmaxf((float)deg, 1.f);
    float4 o = {acc.x * inv, acc.y * inv, acc.z * inv, acc.w * inv};
    *(float4*)&g_sum1[(size_t)w * 128 + lane * 4] = o;
}

__device__ __forceinline__ void acc_relu2(float2& acc, float2 a, float2 b) {
    acc.x += fmaxf(a.x + b.x, 0.f);
    acc.y += fmaxf(a.y + b.y, 0.f);
}

// agg2: per-node mean atomically accumulated into per-graph sums
__global__ void agg2_kernel() {
    int w = (blockIdx.x * blockDim.x + threadIdx.x) >> 5;
    int lane = threadIdx.x & 31;
    int deg = g_deg[w], start = g_off[w];
    float2 a = *(const float2*)&g_AB2[(size_t)w * 128 + lane * 2];
    float2 acc = {0.f, 0.f};
    int i = 0;
    for (; i + 8 <= deg; i += 8) {
        int s[8];
        #pragma unroll
        for (int u = 0; u < 8; u++) s[u] = g_csr[start + i + u];
        float2 b[8];
        #pragma unroll
        for (int u = 0; u < 8; u++)
            b[u] = *(const float2*)&g_AB2[(size_t)s[u] * 128 + 64 + lane * 2];
        #pragma unroll
        for (int u = 0; u < 8; u++) acc_relu2(acc, a, b[u]);
    }
    for (; i + 2 <= deg; i += 2) {
        int s0 = g_csr[start + i], s1 = g_csr[start + i + 1];
        float2 b0 = *(const float2*)&g_AB2[(size_t)s0 * 128 + 64 + lane * 2];
        float2 b1 = *(const float2*)&g_AB2[(size_t)s1 * 128 + 64 + lane * 2];
        acc_relu2(acc, a, b0);
        acc_relu2(acc, a, b1);
    }
    for (; i < deg; i++) {
        int s = g_csr[start + i];
        float2 b = *(const float2*)&g_AB2[(size_t)s * 128 + 64 + lane * 2];
        acc_relu2(acc, a, b);
    }
    if (deg > 0) {
        float inv = 1.f / (float)deg;
        int g = w >> 6;
        atomicAdd(&g_gsum[g * 64 + lane * 2],     acc.x * inv);
        atomicAdd(&g_gsum[g * 64 + lane * 2 + 1], acc.y * inv);
    }
}

// ---------------- fused tail: z = [state|action|ge] --------------------------
__global__ void tail_kernel(const float* __restrict__ state, const float* __restrict__ action,
                            const float* __restrict__ w2, const float* __restrict__ b2) {
    __shared__ float S[64];
    __shared__ int np;
    int g = blockIdx.x;
    int t = threadIdx.x;    // 192
    if (t == 0) np = 0;
    __syncthreads();
    if (t < 128) {
        g_z[g * 192 + t] = (t < 96) ? state[g * 96 + t] : action[g * 32 + (t - 96)];
    } else {
        int c = t - 128;
        S[c] = g_gsum[g * 64 + c];
        unsigned bal = __ballot_sync(0xffffffffu, g_deg[g * 64 + c] > 0);
        if ((t & 31) == 0) atomicAdd(&np, __popc(bal));
    }
    __syncthreads();
    if (t >= 128) {
        int c = t - 128;
        float npos = (float)np;
        float acc = 0.f;
        #pragma unroll 8
        for (int k = 0; k < 64; k++) acc = fmaf(S[k], w2[k * 64 + c], acc);
        g_z[g * 192 + 128 + c] = (acc + npos * b2[c]) * (1.f / 64.f);
    }
}

__global__ void qdot_kernel(const float* __restrict__ w3a, const float* __restrict__ b3a,
                            const float* __restrict__ w3b, const float* __restrict__ b3b,
                            float* __restrict__ out) {
    int warp = (blockIdx.x * blockDim.x + threadIdx.x) >> 5;
    int lane = threadIdx.x & 31;
    if (warp >= 2 * NB) return;
    int head = warp >> 10;
    const float* w3 = head ? w3b : w3a;
    const float* b3 = head ? b3b : b3a;
    const float* t2 = &g_t2[(size_t)warp * 256];
    float s = 0.f;
    #pragma unroll
    for (int k = lane; k < 256; k += 32) s += t2[k] * w3[k];
    #pragma unroll
    for (int o = 16; o > 0; o >>= 1) s += __shfl_down_sync(0xffffffffu, s, o);
    if (lane == 0) out[warp] = s + b3[0];
}

// ---------------- launch ------------------------------------------------------

extern "C" void kernel_launch(void* const* d_in, const int* in_sizes, int n_in,
                              void* d_out, int out_size) {
    const float* state  = (const float*)d_in[0];
    const float* action = (const float*)d_in[1];
    const float* x      = (const float*)d_in[2];
    const int*   eidx   = (const int*)d_in[3];
    const float* g1_w1 = (const float*)d_in[5];
    const float* g1_b1 = (const float*)d_in[6];
    const float* g1_w2 = (const float*)d_in[7];
    const float* g1_b2 = (const float*)d_in[8];
    const float* g2_w1 = (const float*)d_in[9];
    const float* g2_b1 = (const float*)d_in[10];
    const float* g2_w2 = (const float*)d_in[11];
    const float* g2_b2 = (const float*)d_in[12];
    const float* q1_w1 = (const float*)d_in[13];
    const float* q1_b1 = (const float*)d_in[14];
    const float* q1_w2 = (const float*)d_in[15];
    const float* q1_b2 = (const float*)d_in[16];
    const float* q1_w3 = (const float*)d_in[17];
    const float* q1_b3 = (const float*)d_in[18];
    const float* q2_w1 = (const float*)d_in[19];
    const float* q2_b1 = (const float*)d_in[20];
    const float* q2_w2 = (const float*)d_in[21];
    const float* q2_b2 = (const float*)d_in[22];
    const float* q2_w3 = (const float*)d_in[23];
    const float* q2_b3 = (const float*)d_in[24];
    float* out = (float*)d_out;

    const int4* srcs4 = (const int4*)eidx;
    const int4* dsts4 = (const int4*)(eidx + NE);

    float *p_AB1, *p_sum1, *p_AB2, *p_z, *p_t1, *p_t2;
    float *p_W1, *p_b1, *p_W2, *p_b2, *p_act, *p_QW1, *p_Qb1;
    int *p_deg;
    cudaGetSymbolAddress((void**)&p_AB1,  g_AB1);
    cudaGetSymbolAddress((void**)&p_sum1, g_sum1);
    cudaGetSymbolAddress((void**)&p_AB2,  g_AB2);
    cudaGetSymbolAddress((void**)&p_z,    g_z);
    cudaGetSymbolAddress((void**)&p_t1,   g_t1);
    cudaGetSymbolAddress((void**)&p_t2,   g_t2);
    cudaGetSymbolAddress((void**)&p_W1,   g_W1);
    cudaGetSymbolAddress((void**)&p_b1,   g_bias1);
    cudaGetSymbolAddress((void**)&p_W2,   g_W2);
    cudaGetSymbolAddress((void**)&p_b2,   g_bias2);
    cudaGetSymbolAddress((void**)&p_act,  g_actterm);
    cudaGetSymbolAddress((void**)&p_QW1,  g_QW1);
    cudaGetSymbolAddress((void**)&p_Qb1,  g_Qb1);
    cudaGetSymbolAddress((void**)&p_deg,  g_deg);

    const int GNN2_SMEM = (128 * 132 + 32 * 136) * 4;   // 84992 bytes
    cudaFuncSetAttribute(gnn2_kernel, cudaFuncAttributeMaxDynamicSharedMemorySize, GNN2_SMEM);

    // prep (+zeros) and CSR build
    prep_kernel<<<(148352 + NN + NB * 64 + 255) / 256, 256>>>(g1_w1, g1_b1, g2_w1, g2_b1,
                                                              q1_w1, q1_b1, q2_w1, q2_b1);
    count_kernel<<<NE / 4 / 256, 256>>>(dsts4);
    blocksum_kernel<<<256, 256>>>();
    bscan_kernel<<<1, 256>>>();
    fill_kernel<<<256, 256>>>();
    scatter_kernel<<<NE / 4 / 256, 256>>>(srcs4, dsts4);

    // actterm = action @ W1cat[96:128] + b1cat
    gemm_kernel<<<dim3(4, NB / 128), 256>>>(action, p_W1 + 96 * 256, p_b1, p_act,
                                            NB, 32, 256, 0);
    // AB1 = x @ W1cat[0:96] + actterm[graph]
    gemm_tf32_kernel<<<dim3(2, NN / 128), 256>>>(x, p_W1, nullptr, p_AB1,
                                                 NN, 96, 256, 96, 0, p_act,
                                                 nullptr, nullptr, nullptr, 0);
    agg1_kernel<<<NN / 8, 256>>>();
    // fused: h1 = relu(sum1@g1_w2+b2)*mask; AB2 = h1@W2cat + b2cat
    gnn2_kernel<<<dim3(1, NN / 128), 256, GNN2_SMEM>>>(p_sum1, g1_w2, g1_b2,
                                                       p_W2, p_b2, p_AB2, p_deg);
    agg2_kernel<<<NN / 8, 256>>>();
    tail_kernel<<<NB, 192>>>(state, action, g2_w2, g2_b2);
    // Q heads
    gemm_tf32_kernel<<<dim3(4, NB / 128), 256>>>(p_z, p_QW1, p_Qb1, p_t1,
                                                 NB, 192, 512, 192, 1, nullptr,
                                                 nullptr, nullptr, nullptr, 0);
    gemm_tf32_kernel<<<dim3(2, NB / 128, 2), 256>>>(p_t1, q1_w2, q1_b2, p_t2,
                                                    NB, 256, 256, 512, 1, nullptr,
                                                    q2_w2, q2_b2, p_t2 + NB * 256, 256);
    qdot_kernel<<<(2 * NB * 32) / 256, 256>>>(q1_w3, q1_b3, q2_w3, q2_b3, out);
}

// round 8
// speedup vs baseline: 4.1788x; 1.0247x over previous
#include <cuda_runtime.h>
#include <cstdint>

#define NN 65536
#define NE 524288
#define NB 1024

// ---------------- scratch (device globals) ----------------------------------
__device__ float g_AB1[NN * 256];
__device__ float g_sum1[NN * 128];
__device__ float g_AB2[NN * 128];
__device__ float g_gsum[NB * 64];
__device__ float g_z[NB * 192];
__device__ float g_t1[NB * 512];
__device__ float g_t2[2 * NB * 256];
__device__ float g_actterm[NB * 256];
__device__ float g_W1[128 * 256];
__device__ float g_bias1[256];
__device__ float g_W2[128 * 128];
__device__ float g_bias2[128];
__device__ float g_QW1[192 * 512];
__device__ float g_Qb1[512];
__device__ int   g_deg[NN];
__device__ int   g_off[NN];
__device__ int   g_cur[NN];
__device__ int   g_csr[NE];
__device__ int   g_bsum[256];
__device__ int   g_boff[256];

// ---------------- prep (weights only; deg/gsum zero moved to CSR branch) -----

__global__ void prep_kernel(const float* __restrict__ g1w1, const float* __restrict__ g1b1,
                            const float* __restrict__ g2w1, const float* __restrict__ g2b1,
                            const float* __restrict__ q1w1, const float* __restrict__ q1b1,
                            const float* __restrict__ q2w1, const float* __restrict__ q2b1) {
    int idx = blockIdx.x * blockDim.x + threadIdx.x;
    if (idx < 32768) {
        int k = idx >> 8, j = idx & 255;
        g_W1[idx] = (j < 128) ? g1w1[k * 128 + j] : g1w1[(k + 128) * 128 + (j - 128)];
    } else if (idx < 33024) {
        int j = idx - 32768;
        g_bias1[j] = (j < 128) ? g1b1[j] : 0.f;
    } else if (idx < 49408) {
        int i2 = idx - 33024;
        int k = i2 >> 7, j = i2 & 127;
        g_W2[i2] = (j < 64) ? g2w1[k * 64 + j] : g2w1[(k + 128) * 64 + (j - 64)];
    } else if (idx < 49536) {
        int j = idx - 49408;
        g_bias2[j] = (j < 64) ? g2b1[j] : 0.f;
    } else if (idx < 147840) {
        int i2 = idx - 49536;
        int k = i2 / 512, c = i2 & 511;
        g_QW1[i2] = (c < 256) ? q1w1[k * 256 + c] : q2w1[k * 256 + (c - 256)];
    } else if (idx < 148352) {
        int j = idx - 147840;
        g_Qb1[j] = (j < 256) ? q1b1[j] : q2b1[j - 256];
    }
}

// ---------------- CSR build (side-stream chain) -------------------------------

__global__ void zero_kernel() {
    int idx = blockIdx.x * blockDim.x + threadIdx.x;
    if (idx < NN) g_deg[idx] = 0;
    else if (idx < NN + NB * 64) g_gsum[idx - NN] = 0.f;
}

__global__ void count_kernel(const int4* __restrict__ dst4) {
    int i = blockIdx.x * blockDim.x + threadIdx.x;
    int4 d = dst4[i];
    atomicAdd(&g_deg[d.x], 1);
    atomicAdd(&g_deg[d.y], 1);
    atomicAdd(&g_deg[d.z], 1);
    atomicAdd(&g_deg[d.w], 1);
}

__global__ void blocksum_kernel() {
    __shared__ int sh[256];
    int t = threadIdx.x;
    sh[t] = g_deg[blockIdx.x * 256 + t];
    __syncthreads();
    for (int off = 128; off > 0; off >>= 1) {
        if (t < off) sh[t] += sh[t + off];
        __syncthreads();
    }
    if (t == 0) g_bsum[blockIdx.x] = sh[0];
}

__global__ void bscan_kernel() {
    __shared__ int sh[256];
    int t = threadIdx.x;
    sh[t] = g_bsum[t];
    __syncthreads();
    for (int off = 1; off < 256; off <<= 1) {
        int v = (t >= off) ? sh[t - off] : 0;
        __syncthreads();
        sh[t] += v;
        __syncthreads();
    }
    g_boff[t] = sh[t] - g_bsum[t];
}

__global__ void fill_kernel() {
    __shared__ int sh[256];
    int t = threadIdx.x;
    int gi = blockIdx.x * 256 + t;
    int d = g_deg[gi];
    sh[t] = d;
    __syncthreads();
    for (int off = 1; off < 256; off <<= 1) {
        int v = (t >= off) ? sh[t - off] : 0;
        __syncthreads();
        sh[t] += v;
        __syncthreads();
    }
    int excl = sh[t] - d + g_boff[blockIdx.x];
    g_off[gi] = excl;
    g_cur[gi] = excl;
}

__global__ void scatter_kernel(const int4* __restrict__ src4, const int4* __restrict__ dst4) {
    int i = blockIdx.x * blockDim.x + threadIdx.x;
    int4 s = src4[i];
    int4 d = dst4[i];
    g_csr[atomicAdd(&g_cur[d.x], 1)] = s.x;
    g_csr[atomicAdd(&g_cur[d.y], 1)] = s.y;
    g_csr[atomicAdd(&g_cur[d.z], 1)] = s.z;
    g_csr[atomicAdd(&g_cur[d.w], 1)] = s.w;
}

// ---------------- tf32 helpers -------------------------------------------------

__device__ __forceinline__ float to_tf32(float x) {
    uint32_t u;
    asm("cvt.rna.tf32.f32 %0, %1;" : "=r"(u) : "f"(x));
    return __uint_as_float(u);
}

#define MMA_TF32(acc, af, bf)                                              \
    asm volatile(                                                          \
        "mma.sync.aligned.m16n8k8.row.col.f32.tf32.tf32.f32 "              \
        "{%0,%1,%2,%3}, {%4,%5,%6,%7}, {%8,%9}, {%0,%1,%2,%3};"            \
        : "+f"(acc[0]), "+f"(acc[1]), "+f"(acc[2]), "+f"(acc[3])           \
        : "r"(af[0]), "r"(af[1]), "r"(af[2]), "r"(af[3]),                  \
          "r"(bf[0]), "r"(bf[1]))

// ---------------- tf32 GEMM (register-prefetch pipelined) --------------------
__global__ void __launch_bounds__(256)
gemm_tf32_kernel(const float* __restrict__ A, const float* __restrict__ W,
                 const float* __restrict__ bias, float* __restrict__ C,
                 int M, int K, int Nc, int lda, int do_relu,
                 const float* __restrict__ rowadd,
                 const float* Wb, const float* biasb, float* Cb, int acoloff) {
    if (blockIdx.z == 1) {
        A += acoloff;
        W = Wb;
        bias = biasb;
        C = Cb;
    }
    __shared__ float As[128 * 36];
    __shared__ float Bs[32 * 136];
    int bm = blockIdx.y * 128;
    int bn = blockIdx.x * 128;
    int t = threadIdx.x;
    int warp = t >> 5, lane = t & 31;
    int wm = warp >> 2, wn = warp & 3;
    int gid = lane >> 2, tig = lane & 3;

    int arow[4], akq[4], bkk[4], bn4[4];
    #pragma unroll
    for (int i = 0; i < 4; i++) {
        int idx = t + i * 256;
        arow[i] = idx >> 3;
        akq[i]  = (idx & 7) << 2;
        bkk[i]  = idx >> 5;
        bn4[i]  = (idx & 31) << 2;
    }

    float acc[4][4][4];
    #pragma unroll
    for (int a = 0; a < 4; a++)
        #pragma unroll
        for (int b = 0; b < 4; b++)
            #pragma unroll
            for (int c = 0; c < 4; c++) acc[a][b][c] = 0.f;

    float4 ra[4], rb[4];
    #pragma unroll
    for (int i = 0; i < 4; i++) {
        ra[i] = *(const float4*)&A[(size_t)(bm + arow[i]) * lda + akq[i]];
        rb[i] = *(const float4*)&W[(size_t)bkk[i] * Nc + bn + bn4[i]];
    }

    for (int k0 = 0; k0 < K; k0 += 32) {
        #pragma unroll
        for (int i = 0; i < 4; i++) {
            float4 v = ra[i];
            v.x = to_tf32(v.x); v.y = to_tf32(v.y);
            v.z = to_tf32(v.z); v.w = to_tf32(v.w);
            *(float4*)&As[arow[i] * 36 + akq[i]] = v;
            float4 w = rb[i];
            w.x = to_tf32(w.x); w.y = to_tf32(w.y);
            w.z = to_tf32(w.z); w.w = to_tf32(w.w);
            *(float4*)&Bs[bkk[i] * 136 + bn4[i]] = w;
        }
        __syncthreads();
        if (k0 + 32 < K) {
            #pragma unroll
            for (int i = 0; i < 4; i++) {
                ra[i] = *(const float4*)&A[(size_t)(bm + arow[i]) * lda + k0 + 32 + akq[i]];
                rb[i] = *(const float4*)&W[(size_t)(k0 + 32 + bkk[i]) * Nc + bn + bn4[i]];
            }
        }
        #pragma unroll
        for (int ks = 0; ks < 32; ks += 8) {
            uint32_t af[4][4], bf[4][2];
            #pragma unroll
            for (int mt = 0; mt < 4; mt++) {
                const float* ap = &As[(wm * 64 + mt * 16 + gid) * 36 + ks + tig];
                af[mt][0] = __float_as_uint(ap[0]);
                af[mt][1] = __float_as_uint(ap[8 * 36]);
                af[mt][2] = __float_as_uint(ap[4]);
                af[mt][3] = __float_as_uint(ap[8 * 36 + 4]);
            }
            #pragma unroll
            for (int nt = 0; nt < 4; nt++) {
                const float* bp = &Bs[(ks + tig) * 136 + wn * 32 + nt * 8 + gid];
                bf[nt][0] = __float_as_uint(bp[0]);
                bf[nt][1] = __float_as_uint(bp[4 * 136]);
            }
            #pragma unroll
            for (int mt = 0; mt < 4; mt++)
                #pragma unroll
                for (int nt = 0; nt < 4; nt++) MMA_TF32(acc[mt][nt], af[mt], bf[nt]);
        }
        __syncthreads();
    }

    #pragma unroll
    for (int mt = 0; mt < 4; mt++) {
        int r0 = bm + wm * 64 + mt * 16 + gid;
        int r1 = r0 + 8;
        #pragma unroll
        for (int nt = 0; nt < 4; nt++) {
            int c0 = bn + wn * 32 + nt * 8 + 2 * tig;
            float b0 = bias ? bias[c0] : 0.f;
            float b1 = bias ? bias[c0 + 1] : 0.f;
            float ra00 = 0.f, ra01 = 0.f, ra10 = 0.f, ra11 = 0.f;
            if (rowadd) {
                ra00 = rowadd[(size_t)(r0 >> 6) * Nc + c0];
                ra01 = rowadd[(size_t)(r0 >> 6) * Nc + c0 + 1];
                ra10 = rowadd[(size_t)(r1 >> 6) * Nc + c0];
                ra11 = rowadd[(size_t)(r1 >> 6) * Nc + c0 + 1];
            }
            float v00 = acc[mt][nt][0] + b0 + ra00;
            float v01 = acc[mt][nt][1] + b1 + ra01;
            float v10 = acc[mt][nt][2] + b0 + ra10;
            float v11 = acc[mt][nt][3] + b1 + ra11;
            if (do_relu) {
                v00 = fmaxf(v00, 0.f); v01 = fmaxf(v01, 0.f);
                v10 = fmaxf(v10, 0.f); v11 = fmaxf(v11, 0.f);
            }
            float2 o0 = {v00, v01};
            float2 o1 = {v10, v11};
            *(float2*)&C[(size_t)r0 * Nc + c0] = o0;
            *(float2*)&C[(size_t)r1 * Nc + c0] = o1;
        }
    }
}

// ---------------- fused GNN stage 2 ------------------------------------------
__global__ void __launch_bounds__(256)
gnn2_kernel(const float* __restrict__ sum1, const float* __restrict__ W1b,
            const float* __restrict__ b1b, const float* __restrict__ W2c,
            const float* __restrict__ b2c, const int* __restrict__ deg) {
    extern __shared__ float sm[];
    float* Hs = sm;
    float* As = sm;
    float* Bs = sm + 128 * 132;
    int bm = blockIdx.y * 128;
    int t = threadIdx.x;
    int warp = t >> 5, lane = t & 31;
    int wm = warp >> 2, wn = warp & 3;
    int gid = lane >> 2, tig = lane & 3;

    int arow[4], akq[4], bkk[4], bn4[4];
    #pragma unroll
    for (int i = 0; i < 4; i++) {
        int idx = t + i * 256;
        arow[i] = idx >> 3;
        akq[i]  = (idx & 7) << 2;
        bkk[i]  = idx >> 5;
        bn4[i]  = (idx & 31) << 2;
    }

    float acc[4][4][4];
    #pragma unroll
    for (int a = 0; a < 4; a++)
        #pragma unroll
        for (int b = 0; b < 4; b++)
            #pragma unroll
            for (int c = 0; c < 4; c++) acc[a][b][c] = 0.f;

    float4 ra[4], rb[4];
    #pragma unroll
    for (int i = 0; i < 4; i++) {
        ra[i] = *(const float4*)&sum1[(size_t)(bm + arow[i]) * 128 + akq[i]];
        rb[i] = *(const float4*)&W1b[(size_t)bkk[i] * 128 + bn4[i]];
    }
    for (int k0 = 0; k0 < 128; k0 += 32) {
        #pragma unroll
        for (int i = 0; i < 4; i++) {
            float4 v = ra[i];
            v.x = to_tf32(v.x); v.y = to_tf32(v.y);
            v.z = to_tf32(v.z); v.w = to_tf32(v.w);
            *(float4*)&As[arow[i] * 36 + akq[i]] = v;
            float4 w = rb[i];
            w.x = to_tf32(w.x); w.y = to_tf32(w.y);
            w.z = to_tf32(w.z); w.w = to_tf32(w.w);
            *(float4*)&Bs[bkk[i] * 136 + bn4[i]] = w;
        }
        __syncthreads();
        if (k0 + 32 < 128) {
            #pragma unroll
            for (int i = 0; i < 4; i++) {
                ra[i] = *(const float4*)&sum1[(size_t)(bm + arow[i]) * 128 + k0 + 32 + akq[i]];
                rb[i] = *(const float4*)&W1b[(size_t)(k0 + 32 + bkk[i]) * 128 + bn4[i]];
            }
        }
        #pragma unroll
        for (int ks = 0; ks < 32; ks += 8) {
            uint32_t af[4][4], bf[4][2];
            #pragma unroll
            for (int mt = 0; mt < 4; mt++) {
                const float* ap = &As[(wm * 64 + mt * 16 + gid) * 36 + ks + tig];
                af[mt][0] = __float_as_uint(ap[0]);
                af[mt][1] = __float_as_uint(ap[8 * 36]);
                af[mt][2] = __float_as_uint(ap[4]);
                af[mt][3] = __float_as_uint(ap[8 * 36 + 4]);
            }
            #pragma unroll
            for (int nt = 0; nt < 4; nt++) {
                const float* bp = &Bs[(ks + tig) * 136 + wn * 32 + nt * 8 + gid];
                bf[nt][0] = __float_as_uint(bp[0]);
                bf[nt][1] = __float_as_uint(bp[4 * 136]);
            }
            #pragma unroll
            for (int mt = 0; mt < 4; mt++)
                #pragma unroll
                for (int nt = 0; nt < 4; nt++) MMA_TF32(acc[mt][nt], af[mt], bf[nt]);
        }
        __syncthreads();
    }

    #pragma unroll
    for (int mt = 0; mt < 4; mt++) {
        int rl0 = wm * 64 + mt * 16 + gid;
        int rl1 = rl0 + 8;
        float zm0 = (deg[bm + rl0] == 0) ? 0.f : 1.f;
        float zm1 = (deg[bm + rl1] == 0) ? 0.f : 1.f;
        #pragma unroll
        for (int nt = 0; nt < 4; nt++) {
            int c0 = wn * 32 + nt * 8 + 2 * tig;
            float b0 = b1b[c0], b1 = b1b[c0 + 1];
            float2 o0 = {to_tf32(fmaxf(acc[mt][nt][0] + b0, 0.f) * zm0),
                         to_tf32(fmaxf(acc[mt][nt][1] + b1, 0.f) * zm0)};
            float2 o1 = {to_tf32(fmaxf(acc[mt][nt][2] + b0, 0.f) * zm1),
                         to_tf32(fmaxf(acc[mt][nt][3] + b1, 0.f) * zm1)};
            *(float2*)&Hs[rl0 * 132 + c0] = o0;
            *(float2*)&Hs[rl1 * 132 + c0] = o1;
            acc[mt][nt][0] = 0.f; acc[mt][nt][1] = 0.f;
            acc[mt][nt][2] = 0.f; acc[mt][nt][3] = 0.f;
        }
    }
    __syncthreads();

    #pragma unroll
    for (int i = 0; i < 4; i++)
        rb[i] = *(const float4*)&W2c[(size_t)bkk[i] * 128 + bn4[i]];
    for (int k0 = 0; k0 < 128; k0 += 32) {
        #pragma unroll
        for (int i = 0; i < 4; i++) {
            float4 w = rb[i];
            w.x = to_tf32(w.x); w.y = to_tf32(w.y);
            w.z = to_tf32(w.z); w.w = to_tf32(w.w);
            *(float4*)&Bs[bkk[i] * 136 + bn4[i]] = w;
        }
        __syncthreads();
        if (k0 + 32 < 128) {
            #pragma unroll
            for (int i = 0; i < 4; i++)
                rb[i] = *(const float4*)&W2c[(size_t)(k0 + 32 + bkk[i]) * 128 + bn4[i]];
        }
        #pragma unroll
        for (int ks = 0; ks < 32; ks += 8) {
            uint32_t af[4][4], bf[4][2];
            #pragma unroll
            for (int mt = 0; mt < 4; mt++) {
                const float* ap = &Hs[(wm * 64 + mt * 16 + gid) * 132 + k0 + ks + tig];
                af[mt][0] = __float_as_uint(ap[0]);
                af[mt][1] = __float_as_uint(ap[8 * 132]);
                af[mt][2] = __float_as_uint(ap[4]);
                af[mt][3] = __float_as_uint(ap[8 * 132 + 4]);
            }
            #pragma unroll
            for (int nt = 0; nt < 4; nt++) {
                const float* bp = &Bs[(ks + tig) * 136 + wn * 32 + nt * 8 + gid];
                bf[nt][0] = __float_as_uint(bp[0]);
                bf[nt][1] = __float_as_uint(bp[4 * 136]);
            }
            #pragma unroll
            for (int mt = 0; mt < 4; mt++)
                #pragma unroll
                for (int nt = 0; nt < 4; nt++) MMA_TF32(acc[mt][nt], af[mt], bf[nt]);
        }
        __syncthreads();
    }

    #pragma unroll
    for (int mt = 0; mt < 4; mt++) {
        int r0 = bm + wm * 64 + mt * 16 + gid;
        int r1 = r0 + 8;
        #pragma unroll
        for (int nt = 0; nt < 4; nt++) {
            int c0 = wn * 32 + nt * 8 + 2 * tig;
            float b0 = b2c[c0], b1 = b2c[c0 + 1];
            float2 o0 = {acc[mt][nt][0] + b0, acc[mt][nt][1] + b1};
            float2 o1 = {acc[mt][nt][2] + b0, acc[mt][nt][3] + b1};
            *(float2*)&g_AB2[(size_t)r0 * 128 + c0] = o0;
            *(float2*)&g_AB2[(size_t)r1 * 128 + c0] = o1;
        }
    }
}

// ---------------- fp32 GEMM 128x64 tile (actterm) ----------------------------
__global__ void gemm_kernel(const float* __restrict__ A, const float* __restrict__ W,
                            const float* __restrict__ bias, float* __restrict__ C,
                            int M, int K, int Nc, int do_relu) {
    __shared__ float As[16][132];
    __shared__ float Bs[16][68];
    int bm = blockIdx.y * 128;
    int bn = blockIdx.x * 64;
    int t = threadIdx.x;
    int ty = t >> 4, tx = t & 15;
    float acc[8][4] = {};
    for (int k0 = 0; k0 < K; k0 += 16) {
        #pragma unroll
        for (int i = 0; i < 2; i++) {
            int idx = t + i * 256;
            int row = idx >> 2;
            int kq = (idx & 3) << 2;
            float4 v = *(const float4*)&A[(size_t)(bm + row) * K + k0 + kq];
            As[kq + 0][row] = v.x;
            As[kq + 1][row] = v.y;
            As[kq + 2][row] = v.z;
            As[kq + 3][row] = v.w;
        }
        {
            int kk = t >> 4;
            int col = (t & 15) << 2;
            *(float4*)&Bs[kk][col] = *(const float4*)&W[(size_t)(k0 + kk) * Nc + bn + col];
        }
        __syncthreads();
        #pragma unroll
        for (int kk = 0; kk < 16; kk++) {
            float a[8], b[4];
            *(float4*)&a[0] = *(const float4*)&As[kk][ty * 8];
            *(float4*)&a[4] = *(const float4*)&As[kk][ty * 8 + 4];
            *(float4*)&b[0] = *(const float4*)&Bs[kk][tx * 4];
            #pragma unroll
            for (int i = 0; i < 8; i++)
                #pragma unroll
                for (int j = 0; j < 4; j++) acc[i][j] = fmaf(a[i], b[j], acc[i][j]);
        }
        __syncthreads();
    }
    #pragma unroll
    for (int i = 0; i < 8; i++) {
        int r = bm + ty * 8 + i;
        int c0 = bn + tx * 4;
        float4 v;
        float* vp = &v.x;
        #pragma unroll
        for (int j = 0; j < 4; j++) {
            float xv = acc[i][j] + bias[c0 + j];
            if (do_relu) xv = fmaxf(xv, 0.f);
            vp[j] = xv;
        }
        *(float4*)&C[(size_t)r * Nc + c0] = v;
    }
}

// ---------------- edge aggregation --------------------------------------------

__device__ __forceinline__ void acc_relu4(float4& acc, float4 a, float4 b) {
    acc.x += fmaxf(a.x + b.x, 0.f);
    acc.y += fmaxf(a.y + b.y, 0.f);
    acc.z += fmaxf(a.z + b.z, 0.f);
    acc.w += fmaxf(a.w + b.w, 0.f);
}

__global__ void agg1_kernel() {
    int w = (blockIdx.x * blockDim.x + threadIdx.x) >> 5;
    int lane = threadIdx.x & 31;
    int deg = g_deg[w], start = g_off[w];
    float4 a = *(const float4*)&g_AB1[(size_t)w * 256 + lane * 4];
    float4 acc = {0.f, 0.f, 0.f, 0.f};
    int i = 0;
    for (; i + 8 <= deg; i += 8) {
        int s[8];
        #pragma unroll
        for (int u = 0; u < 8; u++) s[u] = g_csr[start + i + u];
        float4 b[8];
        #pragma unroll
        for (int u = 0; u < 8; u++)
            b[u] = *(const float4*)&g_AB1[(size_t)s[u] * 256 + 128 + lane * 4];
        #pragma unroll
        for (int u = 0; u < 8; u++) acc_relu4(acc, a, b[u]);
    }
    for (; i + 2 <= deg; i += 2) {
        int s0 = g_csr[start + i], s1 = g_csr[start + i + 1];
        float4 b0 = *(const float4*)&g_AB1[(size_t)s0 * 256 + 128 + lane * 4];
        float4 b1 = *(const float4*)&g_AB1[(size_t)s1 * 256 + 128 + lane * 4];
        acc_relu4(acc, a, b0);
        acc_relu4(acc, a, b1);
    }
    for (; i < deg; i++) {
        int s = g_csr[start + i];
        float4 b = *(const float4*)&g_AB1[(size_t)s * 256 + 128 + lane * 4];
        acc_relu4(acc, a, b);
    }
    float inv = 1.f / fmaxf((float)deg, 1.f);
    float4 o = {acc.x * inv, acc.y * inv, acc.z * inv, acc.w * inv};
    *(float4*)&g_sum1[(size_t)w * 128 + lane * 4] = o;
}

__device__ __forceinline__ void acc_relu2(float2& acc, float2 a, float2 b) {
    acc.x += fmaxf(a.x + b.x, 0.f);
    acc.y += fmaxf(a.y + b.y, 0.f);
}

__global__ void agg2_kernel() {
    int w = (blockIdx.x * blockDim.x + threadIdx.x) >> 5;
    int lane = threadIdx.x & 31;
    int deg = g_deg[w], start = g_off[w];
    float2 a = *(const float2*)&g_AB2[(size_t)w * 128 + lane * 2];
    float2 acc = {0.f, 0.f};
    int i = 0;
    for (; i + 8 <= deg; i += 8) {
        int s[8];
        #pragma unroll
        for (int u = 0; u < 8; u++) s[u] = g_csr[start + i + u];
        float2 b[8];
        #pragma unroll
        for (int u = 0; u < 8; u++)
            b[u] = *(const float2*)&g_AB2[(size_t)s[u] * 128 + 64 + lane * 2];
        #pragma unroll
        for (int u = 0; u < 8; u++) acc_relu2(acc, a, b[u]);
    }
    for (; i + 2 <= deg; i += 2) {
        int s0 = g_csr[start + i], s1 = g_csr[start + i + 1];
        float2 b0 = *(const float2*)&g_AB2[(size_t)s0 * 128 + 64 + lane * 2];
        float2 b1 = *(const float2*)&g_AB2[(size_t)s1 * 128 + 64 + lane * 2];
        acc_relu2(acc, a, b0);
        acc_relu2(acc, a, b1);
    }
    for (; i < deg; i++) {
        int s = g_csr[start + i];
        float2 b = *(const float2*)&g_AB2[(size_t)s * 128 + 64 + lane * 2];
        acc_relu2(acc, a, b);
    }
    if (deg > 0) {
        float inv = 1.f / (float)deg;
        int g = w >> 6;
        atomicAdd(&g_gsum[g * 64 + lane * 2],     acc.x * inv);
        atomicAdd(&g_gsum[g * 64 + lane * 2 + 1], acc.y * inv);
    }
}

// ---------------- fused tail --------------------------------------------------
__global__ void tail_kernel(const float* __restrict__ state, const float* __restrict__ action,
                            const float* __restrict__ w2, const float* __restrict__ b2) {
    __shared__ float S[64];
    __shared__ int np;
    int g = blockIdx.x;
    int t = threadIdx.x;
    if (t == 0) np = 0;
    __syncthreads();
    if (t < 128) {
        g_z[g * 192 + t] = (t < 96) ? state[g * 96 + t] : action[g * 32 + (t - 96)];
    } else {
        int c = t - 128;
        S[c] = g_gsum[g * 64 + c];
        unsigned bal = __ballot_sync(0xffffffffu, g_deg[g * 64 + c] > 0);
        if ((t & 31) == 0) atomicAdd(&np, __popc(bal));
    }
    __syncthreads();
    if (t >= 128) {
        int c = t - 128;
        float npos = (float)np;
        float acc = 0.f;
        #pragma unroll 8
        for (int k = 0; k < 64; k++) acc = fmaf(S[k], w2[k * 64 + c], acc);
        g_z[g * 192 + 128 + c] = (acc + npos * b2[c]) * (1.f / 64.f);
    }
}

__global__ void qdot_kernel(const float* __restrict__ w3a, const float* __restrict__ b3a,
                            const float* __restrict__ w3b, const float* __restrict__ b3b,
                            float* __restrict__ out) {
    int warp = (blockIdx.x * blockDim.x + threadIdx.x) >> 5;
    int lane = threadIdx.x & 31;
    if (warp >= 2 * NB) return;
    int head = warp >> 10;
    const float* w3 = head ? w3b : w3a;
    const float* b3 = head ? b3b : b3a;
    const float* t2 = &g_t2[(size_t)warp * 256];
    float s = 0.f;
    #pragma unroll
    for (int k = lane; k < 256; k += 32) s += t2[k] * w3[k];
    #pragma unroll
    for (int o = 16; o > 0; o >>= 1) s += __shfl_down_sync(0xffffffffu, s, o);
    if (lane == 0) out[warp] = s + b3[0];
}

// ---------------- launch ------------------------------------------------------

extern "C" void kernel_launch(void* const* d_in, const int* in_sizes, int n_in,
                              void* d_out, int out_size) {
    const float* state  = (const float*)d_in[0];
    const float* action = (const float*)d_in[1];
    const float* x      = (const float*)d_in[2];
    const int*   eidx   = (const int*)d_in[3];
    const float* g1_w1 = (const float*)d_in[5];
    const float* g1_b1 = (const float*)d_in[6];
    const float* g1_w2 = (const float*)d_in[7];
    const float* g1_b2 = (const float*)d_in[8];
    const float* g2_w1 = (const float*)d_in[9];
    const float* g2_b1 = (const float*)d_in[10];
    const float* g2_w2 = (const float*)d_in[11];
    const float* g2_b2 = (const float*)d_in[12];
    const float* q1_w1 = (const float*)d_in[13];
    const float* q1_b1 = (const float*)d_in[14];
    const float* q1_w2 = (const float*)d_in[15];
    const float* q1_b2 = (const float*)d_in[16];
    const float* q1_w3 = (const float*)d_in[17];
    const float* q1_b3 = (const float*)d_in[18];
    const float* q2_w1 = (const float*)d_in[19];
    const float* q2_b1 = (const float*)d_in[20];
    const float* q2_w2 = (const float*)d_in[21];
    const float* q2_b2 = (const float*)d_in[22];
    const float* q2_w3 = (const float*)d_in[23];
    const float* q2_b3 = (const float*)d_in[24];
    float* out = (float*)d_out;

    const int4* srcs4 = (const int4*)eidx;
    const int4* dsts4 = (const int4*)(eidx + NE);

    float *p_AB1, *p_sum1, *p_AB2, *p_z, *p_t1, *p_t2;
    float *p_W1, *p_b1, *p_W2, *p_b2, *p_act, *p_QW1, *p_Qb1;
    int *p_deg;
    cudaGetSymbolAddress((void**)&p_AB1,  g_AB1);
    cudaGetSymbolAddress((void**)&p_sum1, g_sum1);
    cudaGetSymbolAddress((void**)&p_AB2,  g_AB2);
    cudaGetSymbolAddress((void**)&p_z,    g_z);
    cudaGetSymbolAddress((void**)&p_t1,   g_t1);
    cudaGetSymbolAddress((void**)&p_t2,   g_t2);
    cudaGetSymbolAddress((void**)&p_W1,   g_W1);
    cudaGetSymbolAddress((void**)&p_b1,   g_bias1);
    cudaGetSymbolAddress((void**)&p_W2,   g_W2);
    cudaGetSymbolAddress((void**)&p_b2,   g_bias2);
    cudaGetSymbolAddress((void**)&p_act,  g_actterm);
    cudaGetSymbolAddress((void**)&p_QW1,  g_QW1);
    cudaGetSymbolAddress((void**)&p_Qb1,  g_Qb1);
    cudaGetSymbolAddress((void**)&p_deg,  g_deg);

    const int GNN2_SMEM = (128 * 132 + 32 * 136) * 4;
    cudaFuncSetAttribute(gnn2_kernel, cudaFuncAttributeMaxDynamicSharedMemorySize, GNN2_SMEM);

    // fork: side stream for CSR build (independent of the GEMM chain)
    cudaStream_t s2;
    cudaEvent_t eFork, eJoin;
    cudaStreamCreateWithFlags(&s2, cudaStreamNonBlocking);
    cudaEventCreateWithFlags(&eFork, cudaEventDisableTiming);
    cudaEventCreateWithFlags(&eJoin, cudaEventDisableTiming);

    cudaEventRecord(eFork, 0);
    cudaStreamWaitEvent(s2, eFork, 0);

    // ---- Chain B (side stream): CSR build ----
    zero_kernel<<<(NN + NB * 64 + 255) / 256, 256, 0, s2>>>();
    count_kernel<<<NE / 4 / 256, 256, 0, s2>>>(dsts4);
    blocksum_kernel<<<256, 256, 0, s2>>>();
    bscan_kernel<<<1, 256, 0, s2>>>();
    fill_kernel<<<256, 256, 0, s2>>>();
    scatter_kernel<<<NE / 4 / 256, 256, 0, s2>>>(srcs4, dsts4);
    cudaEventRecord(eJoin, s2);

    // ---- Chain A (main stream): weights + AB1 ----
    prep_kernel<<<(148352 + 255) / 256, 256>>>(g1_w1, g1_b1, g2_w1, g2_b1,
                                               q1_w1, q1_b1, q2_w1, q2_b1);
    gemm_kernel<<<dim3(4, NB / 128), 256>>>(action, p_W1 + 96 * 256, p_b1, p_act,
                                            NB, 32, 256, 0);
    gemm_tf32_kernel<<<dim3(2, NN / 128), 256>>>(x, p_W1, nullptr, p_AB1,
                                                 NN, 96, 256, 96, 0, p_act,
                                                 nullptr, nullptr, nullptr, 0);

    // join: agg1 needs both chains
    cudaStreamWaitEvent(0, eJoin, 0);

    agg1_kernel<<<NN / 8, 256>>>();
    gnn2_kernel<<<dim3(1, NN / 128), 256, GNN2_SMEM>>>(p_sum1, g1_w2, g1_b2,
                                                       p_W2, p_b2, p_deg);
    agg2_kernel<<<NN / 8, 256>>>();
    tail_kernel<<<NB, 192>>>(state, action, g2_w2, g2_b2);
    gemm_tf32_kernel<<<dim3(4, NB / 128), 256>>>(p_z, p_QW1, p_Qb1, p_t1,
                                                 NB, 192, 512, 192, 1, nullptr,
                                                 nullptr, nullptr, nullptr, 0);
    gemm_tf32_kernel<<<dim3(2, NB / 128, 2), 256>>>(p_t1, q1_w2, q1_b2, p_t2,
                                                    NB, 256, 256, 512, 1, nullptr,
                                                    q2_w2, q2_b2, p_t2 + NB * 256, 256);
    qdot_kernel<<<(2 * NB * 32) / 256, 256>>>(q1_w3, q1_b3, q2_w3, q2_b3, out);
}

// round 9
// speedup vs baseline: 4.1954x; 1.0040x over previous
#include <cuda_runtime.h>
#include <cstdint>

#define NN 65536
#define NE 524288
#define NB 1024

// ---------------- scratch (device globals) ----------------------------------
__device__ float g_xr[NN * 96];     // tf32-rounded x
__device__ float g_AB1[NN * 256];
__device__ float g_sum1[NN * 128];  // tf32-rounded means
__device__ float g_h1[NN * 128];    // tf32-rounded h1
__device__ float g_AB2[NN * 128];
__device__ float g_gsum[NB * 64];
__device__ float g_z[NB * 192];     // tf32-rounded z
__device__ float g_t1[NB * 512];    // tf32-rounded t1
__device__ float g_t2[2 * NB * 256];
__device__ float g_actterm[NB * 256];
__device__ float g_W1[128 * 256];   // rows 0..95 tf32-rounded, 96..127 raw fp32
__device__ float g_bias1[256];
__device__ float g_W2[128 * 128];   // tf32-rounded
__device__ float g_bias2[128];
__device__ float g_W1b[128 * 128];  // tf32(g1_w2)
__device__ float g_QW1[192 * 512];  // tf32-rounded
__device__ float g_Qb1[512];
__device__ float g_QW2a[256 * 256]; // tf32(q1_w2)
__device__ float g_QW2b[256 * 256]; // tf32(q2_w2)
__device__ int   g_deg[NN];
__device__ int   g_off[NN];
__device__ int   g_cur[NN];
__device__ int   g_csr[NE];
__device__ int   g_bsum[256];
__device__ int   g_boff[256];

// ---------------- tf32 helpers -------------------------------------------------

__device__ __forceinline__ float to_tf32(float x) {
    uint32_t u;
    asm("cvt.rna.tf32.f32 %0, %1;" : "=r"(u) : "f"(x));
    return __uint_as_float(u);
}

#define MMA_TF32(acc, af, bf)                                              \
    asm volatile(                                                          \
        "mma.sync.aligned.m16n8k8.row.col.f32.tf32.tf32.f32 "              \
        "{%0,%1,%2,%3}, {%4,%5,%6,%7}, {%8,%9}, {%0,%1,%2,%3};"            \
        : "+f"(acc[0]), "+f"(acc[1]), "+f"(acc[2]), "+f"(acc[3])           \
        : "r"(af[0]), "r"(af[1]), "r"(af[2]), "r"(af[3]),                  \
          "r"(bf[0]), "r"(bf[1]))

__device__ __forceinline__ void cp16(uint32_t s, const void* g) {
    asm volatile("cp.async.ca.shared.global [%0], [%1], 16;" :: "r"(s), "l"(g));
}

// ---------------- prep: pack + tf32-round all GEMM weights --------------------

__global__ void prep_kernel(const float* __restrict__ g1w1, const float* __restrict__ g1b1,
                            const float* __restrict__ g1w2,
                            const float* __restrict__ g2w1, const float* __restrict__ g2b1,
                            const float* __restrict__ q1w1, const float* __restrict__ q1b1,
                            const float* __restrict__ q1w2,
                            const float* __restrict__ q2w1, const float* __restrict__ q2b1,
                            const float* __restrict__ q2w2) {
    int idx = blockIdx.x * blockDim.x + threadIdx.x;
    if (idx < 32768) {
        int k = idx >> 8, j = idx & 255;
        float v = (j < 128) ? g1w1[k * 128 + j] : g1w1[(k + 128) * 128 + (j - 128)];
        g_W1[idx] = (k < 96) ? to_tf32(v) : v;   // rows>=96 stay fp32 (actterm path)
    } else if (idx < 33024) {
        int j = idx - 32768;
        g_bias1[j] = (j < 128) ? g1b1[j] : 0.f;
    } else if (idx < 49408) {
        int i2 = idx - 33024;
        int k = i2 >> 7, j = i2 & 127;
        float v = (j < 64) ? g2w1[k * 64 + j] : g2w1[(k + 128) * 64 + (j - 64)];
        g_W2[i2] = to_tf32(v);
    } else if (idx < 49536) {
        int j = idx - 49408;
        g_bias2[j] = (j < 64) ? g2b1[j] : 0.f;
    } else if (idx < 147840) {
        int i2 = idx - 49536;
        int k = i2 / 512, c = i2 & 511;
        float v = (c < 256) ? q1w1[k * 256 + c] : q2w1[k * 256 + (c - 256)];
        g_QW1[i2] = to_tf32(v);
    } else if (idx < 148352) {
        int j = idx - 147840;
        g_Qb1[j] = (j < 256) ? q1b1[j] : q2b1[j - 256];
    } else if (idx < 164736) {
        int i2 = idx - 148352;
        g_W1b[i2] = to_tf32(g1w2[i2]);
    } else if (idx < 230272) {
        int i2 = idx - 164736;
        g_QW2a[i2] = to_tf32(q1w2[i2]);
    } else if (idx < 295808) {
        int i2 = idx - 230272;
        g_QW2b[i2] = to_tf32(q2w2[i2]);
    }
}

// round x -> g_xr
__global__ void xr_kernel(const float4* __restrict__ x4) {
    int i = blockIdx.x * blockDim.x + threadIdx.x;   // NN*96/4
    float4 v = x4[i];
    v.x = to_tf32(v.x); v.y = to_tf32(v.y);
    v.z = to_tf32(v.z); v.w = to_tf32(v.w);
    *(float4*)&g_xr[(size_t)i * 4] = v;
}

// ---------------- CSR build (side-stream chain) -------------------------------

__global__ void zero_kernel() {
    int idx = blockIdx.x * blockDim.x + threadIdx.x;
    if (idx < NN) g_deg[idx] = 0;
    else if (idx < NN + NB * 64) g_gsum[idx - NN] = 0.f;
}

__global__ void count_kernel(const int4* __restrict__ dst4) {
    int i = blockIdx.x * blockDim.x + threadIdx.x;
    int4 d = dst4[i];
    atomicAdd(&g_deg[d.x], 1);
    atomicAdd(&g_deg[d.y], 1);
    atomicAdd(&g_deg[d.z], 1);
    atomicAdd(&g_deg[d.w], 1);
}

__global__ void blocksum_kernel() {
    __shared__ int sh[256];
    int t = threadIdx.x;
    sh[t] = g_deg[blockIdx.x * 256 + t];
    __syncthreads();
    for (int off = 128; off > 0; off >>= 1) {
        if (t < off) sh[t] += sh[t + off];
        __syncthreads();
    }
    if (t == 0) g_bsum[blockIdx.x] = sh[0];
}

__global__ void bscan_kernel() {
    __shared__ int sh[256];
    int t = threadIdx.x;
    sh[t] = g_bsum[t];
    __syncthreads();
    for (int off = 1; off < 256; off <<= 1) {
        int v = (t >= off) ? sh[t - off] : 0;
        __syncthreads();
        sh[t] += v;
        __syncthreads();
    }
    g_boff[t] = sh[t] - g_bsum[t];
}

__global__ void fill_kernel() {
    __shared__ int sh[256];
    int t = threadIdx.x;
    int gi = blockIdx.x * 256 + t;
    int d = g_deg[gi];
    sh[t] = d;
    __syncthreads();
    for (int off = 1; off < 256; off <<= 1) {
        int v = (t >= off) ? sh[t - off] : 0;
        __syncthreads();
        sh[t] += v;
        __syncthreads();
    }
    int excl = sh[t] - d + g_boff[blockIdx.x];
    g_off[gi] = excl;
    g_cur[gi] = excl;
}

__global__ void scatter_kernel(const int4* __restrict__ src4, const int4* __restrict__ dst4) {
    int i = blockIdx.x * blockDim.x + threadIdx.x;
    int4 s = src4[i];
    int4 d = dst4[i];
    g_csr[atomicAdd(&g_cur[d.x], 1)] = s.x;
    g_csr[atomicAdd(&g_cur[d.y], 1)] = s.y;
    g_csr[atomicAdd(&g_cur[d.z], 1)] = s.z;
    g_csr[atomicAdd(&g_cur[d.w], 1)] = s.w;
}

// ---------------- tf32 GEMM: cp.async double-buffered, operands pre-rounded ---
// C = act(A@W + bias + rowadd) [*mask] [round]; 128x128 tile, BK=32.
// gridDim.z==2: blockIdx.z==1 switches to Wb/biasb/Cb, A+acoloff.

__global__ void __launch_bounds__(256, 2)
gemm_db_kernel(const float* __restrict__ A, const float* __restrict__ W,
               const float* __restrict__ bias, float* __restrict__ C,
               int K, int Nc, int lda, int do_relu, int do_round,
               const int* __restrict__ degmask,
               const float* __restrict__ rowadd,
               const float* Wb, const float* biasb, float* Cb, int acoloff) {
    if (blockIdx.z == 1) {
        A += acoloff;
        W = Wb;
        bias = biasb;
        C = Cb;
    }
    extern __shared__ float sm[];
    float* AsB = sm;                     // [2][128*36]
    float* BsB = sm + 2 * 128 * 36;      // [2][32*136]
    const int ASZ = 128 * 36, BSZ = 32 * 136;
    int bm = blockIdx.y * 128;
    int bn = blockIdx.x * 128;
    int t = threadIdx.x;
    int warp = t >> 5, lane = t & 31;
    int wm = warp >> 2, wn = warp & 3;
    int gid = lane >> 2, tig = lane & 3;

    int ar[4], ak[4], bk[4], bn4[4];
    #pragma unroll
    for (int i = 0; i < 4; i++) {
        int idx = t + i * 256;
        ar[i] = idx >> 3;  ak[i]  = (idx & 7) << 2;
        bk[i] = idx >> 5;  bn4[i] = (idx & 31) << 2;
    }

    float acc[4][4][4];
    #pragma unroll
    for (int a = 0; a < 4; a++)
        #pragma unroll
        for (int b = 0; b < 4; b++)
            #pragma unroll
            for (int c = 0; c < 4; c++) acc[a][b][c] = 0.f;

    int ntiles = K >> 5;

    // issue stage 0
    #pragma unroll
    for (int i = 0; i < 4; i++)
        cp16((uint32_t)__cvta_generic_to_shared(&AsB[ar[i] * 36 + ak[i]]),
             &A[(size_t)(bm + ar[i]) * lda + ak[i]]);
    #pragma unroll
    for (int i = 0; i < 4; i++)
        cp16((uint32_t)__cvta_generic_to_shared(&BsB[bk[i] * 136 + bn4[i]]),
             &W[(size_t)bk[i] * Nc + bn + bn4[i]]);
    asm volatile("cp.async.commit_group;" ::: "memory");

    for (int it = 0; it < ntiles; it++) {
        if (it + 1 < ntiles) {
            int st = (it + 1) & 1;
            int k0 = (it + 1) * 32;
            #pragma unroll
            for (int i = 0; i < 4; i++)
                cp16((uint32_t)__cvta_generic_to_shared(&AsB[st * ASZ + ar[i] * 36 + ak[i]]),
                     &A[(size_t)(bm + ar[i]) * lda + k0 + ak[i]]);
            #pragma unroll
            for (int i = 0; i < 4; i++)
                cp16((uint32_t)__cvta_generic_to_shared(&BsB[st * BSZ + bk[i] * 136 + bn4[i]]),
                     &W[(size_t)(k0 + bk[i]) * Nc + bn + bn4[i]]);
            asm volatile("cp.async.commit_group;" ::: "memory");
            asm volatile("cp.async.wait_group 1;" ::: "memory");
        } else {
            asm volatile("cp.async.wait_group 0;" ::: "memory");
        }
        __syncthreads();
        const float* as = &AsB[(it & 1) * ASZ];
        const float* bs = &BsB[(it & 1) * BSZ];
        #pragma unroll
        for (int ks = 0; ks < 32; ks += 8) {
            uint32_t af[4][4], bf[4][2];
            #pragma unroll
            for (int mt = 0; mt < 4; mt++) {
                const float* ap = &as[(wm * 64 + mt * 16 + gid) * 36 + ks + tig];
                af[mt][0] = __float_as_uint(ap[0]);
                af[mt][1] = __float_as_uint(ap[8 * 36]);
                af[mt][2] = __float_as_uint(ap[4]);
                af[mt][3] = __float_as_uint(ap[8 * 36 + 4]);
            }
            #pragma unroll
            for (int nt = 0; nt < 4; nt++) {
                const float* bp = &bs[(ks + tig) * 136 + wn * 32 + nt * 8 + gid];
                bf[nt][0] = __float_as_uint(bp[0]);
                bf[nt][1] = __float_as_uint(bp[4 * 136]);
            }
            #pragma unroll
            for (int mt = 0; mt < 4; mt++)
                #pragma unroll
                for (int nt = 0; nt < 4; nt++) MMA_TF32(acc[mt][nt], af[mt], bf[nt]);
        }
        __syncthreads();
    }

    #pragma unroll
    for (int mt = 0; mt < 4; mt++) {
        int r0 = bm + wm * 64 + mt * 16 + gid;
        int r1 = r0 + 8;
        float zm0 = (degmask && degmask[r0] == 0) ? 0.f : 1.f;
        float zm1 = (degmask && degmask[r1] == 0) ? 0.f : 1.f;
        #pragma unroll
        for (int nt = 0; nt < 4; nt++) {
            int c0 = bn + wn * 32 + nt * 8 + 2 * tig;
            float b0 = bias ? bias[c0] : 0.f;
            float b1 = bias ? bias[c0 + 1] : 0.f;
            float ra00 = 0.f, ra01 = 0.f, ra10 = 0.f, ra11 = 0.f;
            if (rowadd) {
                ra00 = rowadd[(size_t)(r0 >> 6) * Nc + c0];
                ra01 = rowadd[(size_t)(r0 >> 6) * Nc + c0 + 1];
                ra10 = rowadd[(size_t)(r1 >> 6) * Nc + c0];
                ra11 = rowadd[(size_t)(r1 >> 6) * Nc + c0 + 1];
            }
            float v00 = acc[mt][nt][0] + b0 + ra00;
            float v01 = acc[mt][nt][1] + b1 + ra01;
            float v10 = acc[mt][nt][2] + b0 + ra10;
            float v11 = acc[mt][nt][3] + b1 + ra11;
            if (do_relu) {
                v00 = fmaxf(v00, 0.f); v01 = fmaxf(v01, 0.f);
                v10 = fmaxf(v10, 0.f); v11 = fmaxf(v11, 0.f);
            }
            v00 *= zm0; v01 *= zm0; v10 *= zm1; v11 *= zm1;
            if (do_round) {
                v00 = to_tf32(v00); v01 = to_tf32(v01);
                v10 = to_tf32(v10); v11 = to_tf32(v11);
            }
            float2 o0 = {v00, v01};
            float2 o1 = {v10, v11};
            *(float2*)&C[(size_t)r0 * Nc + c0] = o0;
            *(float2*)&C[(size_t)r1 * Nc + c0] = o1;
        }
    }
}

// ---------------- fp32 GEMM 128x64 tile (actterm; raw W1 rows 96..127) -------
__global__ void gemm_kernel(const float* __restrict__ A, const float* __restrict__ W,
                            const float* __restrict__ bias, float* __restrict__ C,
                            int M, int K, int Nc, int do_relu) {
    __shared__ float As[16][132];
    __shared__ float Bs[16][68];
    int bm = blockIdx.y * 128;
    int bn = blockIdx.x * 64;
    int t = threadIdx.x;
    int ty = t >> 4, tx = t & 15;
    float acc[8][4] = {};
    for (int k0 = 0; k0 < K; k0 += 16) {
        #pragma unroll
        for (int i = 0; i < 2; i++) {
            int idx = t + i * 256;
            int row = idx >> 2;
            int kq = (idx & 3) << 2;
            float4 v = *(const float4*)&A[(size_t)(bm + row) * K + k0 + kq];
            As[kq + 0][row] = v.x;
            As[kq + 1][row] = v.y;
            As[kq + 2][row] = v.z;
            As[kq + 3][row] = v.w;
        }
        {
            int kk = t >> 4;
            int col = (t & 15) << 2;
            *(float4*)&Bs[kk][col] = *(const float4*)&W[(size_t)(k0 + kk) * Nc + bn + col];
        }
        __syncthreads();
        #pragma unroll
        for (int kk = 0; kk < 16; kk++) {
            float a[8], b[4];
            *(float4*)&a[0] = *(const float4*)&As[kk][ty * 8];
            *(float4*)&a[4] = *(const float4*)&As[kk][ty * 8 + 4];
            *(float4*)&b[0] = *(const float4*)&Bs[kk][tx * 4];
            #pragma unroll
            for (int i = 0; i < 8; i++)
                #pragma unroll
                for (int j = 0; j < 4; j++) acc[i][j] = fmaf(a[i], b[j], acc[i][j]);
        }
        __syncthreads();
    }
    #pragma unroll
    for (int i = 0; i < 8; i++) {
        int r = bm + ty * 8 + i;
        int c0 = bn + tx * 4;
        float4 v;
        float* vp = &v.x;
        #pragma unroll
        for (int j = 0; j < 4; j++) {
            float xv = acc[i][j] + bias[c0 + j];
            if (do_relu) xv = fmaxf(xv, 0.f);
            vp[j] = xv;
        }
        *(float4*)&C[(size_t)r * Nc + c0] = v;
    }
}

// ---------------- edge aggregation --------------------------------------------

__device__ __forceinline__ void acc_relu4(float4& acc, float4 a, float4 b) {
    acc.x += fmaxf(a.x + b.x, 0.f);
    acc.y += fmaxf(a.y + b.y, 0.f);
    acc.z += fmaxf(a.z + b.z, 0.f);
    acc.w += fmaxf(a.w + b.w, 0.f);
}

__global__ void agg1_kernel() {
    int w = (blockIdx.x * blockDim.x + threadIdx.x) >> 5;
    int lane = threadIdx.x & 31;
    int deg = g_deg[w], start = g_off[w];
    float4 a = *(const float4*)&g_AB1[(size_t)w * 256 + lane * 4];
    float4 acc = {0.f, 0.f, 0.f, 0.f};
    int i = 0;
    for (; i + 8 <= deg; i += 8) {
        int s[8];
        #pragma unroll
        for (int u = 0; u < 8; u++) s[u] = g_csr[start + i + u];
        float4 b[8];
        #pragma unroll
        for (int u = 0; u < 8; u++)
            b[u] = *(const float4*)&g_AB1[(size_t)s[u] * 256 + 128 + lane * 4];
        #pragma unroll
        for (int u = 0; u < 8; u++) acc_relu4(acc, a, b[u]);
    }
    for (; i + 2 <= deg; i += 2) {
        int s0 = g_csr[start + i], s1 = g_csr[start + i + 1];
        float4 b0 = *(const float4*)&g_AB1[(size_t)s0 * 256 + 128 + lane * 4];
        float4 b1 = *(const float4*)&g_AB1[(size_t)s1 * 256 + 128 + lane * 4];
        acc_relu4(acc, a, b0);
        acc_relu4(acc, a, b1);
    }
    for (; i < deg; i++) {
        int s = g_csr[start + i];
        float4 b = *(const float4*)&g_AB1[(size_t)s * 256 + 128 + lane * 4];
        acc_relu4(acc, a, b);
    }
    float inv = 1.f / fmaxf((float)deg, 1.f);
    // tf32-round at write: sum1 is consumed only by the tf32 GEMM
    float4 o = {to_tf32(acc.x * inv), to_tf32(acc.y * inv),
                to_tf32(acc.z * inv), to_tf32(acc.w * inv)};
    *(float4*)&g_sum1[(size_t)w * 128 + lane * 4] = o;
}

__device__ __forceinline__ void acc_relu2(float2& acc, float2 a, float2 b) {
    acc.x += fmaxf(a.x + b.x, 0.f);
    acc.y += fmaxf(a.y + b.y, 0.f);
}

__global__ void agg2_kernel() {
    int w = (blockIdx.x * blockDim.x + threadIdx.x) >> 5;
    int lane = threadIdx.x & 31;
    int deg = g_deg[w], start = g_off[w];
    float2 a = *(const float2*)&g_AB2[(size_t)w * 128 + lane * 2];
    float2 acc = {0.f, 0.f};
    int i = 0;
    for (; i + 8 <= deg; i += 8) {
        int s[8];
        #pragma unroll
        for (int u = 0; u < 8; u++) s[u] = g_csr[start + i + u];
        float2 b[8];
        #pragma unroll
        for (int u = 0; u < 8; u++)
            b[u] = *(const float2*)&g_AB2[(size_t)s[u] * 128 + 64 + lane * 2];
        #pragma unroll
        for (int u = 0; u < 8; u++) acc_relu2(acc, a, b[u]);
    }
    for (; i + 2 <= deg; i += 2) {
        int s0 = g_csr[start + i], s1 = g_csr[start + i + 1];
        float2 b0 = *(const float2*)&g_AB2[(size_t)s0 * 128 + 64 + lane * 2];
        float2 b1 = *(const float2*)&g_AB2[(size_t)s1 * 128 + 64 + lane * 2];
        acc_relu2(acc, a, b0);
        acc_relu2(acc, a, b1);
    }
    for (; i < deg; i++) {
        int s = g_csr[start + i];
        float2 b = *(const float2*)&g_AB2[(size_t)s * 128 + 64 + lane * 2];
        acc_relu2(acc, a, b);
    }
    if (deg > 0) {
        float inv = 1.f / (float)deg;
        int g = w >> 6;
        atomicAdd(&g_gsum[g * 64 + lane * 2],     acc.x * inv);
        atomicAdd(&g_gsum[g * 64 + lane * 2 + 1], acc.y * inv);
    }
}

// ---------------- fused tail: z = tf32([state|action|ge]) --------------------
__global__ void tail_kernel(const float* __restrict__ state, const float* __restrict__ action,
                            const float* __restrict__ w2, const float* __restrict__ b2) {
    __shared__ float S[64];
    __shared__ int np;
    int g = blockIdx.x;
    int t = threadIdx.x;
    if (t == 0) np = 0;
    __syncthreads();
    if (t < 128) {
        float v = (t < 96) ? state[g * 96 + t] : action[g * 32 + (t - 96)];
        g_z[g * 192 + t] = to_tf32(v);
    } else {
        int c = t - 128;
        S[c] = g_gsum[g * 64 + c];
        unsigned bal = __ballot_sync(0xffffffffu, g_deg[g * 64 + c] > 0);
        if ((t & 31) == 0) atomicAdd(&np, __popc(bal));
    }
    __syncthreads();
    if (t >= 128) {
        int c = t - 128;
        float npos = (float)np;
        float acc = 0.f;
        #pragma unroll 8
        for (int k = 0; k < 64; k++) acc = fmaf(S[k], w2[k * 64 + c], acc);
        g_z[g * 192 + 128 + c] = to_tf32((acc + npos * b2[c]) * (1.f / 64.f));
    }
}

__global__ void qdot_kernel(const float* __restrict__ w3a, const float* __restrict__ b3a,
                            const float* __restrict__ w3b, const float* __restrict__ b3b,
                            float* __restrict__ out) {
    int warp = (blockIdx.x * blockDim.x + threadIdx.x) >> 5;
    int lane = threadIdx.x & 31;
    if (warp >= 2 * NB) return;
    int head = warp >> 10;
    const float* w3 = head ? w3b : w3a;
    const float* b3 = head ? b3b : b3a;
    const float* t2 = &g_t2[(size_t)warp * 256];
    float s = 0.f;
    #pragma unroll
    for (int k = lane; k < 256; k += 32) s += t2[k] * w3[k];
    #pragma unroll
    for (int o = 16; o > 0; o >>= 1) s += __shfl_down_sync(0xffffffffu, s, o);
    if (lane == 0) out[warp] = s + b3[0];
}

// ---------------- launch ------------------------------------------------------

extern "C" void kernel_launch(void* const* d_in, const int* in_sizes, int n_in,
                              void* d_out, int out_size) {
    const float* state  = (const float*)d_in[0];
    const float* action = (const float*)d_in[1];
    const float* x      = (const float*)d_in[2];
    const int*   eidx   = (const int*)d_in[3];
    const float* g1_w1 = (const float*)d_in[5];
    const float* g1_b1 = (const float*)d_in[6];
    const float* g1_w2 = (const float*)d_in[7];
    const float* g1_b2 = (const float*)d_in[8];
    const float* g2_w1 = (const float*)d_in[9];
    const float* g2_b1 = (const float*)d_in[10];
    const float* g2_w2 = (const float*)d_in[11];
    const float* g2_b2 = (const float*)d_in[12];
    const float* q1_w1 = (const float*)d_in[13];
    const float* q1_b1 = (const float*)d_in[14];
    const float* q1_w2 = (const float*)d_in[15];
    const float* q1_b2 = (const float*)d_in[16];
    const float* q1_w3 = (const float*)d_in[17];
    const float* q1_b3 = (const float*)d_in[18];
    const float* q2_w1 = (const float*)d_in[19];
    const float* q2_b1 = (const float*)d_in[20];
    const float* q2_w2 = (const float*)d_in[21];
    const float* q2_b2 = (const float*)d_in[22];
    const float* q2_w3 = (const float*)d_in[23];
    const float* q2_b3 = (const float*)d_in[24];
    float* out = (float*)d_out;

    const int4* srcs4 = (const int4*)eidx;
    const int4* dsts4 = (const int4*)(eidx + NE);

    float *p_xr, *p_AB1, *p_sum1, *p_h1, *p_AB2, *p_z, *p_t1, *p_t2;
    float *p_W1, *p_b1, *p_W2, *p_b2, *p_W1b, *p_act, *p_QW1, *p_Qb1, *p_QW2a, *p_QW2b;
    int *p_deg;
    cudaGetSymbolAddress((void**)&p_xr,   g_xr);
    cudaGetSymbolAddress((void**)&p_AB1,  g_AB1);
    cudaGetSymbolAddress((void**)&p_sum1, g_sum1);
    cudaGetSymbolAddress((void**)&p_h1,   g_h1);
    cudaGetSymbolAddress((void**)&p_AB2,  g_AB2);
    cudaGetSymbolAddress((void**)&p_z,    g_z);
    cudaGetSymbolAddress((void**)&p_t1,   g_t1);
    cudaGetSymbolAddress((void**)&p_t2,   g_t2);
    cudaGetSymbolAddress((void**)&p_W1,   g_W1);
    cudaGetSymbolAddress((void**)&p_b1,   g_bias1);
    cudaGetSymbolAddress((void**)&p_W2,   g_W2);
    cudaGetSymbolAddress((void**)&p_b2,   g_bias2);
    cudaGetSymbolAddress((void**)&p_W1b,  g_W1b);
    cudaGetSymbolAddress((void**)&p_act,  g_actterm);
    cudaGetSymbolAddress((void**)&p_QW1,  g_QW1);
    cudaGetSymbolAddress((void**)&p_Qb1,  g_Qb1);
    cudaGetSymbolAddress((void**)&p_QW2a, g_QW2a);
    cudaGetSymbolAddress((void**)&p_QW2b, g_QW2b);
    cudaGetSymbolAddress((void**)&p_deg,  g_deg);

    const int GEMM_SMEM = (2 * 128 * 36 + 2 * 32 * 136) * 4;   // 71680 bytes
    cudaFuncSetAttribute(gemm_db_kernel, cudaFuncAttributeMaxDynamicSharedMemorySize, GEMM_SMEM);

    cudaStream_t s2;
    cudaEvent_t eFork, eXr, eJoin;
    cudaStreamCreateWithFlags(&s2, cudaStreamNonBlocking);
    cudaEventCreateWithFlags(&eFork, cudaEventDisableTiming);
    cudaEventCreateWithFlags(&eXr, cudaEventDisableTiming);
    cudaEventCreateWithFlags(&eJoin, cudaEventDisableTiming);

    cudaEventRecord(eFork, 0);
    cudaStreamWaitEvent(s2, eFork, 0);

    // ---- side stream: xr round + CSR build ----
    xr_kernel<<<(NN * 96 / 4) / 256, 256, 0, s2>>>((const float4*)x);
    cudaEventRecord(eXr, s2);
    zero_kernel<<<(NN + NB * 64 + 255) / 256, 256, 0, s2>>>();
    count_kernel<<<NE / 4 / 256, 256, 0, s2>>>(dsts4);
    blocksum_kernel<<<256, 256, 0, s2>>>();
    bscan_kernel<<<1, 256, 0, s2>>>();
    fill_kernel<<<256, 256, 0, s2>>>();
    scatter_kernel<<<NE / 4 / 256, 256, 0, s2>>>(srcs4, dsts4);
    cudaEventRecord(eJoin, s2);

    // ---- main stream: weights + actterm ----
    prep_kernel<<<(295808 + 255) / 256, 256>>>(g1_w1, g1_b1, g1_w2, g2_w1, g2_b1,
                                               q1_w1, q1_b1, q1_w2, q2_w1, q2_b1, q2_w2);
    gemm_kernel<<<dim3(4, NB / 128), 256>>>(action, p_W1 + 96 * 256, p_b1, p_act,
                                            NB, 32, 256, 0);
    // AB1 = xr @ W1[0:96] + actterm[graph]
    cudaStreamWaitEvent(0, eXr, 0);
    gemm_db_kernel<<<dim3(2, NN / 128), 256, GEMM_SMEM>>>(
        p_xr, p_W1, nullptr, p_AB1, 96, 256, 96, 0, 0, nullptr, p_act,
        nullptr, nullptr, nullptr, 0);

    cudaStreamWaitEvent(0, eJoin, 0);
    agg1_kernel<<<NN / 8, 256>>>();
    // h1 = round(relu(sum1 @ W1b + g1_b2) * mask)
    gemm_db_kernel<<<dim3(1, NN / 128), 256, GEMM_SMEM>>>(
        p_sum1, p_W1b, g1_b2, p_h1, 128, 128, 128, 1, 1, p_deg, nullptr,
        nullptr, nullptr, nullptr, 0);
    // AB2 = h1 @ W2cat + b2cat
    gemm_db_kernel<<<dim3(1, NN / 128), 256, GEMM_SMEM>>>(
        p_h1, p_W2, p_b2, p_AB2, 128, 128, 128, 0, 0, nullptr, nullptr,
        nullptr, nullptr, nullptr, 0);
    agg2_kernel<<<NN / 8, 256>>>();
    tail_kernel<<<NB, 192>>>(state, action, g2_w2, g2_b2);
    // Q layer 1 (both heads fused, Nc=512)
    gemm_db_kernel<<<dim3(4, NB / 128), 256, GEMM_SMEM>>>(
        p_z, p_QW1, p_Qb1, p_t1, 192, 512, 192, 1, 1, nullptr, nullptr,
        nullptr, nullptr, nullptr, 0);
    // Q layer 2 (z-batched heads)
    gemm_db_kernel<<<dim3(2, NB / 128, 2), 256, GEMM_SMEM>>>(
        p_t1, p_QW2a, q1_b2, p_t2, 256, 256, 512, 1, 0, nullptr, nullptr,
        p_QW2b, q2_b2, p_t2 + NB * 256, 256);
    qdot_kernel<<<(2 * NB * 32) / 256, 256>>>(q1_w3, q1_b3, q2_w3, q2_b3, out);
}